// round 1
// baseline (speedup 1.0000x reference)
#include <cuda_runtime.h>
#include <cuda_bf16.h>
#include <math.h>

// ---------------- problem constants ----------------
#define LAYERS 2
#define NH     12
#define DMODEL 768
#define HS     64
#define FF     3072
#define VOCAB  50257
#define BB     4
#define TT     512
#define BT     (BB*TT)          // 2048

// ---------------- device scratch (no runtime allocation allowed) ----------------
__device__ float g_x[BT*DMODEL];
__device__ float g_h[BT*DMODEL];
__device__ float g_q[BT*DMODEL];
__device__ float g_k[BT*DMODEL];
__device__ float g_v[BT*DMODEL];
__device__ float g_att[BT*DMODEL];
__device__ float g_ffn[BT*FF];
__device__ float g_wq[DMODEL*DMODEL];
__device__ float g_wk[DMODEL*DMODEL];
__device__ float g_wv[DMODEL*DMODEL];
__device__ float g_rowloss[BT];

// ---------------- embedding ----------------
__global__ void embed_kernel(const int* __restrict__ idx,
                             const float* __restrict__ wte,
                             const float* __restrict__ wpe,
                             float* __restrict__ x)
{
    int bt = blockIdx.x;
    int t  = bt % TT;
    int tok = idx[bt];
    const float* te = wte + (size_t)tok * DMODEL;
    const float* pe = wpe + (size_t)t * DMODEL;
    float* xr = x + (size_t)bt * DMODEL;
    for (int d = threadIdx.x; d < DMODEL; d += blockDim.x)
        xr[d] = te[d] + pe[d];
}

// ---------------- layernorm (one row per block) ----------------
__global__ void ln_kernel(const float* __restrict__ x,
                          const float* __restrict__ s,
                          const float* __restrict__ b,
                          float* __restrict__ y)
{
    __shared__ float red[256];
    int row = blockIdx.x;
    const float* xr = x + (size_t)row * DMODEL;
    float* yr = y + (size_t)row * DMODEL;

    float sum = 0.f, sq = 0.f;
    for (int d = threadIdx.x; d < DMODEL; d += 256) {
        float v = xr[d];
        sum += v; sq += v * v;
    }
    red[threadIdx.x] = sum; __syncthreads();
    for (int o = 128; o > 0; o >>= 1) { if (threadIdx.x < o) red[threadIdx.x] += red[threadIdx.x + o]; __syncthreads(); }
    float mean = red[0] / DMODEL; __syncthreads();
    red[threadIdx.x] = sq; __syncthreads();
    for (int o = 128; o > 0; o >>= 1) { if (threadIdx.x < o) red[threadIdx.x] += red[threadIdx.x + o]; __syncthreads(); }
    float var = red[0] / DMODEL - mean * mean;
    float rstd = rsqrtf(var + 1e-5f);
    for (int d = threadIdx.x; d < DMODEL; d += 256)
        yr[d] = (xr[d] - mean) * rstd * s[d] + b[d];
}

// ---------------- weight repack: [L,H,D,HS] -> [D, H*HS] ----------------
__global__ void repack_kernel(const float* __restrict__ W, float* __restrict__ out, int layer)
{
    int i = blockIdx.x * blockDim.x + threadIdx.x;
    const int total = DMODEL * NH * HS;
    if (i >= total) return;
    int e = i % HS;
    int d = (i / HS) % DMODEL;
    int h = i / (HS * DMODEL);
    out[(size_t)d * DMODEL + h * HS + e] =
        W[((((size_t)layer * NH + h) * DMODEL) + d) * HS + e];
}

// ---------------- fp32 SGEMM: C[M,N] = A[M,K] @ B (+bias, +res | gelu) --------
// transB==0: B is [K,N] row-major.  transB==1: B is [N,K] row-major (NT).
// epi: 0 = +bias; 1 = +bias +res; 2 = +bias then exact GELU.
#define GBM 128
#define GBN 128
#define GBK 8
__global__ __launch_bounds__(256)
void sgemm_kernel(const float* __restrict__ A, const float* __restrict__ B,
                  const float* __restrict__ bias, const float* __restrict__ res,
                  float* __restrict__ C, int M, int N, int K, int transB, int epi)
{
    __shared__ float As[GBK][GBM];
    __shared__ float Bs[GBK][GBN];

    int tid = threadIdx.x;
    int tx = tid & 15;          // 0..15 -> col group
    int ty = tid >> 4;          // 0..15 -> row group
    int rowBase = blockIdx.y * GBM;
    int colBase = blockIdx.x * GBN;

    float acc[8][8];
#pragma unroll
    for (int i = 0; i < 8; i++)
#pragma unroll
        for (int j = 0; j < 8; j++) acc[i][j] = 0.f;

    // A load mapping: 128 rows x 8 k, float4 per thread
    int aRow = tid >> 1;            // 0..127
    int aCol = (tid & 1) * 4;       // 0 or 4
    // B NN load mapping: 8 k x 128 cols
    int bRow = tid >> 5;            // 0..7
    int bCol = (tid & 31) * 4;      // 0..124
    // B NT load mapping: 128 cols x 8 k
    int cT   = tid >> 1;            // col 0..127
    int kOff = (tid & 1) * 4;

    for (int k0 = 0; k0 < K; k0 += GBK) {
        // ---- load A tile ----
        {
            int row = rowBase + aRow;
            if (row < M) {
                const float* ap = A + (size_t)row * K + k0 + aCol;
#pragma unroll
                for (int j = 0; j < 4; j++) As[aCol + j][aRow] = ap[j];
            } else {
#pragma unroll
                for (int j = 0; j < 4; j++) As[aCol + j][aRow] = 0.f;
            }
        }
        // ---- load B tile ----
        if (transB == 0) {
            int k = k0 + bRow;
            const float* bp = B + (size_t)k * N + colBase + bCol;
#pragma unroll
            for (int j = 0; j < 4; j++) {
                int col = colBase + bCol + j;
                Bs[bRow][bCol + j] = (col < N) ? bp[j] : 0.f;
            }
        } else {
            int col = colBase + cT;
            if (col < N) {
                const float* bp = B + (size_t)col * K + k0 + kOff;
#pragma unroll
                for (int j = 0; j < 4; j++) Bs[kOff + j][cT] = bp[j];
            } else {
#pragma unroll
                for (int j = 0; j < 4; j++) Bs[kOff + j][cT] = 0.f;
            }
        }
        __syncthreads();

#pragma unroll
        for (int k = 0; k < GBK; k++) {
            float a[8], b[8];
            float4 a0 = *(const float4*)&As[k][ty * 8];
            float4 a1 = *(const float4*)&As[k][ty * 8 + 4];
            float4 b0 = *(const float4*)&Bs[k][tx * 8];
            float4 b1 = *(const float4*)&Bs[k][tx * 8 + 4];
            a[0]=a0.x;a[1]=a0.y;a[2]=a0.z;a[3]=a0.w;a[4]=a1.x;a[5]=a1.y;a[6]=a1.z;a[7]=a1.w;
            b[0]=b0.x;b[1]=b0.y;b[2]=b0.z;b[3]=b0.w;b[4]=b1.x;b[5]=b1.y;b[6]=b1.z;b[7]=b1.w;
#pragma unroll
            for (int i = 0; i < 8; i++)
#pragma unroll
                for (int j = 0; j < 8; j++) acc[i][j] = fmaf(a[i], b[j], acc[i][j]);
        }
        __syncthreads();
    }

#pragma unroll
    for (int i = 0; i < 8; i++) {
        int row = rowBase + ty * 8 + i;
        if (row >= M) continue;
#pragma unroll
        for (int j = 0; j < 8; j++) {
            int col = colBase + tx * 8 + j;
            if (col >= N) continue;
            float vv = acc[i][j];
            if (bias) vv += bias[col];
            if (epi == 1) vv += res[(size_t)row * N + col];
            else if (epi == 2) vv = 0.5f * vv * (1.f + erff(vv * 0.70710678118654752f));
            C[(size_t)row * N + col] = vv;
        }
    }
}

// ---------------- attention: one (b,h,tq) row per block (128 threads) --------
__global__ void attn_kernel(const float* __restrict__ q,
                            const float* __restrict__ k,
                            const float* __restrict__ v,
                            float* __restrict__ o)
{
    __shared__ float qs[HS];
    __shared__ float sc[TT];
    __shared__ float red[128];

    int tq = blockIdx.x, h = blockIdx.y, b = blockIdx.z;
    int tid = threadIdx.x;
    size_t qoff = ((size_t)(b * TT + tq)) * DMODEL + h * HS;

    if (tid < HS) qs[tid] = q[qoff + tid];
    __syncthreads();

    int n = tq + 1;
    for (int tk = tid; tk < n; tk += 128) {
        const float* kr = k + ((size_t)(b * TT + tk)) * DMODEL + h * HS;
        float s = 0.f;
#pragma unroll
        for (int e = 0; e < HS; e++) s = fmaf(qs[e], kr[e], s);
        sc[tk] = s;
    }
    __syncthreads();

    // max
    float mx = -1e30f;
    for (int tk = tid; tk < n; tk += 128) mx = fmaxf(mx, sc[tk]);
    red[tid] = mx; __syncthreads();
    for (int off = 64; off > 0; off >>= 1) { if (tid < off) red[tid] = fmaxf(red[tid], red[tid + off]); __syncthreads(); }
    mx = red[0]; __syncthreads();

    // exp + sum
    float sum = 0.f;
    for (int tk = tid; tk < n; tk += 128) { float p = expf(sc[tk] - mx); sc[tk] = p; sum += p; }
    red[tid] = sum; __syncthreads();
    for (int off = 64; off > 0; off >>= 1) { if (tid < off) red[tid] += red[tid + off]; __syncthreads(); }
    float inv = 1.f / (red[0] * 8.0f);   // post-softmax / sqrt(HS)=8
    __syncthreads();

    // o[e] = sum_tk p*v
    int e = tid & 63;
    int half = tid >> 6;
    float accv = 0.f;
    for (int tk = half; tk < n; tk += 2)
        accv = fmaf(sc[tk], v[((size_t)(b * TT + tk)) * DMODEL + h * HS + e], accv);
    red[tid] = accv; __syncthreads();
    if (half == 0)
        o[qoff + e] = (red[e] + red[e + 64]) * inv;
}

// ---------------- loss ----------------
__global__ void lossrow_kernel(const float* __restrict__ logits,
                               const int* __restrict__ targets,
                               float* __restrict__ rowloss)
{
    __shared__ float red[256];
    int r = blockIdx.x;
    const float* p = logits + (size_t)r * VOCAB;

    float mx = -1e30f;
    for (int i = threadIdx.x; i < VOCAB; i += 256) mx = fmaxf(mx, p[i]);
    red[threadIdx.x] = mx; __syncthreads();
    for (int o = 128; o > 0; o >>= 1) { if (threadIdx.x < o) red[threadIdx.x] = fmaxf(red[threadIdx.x], red[threadIdx.x + o]); __syncthreads(); }
    mx = red[0]; __syncthreads();

    float sum = 0.f;
    for (int i = threadIdx.x; i < VOCAB; i += 256) sum += expf(p[i] - mx);
    red[threadIdx.x] = sum; __syncthreads();
    for (int o = 128; o > 0; o >>= 1) { if (threadIdx.x < o) red[threadIdx.x] += red[threadIdx.x + o]; __syncthreads(); }
    if (threadIdx.x == 0) {
        int t = targets[r];
        rowloss[r] = -(p[t] - mx - logf(red[0]));
    }
}

__global__ void lossred_kernel(const float* __restrict__ rowloss, float* __restrict__ out)
{
    __shared__ float red[256];
    float s = 0.f;
    for (int i = threadIdx.x; i < BT; i += 256) s += rowloss[i];
    red[threadIdx.x] = s; __syncthreads();
    for (int o = 128; o > 0; o >>= 1) { if (threadIdx.x < o) red[threadIdx.x] += red[threadIdx.x + o]; __syncthreads(); }
    if (threadIdx.x == 0) out[0] = red[0] / (float)BT;
}

// ---------------- host orchestration ----------------
static float* symaddr(const void* sym)
{
    void* p = nullptr;
    cudaGetSymbolAddress(&p, sym);
    return (float*)p;
}

static void launch_gemm(const float* A, const float* B, const float* bias, const float* res,
                        float* C, int M, int N, int K, int transB, int epi)
{
    dim3 grid((N + GBN - 1) / GBN, (M + GBM - 1) / GBM);
    sgemm_kernel<<<grid, 256>>>(A, B, bias, res, C, M, N, K, transB, epi);
}

extern "C" void kernel_launch(void* const* d_in, const int* in_sizes, int n_in,
                              void* d_out, int out_size)
{
    const int*   idx     = (const int*)d_in[0];
    const int*   targets = (const int*)d_in[1];
    const float* wte     = (const float*)d_in[2];
    const float* wpe     = (const float*)d_in[3];
    const float* ln1_s   = (const float*)d_in[4];
    const float* ln1_b   = (const float*)d_in[5];
    const float* ln2_s   = (const float*)d_in[6];
    const float* ln2_b   = (const float*)d_in[7];
    const float* Wq      = (const float*)d_in[8];
    const float* bq      = (const float*)d_in[9];
    const float* Wk      = (const float*)d_in[10];
    const float* bk      = (const float*)d_in[11];
    const float* Wv      = (const float*)d_in[12];
    const float* bv      = (const float*)d_in[13];
    const float* Wo      = (const float*)d_in[14];
    const float* bo      = (const float*)d_in[15];
    const float* W1      = (const float*)d_in[16];
    const float* b1      = (const float*)d_in[17];
    const float* W2      = (const float*)d_in[18];
    const float* b2      = (const float*)d_in[19];
    const float* lnf_s   = (const float*)d_in[20];
    const float* lnf_b   = (const float*)d_in[21];

    float* out = (float*)d_out;

    float* x   = symaddr(g_x);
    float* h   = symaddr(g_h);
    float* q   = symaddr(g_q);
    float* k   = symaddr(g_k);
    float* v   = symaddr(g_v);
    float* att = symaddr(g_att);
    float* ffn = symaddr(g_ffn);
    float* wq  = symaddr(g_wq);
    float* wk  = symaddr(g_wk);
    float* wv  = symaddr(g_wv);
    float* rowloss = symaddr(g_rowloss);

    // 1) embeddings
    embed_kernel<<<BT, 256>>>(idx, wte, wpe, x);

    // 2) transformer layers
    for (int l = 0; l < LAYERS; l++) {
        // LN1
        ln_kernel<<<BT, 256>>>(x, ln1_s + l * DMODEL, ln1_b + l * DMODEL, h);

        // repack qkv weights for this layer into [D, H*HS]
        const int total = DMODEL * DMODEL;
        repack_kernel<<<(total + 255) / 256, 256>>>(Wq, wq, l);
        repack_kernel<<<(total + 255) / 256, 256>>>(Wk, wk, l);
        repack_kernel<<<(total + 255) / 256, 256>>>(Wv, wv, l);

        // q/k/v projections
        launch_gemm(h, wq, bq + l * DMODEL, nullptr, q, BT, DMODEL, DMODEL, 0, 0);
        launch_gemm(h, wk, bk + l * DMODEL, nullptr, k, BT, DMODEL, DMODEL, 0, 0);
        launch_gemm(h, wv, bv + l * DMODEL, nullptr, v, BT, DMODEL, DMODEL, 0, 0);

        // attention
        dim3 agrid(TT, NH, BB);
        attn_kernel<<<agrid, 128>>>(q, k, v, att);

        // output projection + residual  (x = x + att @ Wo + bo)
        launch_gemm(att, Wo + (size_t)l * DMODEL * DMODEL, bo + l * DMODEL, x, x,
                    BT, DMODEL, DMODEL, 0, 1);

        // MLP
        ln_kernel<<<BT, 256>>>(x, ln2_s + l * DMODEL, ln2_b + l * DMODEL, h);
        launch_gemm(h, W1 + (size_t)l * DMODEL * FF, b1 + l * FF, nullptr, ffn,
                    BT, FF, DMODEL, 0, 2);                       // GELU epilogue
        launch_gemm(ffn, W2 + (size_t)l * FF * DMODEL, b2 + l * DMODEL, x, x,
                    BT, DMODEL, FF, 0, 1);                       // +residual
    }

    // 3) final LN
    ln_kernel<<<BT, 256>>>(x, lnf_s, lnf_b, h);

    // 4) logits = h @ wte^T  -> d_out
    launch_gemm(h, wte, nullptr, nullptr, out, BT, VOCAB, DMODEL, 1, 0);

    // 5) loss (if the output buffer has a slot after the logits)
    const long long NL = (long long)BT * VOCAB;
    lossrow_kernel<<<BT, 256>>>(out, targets, rowloss);
    if ((long long)out_size > NL)
        lossred_kernel<<<1, 256>>>(rowloss, out + NL);
}

// round 3
// speedup vs baseline: 1.2805x; 1.2805x over previous
#include <cuda_runtime.h>
#include <cuda_bf16.h>
#include <math.h>
#include <stdint.h>

// ---------------- problem constants ----------------
#define LAYERS 2
#define NH     12
#define DMODEL 768
#define HS     64
#define FF     3072
#define VOCAB  50257
#define BB     4
#define TT     512
#define BT     2048
#define QKVN   2304      // fused q|k|v output width

// ---------------- device scratch ----------------
__device__ float g_x[BT*DMODEL];
__device__ float g_qkv[BT*QKVN];
__device__ float g_rowloss[BT];
__device__ float g_bqkv[QKVN];

__device__ __nv_bfloat16 g_hh[BT*DMODEL],  g_hl[BT*DMODEL];     // LN outputs (split)
__device__ __nv_bfloat16 g_ffh[BT*FF],     g_ffl[BT*FF];        // GELU outputs (split)
__device__ __nv_bfloat16 g_ath[BT*DMODEL], g_atl[BT*DMODEL];    // attention outputs (split)
__device__ __nv_bfloat16 g_wqkvh[QKVN*DMODEL], g_wqkvl[QKVN*DMODEL];
__device__ __nv_bfloat16 g_woh[DMODEL*DMODEL], g_wol[DMODEL*DMODEL];
__device__ __nv_bfloat16 g_w1h[FF*DMODEL],     g_w1l[FF*DMODEL];
__device__ __nv_bfloat16 g_w2h[DMODEL*FF],     g_w2l[DMODEL*FF];
__device__ __nv_bfloat16 g_wteh[VOCAB*DMODEL], g_wtel[VOCAB*DMODEL];

// ---------------- helpers ----------------
__device__ __forceinline__ uint32_t smem_u32(const void* p) {
    uint32_t a;
    asm("{ .reg .u64 t; cvta.to.shared.u64 t, %1; cvt.u32.u64 %0, t; }" : "=r"(a) : "l"(p));
    return a;
}
__device__ __forceinline__ void cp_async16(uint32_t saddr, const void* gptr, int src_bytes) {
    asm volatile("cp.async.cg.shared.global [%0], [%1], 16, %2;"
                 :: "r"(saddr), "l"(gptr), "r"(src_bytes) : "memory");
}
__device__ __forceinline__ void cp_commit() { asm volatile("cp.async.commit_group;" ::: "memory"); }
__device__ __forceinline__ void cp_wait0()  { asm volatile("cp.async.wait_group 0;" ::: "memory"); }

__device__ __forceinline__ void mma16816(float* c, const uint32_t* a, const uint32_t* b) {
    asm volatile(
        "mma.sync.aligned.m16n8k16.row.col.f32.bf16.bf16.f32 "
        "{%0,%1,%2,%3}, {%4,%5,%6,%7}, {%8,%9}, {%0,%1,%2,%3};"
        : "+f"(c[0]), "+f"(c[1]), "+f"(c[2]), "+f"(c[3])
        : "r"(a[0]), "r"(a[1]), "r"(a[2]), "r"(a[3]), "r"(b[0]), "r"(b[1]));
}

__device__ __forceinline__ void split2(float v, __nv_bfloat16* hi, __nv_bfloat16* lo) {
    __nv_bfloat16 h = __float2bfloat16(v);
    *hi = h;
    *lo = __float2bfloat16(v - __bfloat162float(h));
}

// ---------------- bf16 hi/lo split GEMM via mma.sync -------------------------
// D[m][n] = sum_k (Ah+Al)[m][k] * (Bh+Bl)[n][k]   (drops Al*Bl term)
// A row-major [M,K] bf16; B K-major [N,K] bf16.
// gelu_split=0: Cf = acc (+bias)(+res).  gelu_split=1: gelu(acc+bias) -> Chi/Clo.
#define BM 128
#define BN 128
#define BKC 32
#define PADK 40           // SMEM row stride in bf16 elements (conflict-free)

__global__ void __launch_bounds__(256, 1)
mm_gemm(const __nv_bfloat16* __restrict__ Ah, const __nv_bfloat16* __restrict__ Al,
        const __nv_bfloat16* __restrict__ Bh, const __nv_bfloat16* __restrict__ Bl,
        const float* __restrict__ bias, const float* __restrict__ res,
        float* __restrict__ Cf, __nv_bfloat16* __restrict__ Chi, __nv_bfloat16* __restrict__ Clo,
        int M, int N, int K, int gelu_split)
{
    __shared__ __nv_bfloat16 sAh[BM*PADK], sAl[BM*PADK], sBh[BN*PADK], sBl[BN*PADK];

    int tid = threadIdx.x, warp = tid >> 5, lane = tid & 31;
    int g = lane >> 2, t = lane & 3;
    int wr = warp >> 2, wc = warp & 3;        // warp grid 2x4 -> warp tile 64x32
    int rowBase = blockIdx.x * BM;
    int colBase = blockIdx.y * BN;

    float acc[4][4][4];
#pragma unroll
    for (int mi = 0; mi < 4; mi++)
#pragma unroll
        for (int ni = 0; ni < 4; ni++)
#pragma unroll
            for (int v = 0; v < 4; v++) acc[mi][ni][v] = 0.f;

    const __nv_bfloat16* srcs[4] = {Ah, Al, Bh, Bl};
    uint32_t dsts[4] = {smem_u32(sAh), smem_u32(sAl), smem_u32(sBh), smem_u32(sBl)};

    for (int k0 = 0; k0 < K; k0 += BKC) {
        // ---- load 4 tiles (128 rows x 32 bf16 each) via cp.async ----
#pragma unroll
        for (int tle = 0; tle < 4; tle++) {
            bool isB = (tle >= 2);
            int base = isB ? colBase : rowBase;
            const __nv_bfloat16* s = srcs[tle];
            uint32_t d = dsts[tle];
#pragma unroll
            for (int j = 0; j < 2; j++) {
                int u = j * 256 + tid;          // 0..511
                int row = u >> 2;               // 0..127
                int c = u & 3;                  // 16B chunk
                int gr = base + row;
                bool ok = (!isB) || (gr < N);
                const void* gp = s + ((size_t)(ok ? gr : base) * K + k0 + c * 8);
                cp_async16(d + row * (PADK * 2) + c * 16, gp, ok ? 16 : 0);
            }
        }
        cp_commit(); cp_wait0();
        __syncthreads();

        // ---- compute: two k16 steps ----
#pragma unroll
        for (int ks = 0; ks < 2; ks++) {
            int kk = ks * 16 + t * 2;
            uint32_t ah[4][4], al[4][4];
#pragma unroll
            for (int mi = 0; mi < 4; mi++) {
                int r = (wr * 64 + mi * 16 + g) * PADK;
                ah[mi][0] = *(const uint32_t*)&sAh[r + kk];
                ah[mi][1] = *(const uint32_t*)&sAh[r + 8 * PADK + kk];
                ah[mi][2] = *(const uint32_t*)&sAh[r + kk + 8];
                ah[mi][3] = *(const uint32_t*)&sAh[r + 8 * PADK + kk + 8];
                al[mi][0] = *(const uint32_t*)&sAl[r + kk];
                al[mi][1] = *(const uint32_t*)&sAl[r + 8 * PADK + kk];
                al[mi][2] = *(const uint32_t*)&sAl[r + kk + 8];
                al[mi][3] = *(const uint32_t*)&sAl[r + 8 * PADK + kk + 8];
            }
#pragma unroll
            for (int ni = 0; ni < 4; ni++) {
                int nb = (wc * 32 + ni * 8 + g) * PADK;
                uint32_t bh[2], bl[2];
                bh[0] = *(const uint32_t*)&sBh[nb + kk];
                bh[1] = *(const uint32_t*)&sBh[nb + kk + 8];
                bl[0] = *(const uint32_t*)&sBl[nb + kk];
                bl[1] = *(const uint32_t*)&sBl[nb + kk + 8];
#pragma unroll
                for (int mi = 0; mi < 4; mi++) {
                    mma16816(acc[mi][ni], ah[mi], bh);
                    mma16816(acc[mi][ni], ah[mi], bl);
                    mma16816(acc[mi][ni], al[mi], bh);
                }
            }
        }
        __syncthreads();
    }

    // ---- epilogue ----
#pragma unroll
    for (int mi = 0; mi < 4; mi++) {
        int r0 = rowBase + wr * 64 + mi * 16 + g;
#pragma unroll
        for (int ni = 0; ni < 4; ni++) {
            int c0 = colBase + wc * 32 + ni * 8 + t * 2;
#pragma unroll
            for (int v = 0; v < 4; v++) {
                int row = r0 + (v >= 2 ? 8 : 0);
                int col = c0 + (v & 1);
                if (col >= N) continue;
                float val = acc[mi][ni][v];
                if (bias) val += bias[col];
                size_t o = (size_t)row * N + col;
                if (gelu_split) {
                    val = 0.5f * val * (1.f + erff(val * 0.70710678118654752f));
                    __nv_bfloat16 h = __float2bfloat16(val);
                    Chi[o] = h;
                    Clo[o] = __float2bfloat16(val - __bfloat162float(h));
                } else {
                    if (res) val += res[o];
                    Cf[o] = val;
                }
            }
        }
    }
}

// ---------------- embedding ----------------
__global__ void embed_kernel(const int* __restrict__ idx,
                             const float* __restrict__ wte,
                             const float* __restrict__ wpe,
                             float* __restrict__ x)
{
    int bt = blockIdx.x;
    int t  = bt % TT;
    int tok = idx[bt];
    const float* te = wte + (size_t)tok * DMODEL;
    const float* pe = wpe + (size_t)t * DMODEL;
    float* xr = x + (size_t)bt * DMODEL;
    for (int d = threadIdx.x; d < DMODEL; d += blockDim.x)
        xr[d] = te[d] + pe[d];
}

// ---------------- layernorm with split bf16 output ----------------
__global__ void ln_split_kernel(const float* __restrict__ x,
                                const float* __restrict__ s,
                                const float* __restrict__ b,
                                __nv_bfloat16* __restrict__ yh,
                                __nv_bfloat16* __restrict__ yl)
{
    __shared__ float red[256];
    int row = blockIdx.x;
    const float* xr = x + (size_t)row * DMODEL;

    float sum = 0.f, sq = 0.f;
    for (int d = threadIdx.x; d < DMODEL; d += 256) {
        float v = xr[d];
        sum += v; sq += v * v;
    }
    red[threadIdx.x] = sum; __syncthreads();
    for (int o = 128; o > 0; o >>= 1) { if (threadIdx.x < o) red[threadIdx.x] += red[threadIdx.x + o]; __syncthreads(); }
    float mean = red[0] / DMODEL; __syncthreads();
    red[threadIdx.x] = sq; __syncthreads();
    for (int o = 128; o > 0; o >>= 1) { if (threadIdx.x < o) red[threadIdx.x] += red[threadIdx.x + o]; __syncthreads(); }
    float var = red[0] / DMODEL - mean * mean;
    float rstd = rsqrtf(var + 1e-5f);
    for (int d = threadIdx.x; d < DMODEL; d += 256) {
        float v = (xr[d] - mean) * rstd * s[d] + b[d];
        split2(v, &yh[(size_t)row * DMODEL + d], &yl[(size_t)row * DMODEL + d]);
    }
}

// ---------------- weight preparation ----------------
__global__ void prep_qkv_kernel(const float* __restrict__ Wq, const float* __restrict__ Wk,
                                const float* __restrict__ Wv,
                                const float* __restrict__ bq, const float* __restrict__ bk,
                                const float* __restrict__ bv, int layer,
                                __nv_bfloat16* __restrict__ wh, __nv_bfloat16* __restrict__ wl,
                                float* __restrict__ bqkv)
{
    int i = blockIdx.x * blockDim.x + threadIdx.x;
    if (i >= QKVN * DMODEL) return;
    int n = i / DMODEL, k = i % DMODEL;
    int sel = n / DMODEL;            // 0=q 1=k 2=v
    int r = n % DMODEL;
    int h = r / HS, e = r % HS;
    const float* W = (sel == 0) ? Wq : (sel == 1) ? Wk : Wv;
    float v = W[((((size_t)layer * NH + h) * DMODEL) + k) * HS + e];
    split2(v, &wh[i], &wl[i]);
    if (k == 0) {
        const float* bp = (sel == 0) ? bq : (sel == 1) ? bk : bv;
        bqkv[n] = bp[(size_t)layer * DMODEL + r];
    }
}

// generic [K,N] -> K-major [N,K] transpose + split
__global__ void prep_T_kernel(const float* __restrict__ src,
                              __nv_bfloat16* __restrict__ oh, __nv_bfloat16* __restrict__ ol,
                              int K, int N)
{
    int i = blockIdx.x * blockDim.x + threadIdx.x;
    if (i >= N * K) return;
    int n = i / K, k = i % K;
    split2(src[(size_t)k * N + n], &oh[i], &ol[i]);
}

// wte: already [V, D] K-major -> split only
__global__ void prep_split_kernel(const float* __restrict__ src,
                                  __nv_bfloat16* __restrict__ oh, __nv_bfloat16* __restrict__ ol,
                                  int n)
{
    int i = blockIdx.x * blockDim.x + threadIdx.x;
    if (i >= n) return;
    split2(src[i], &oh[i], &ol[i]);
}

// ---------------- attention (fp32, fused qkv buffer, split output) --------
__global__ void attn_kernel(const float* __restrict__ qkv,
                            __nv_bfloat16* __restrict__ oh,
                            __nv_bfloat16* __restrict__ ol)
{
    __shared__ float qs[HS];
    __shared__ float sc[TT];
    __shared__ float red[128];

    int tq = blockIdx.x, h = blockIdx.y, b = blockIdx.z;
    int tid = threadIdx.x;
    size_t qrow = (size_t)(b * TT + tq) * QKVN;

    if (tid < HS) qs[tid] = qkv[qrow + h * HS + tid];
    __syncthreads();

    int n = tq + 1;
    for (int tk = tid; tk < n; tk += 128) {
        const float* kr = qkv + (size_t)(b * TT + tk) * QKVN + DMODEL + h * HS;
        float s = 0.f;
#pragma unroll
        for (int e = 0; e < HS; e++) s = fmaf(qs[e], kr[e], s);
        sc[tk] = s;
    }
    __syncthreads();

    float mx = -1e30f;
    for (int tk = tid; tk < n; tk += 128) mx = fmaxf(mx, sc[tk]);
    red[tid] = mx; __syncthreads();
    for (int off = 64; off > 0; off >>= 1) { if (tid < off) red[tid] = fmaxf(red[tid], red[tid + off]); __syncthreads(); }
    mx = red[0]; __syncthreads();

    float sum = 0.f;
    for (int tk = tid; tk < n; tk += 128) { float p = expf(sc[tk] - mx); sc[tk] = p; sum += p; }
    red[tid] = sum; __syncthreads();
    for (int off = 64; off > 0; off >>= 1) { if (tid < off) red[tid] += red[tid + off]; __syncthreads(); }
    float inv = 1.f / (red[0] * 8.0f);   // post-softmax / sqrt(HS)
    __syncthreads();

    int e = tid & 63;
    int half = tid >> 6;
    float accv = 0.f;
    for (int tk = half; tk < n; tk += 2)
        accv = fmaf(sc[tk], qkv[(size_t)(b * TT + tk) * QKVN + 2 * DMODEL + h * HS + e], accv);
    red[tid] = accv; __syncthreads();
    if (half == 0) {
        float o = (red[e] + red[e + 64]) * inv;
        size_t oo = (size_t)(b * TT + tq) * DMODEL + h * HS + e;
        split2(o, &oh[oo], &ol[oo]);
    }
}

// ---------------- loss ----------------
__global__ void lossrow_kernel(const float* __restrict__ logits,
                               const int* __restrict__ targets,
                               float* __restrict__ rowloss)
{
    __shared__ float red[256];
    int r = blockIdx.x;
    const float* p = logits + (size_t)r * VOCAB;

    float mx = -1e30f;
    for (int i = threadIdx.x; i < VOCAB; i += 256) mx = fmaxf(mx, p[i]);
    red[threadIdx.x] = mx; __syncthreads();
    for (int o = 128; o > 0; o >>= 1) { if (threadIdx.x < o) red[threadIdx.x] = fmaxf(red[threadIdx.x], red[threadIdx.x + o]); __syncthreads(); }
    mx = red[0]; __syncthreads();

    float sum = 0.f;
    for (int i = threadIdx.x; i < VOCAB; i += 256) sum += expf(p[i] - mx);
    red[threadIdx.x] = sum; __syncthreads();
    for (int o = 128; o > 0; o >>= 1) { if (threadIdx.x < o) red[threadIdx.x] += red[threadIdx.x + o]; __syncthreads(); }
    if (threadIdx.x == 0) {
        int t = targets[r];
        rowloss[r] = -(p[t] - mx - logf(red[0]));
    }
}

__global__ void lossred_kernel(const float* __restrict__ rowloss, float* __restrict__ out)
{
    __shared__ float red[256];
    float s = 0.f;
    for (int i = threadIdx.x; i < BT; i += 256) s += rowloss[i];
    red[threadIdx.x] = s; __syncthreads();
    for (int o = 128; o > 0; o >>= 1) { if (threadIdx.x < o) red[threadIdx.x] += red[threadIdx.x + o]; __syncthreads(); }
    if (threadIdx.x == 0) out[0] = red[0] / (float)BT;
}

// ---------------- host ----------------
template <typename T>
static T* symaddr(const void* sym)
{
    void* p = nullptr;
    cudaGetSymbolAddress(&p, sym);
    return (T*)p;
}

static void launch_gemm(const __nv_bfloat16* Ah, const __nv_bfloat16* Al,
                        const __nv_bfloat16* Bh, const __nv_bfloat16* Bl,
                        const float* bias, const float* res,
                        float* Cf, __nv_bfloat16* Chi, __nv_bfloat16* Clo,
                        int M, int N, int K, int gelu_split)
{
    dim3 grid(M / BM, (N + BN - 1) / BN);
    mm_gemm<<<grid, 256>>>(Ah, Al, Bh, Bl, bias, res, Cf, Chi, Clo, M, N, K, gelu_split);
}

extern "C" void kernel_launch(void* const* d_in, const int* in_sizes, int n_in,
                              void* d_out, int out_size)
{
    const int*   idx     = (const int*)d_in[0];
    const int*   targets = (const int*)d_in[1];
    const float* wte     = (const float*)d_in[2];
    const float* wpe     = (const float*)d_in[3];
    const float* ln1_s   = (const float*)d_in[4];
    const float* ln1_b   = (const float*)d_in[5];
    const float* ln2_s   = (const float*)d_in[6];
    const float* ln2_b   = (const float*)d_in[7];
    const float* Wq      = (const float*)d_in[8];
    const float* bq      = (const float*)d_in[9];
    const float* Wk      = (const float*)d_in[10];
    const float* bk      = (const float*)d_in[11];
    const float* Wv      = (const float*)d_in[12];
    const float* bv      = (const float*)d_in[13];
    const float* Wo      = (const float*)d_in[14];
    const float* bo      = (const float*)d_in[15];
    const float* W1      = (const float*)d_in[16];
    const float* b1      = (const float*)d_in[17];
    const float* W2      = (const float*)d_in[18];
    const float* b2      = (const float*)d_in[19];
    const float* lnf_s   = (const float*)d_in[20];
    const float* lnf_b   = (const float*)d_in[21];

    float* out = (float*)d_out;

    float* x    = symaddr<float>(g_x);
    float* qkv  = symaddr<float>(g_qkv);
    float* bqkv = symaddr<float>(g_bqkv);
    float* rowloss = symaddr<float>(g_rowloss);
    __nv_bfloat16* hh  = symaddr<__nv_bfloat16>(g_hh);
    __nv_bfloat16* hl  = symaddr<__nv_bfloat16>(g_hl);
    __nv_bfloat16* ffh = symaddr<__nv_bfloat16>(g_ffh);
    __nv_bfloat16* ffl = symaddr<__nv_bfloat16>(g_ffl);
    __nv_bfloat16* ath = symaddr<__nv_bfloat16>(g_ath);
    __nv_bfloat16* atl = symaddr<__nv_bfloat16>(g_atl);
    __nv_bfloat16* wqkvh = symaddr<__nv_bfloat16>(g_wqkvh);
    __nv_bfloat16* wqkvl = symaddr<__nv_bfloat16>(g_wqkvl);
    __nv_bfloat16* woh = symaddr<__nv_bfloat16>(g_woh);
    __nv_bfloat16* wol = symaddr<__nv_bfloat16>(g_wol);
    __nv_bfloat16* w1h = symaddr<__nv_bfloat16>(g_w1h);
    __nv_bfloat16* w1l = symaddr<__nv_bfloat16>(g_w1l);
    __nv_bfloat16* w2h = symaddr<__nv_bfloat16>(g_w2h);
    __nv_bfloat16* w2l = symaddr<__nv_bfloat16>(g_w2l);
    __nv_bfloat16* wteh = symaddr<__nv_bfloat16>(g_wteh);
    __nv_bfloat16* wtel = symaddr<__nv_bfloat16>(g_wtel);

    // embeddings + wte split
    embed_kernel<<<BT, 256>>>(idx, wte, wpe, x);
    {
        const int n = VOCAB * DMODEL;
        prep_split_kernel<<<(n + 255) / 256, 256>>>(wte, wteh, wtel, n);
    }

    for (int l = 0; l < LAYERS; l++) {
        ln_split_kernel<<<BT, 256>>>(x, ln1_s + l * DMODEL, ln1_b + l * DMODEL, hh, hl);

        {
            const int n = QKVN * DMODEL;
            prep_qkv_kernel<<<(n + 255) / 256, 256>>>(Wq, Wk, Wv, bq, bk, bv, l, wqkvh, wqkvl, bqkv);
        }
        launch_gemm(hh, hl, wqkvh, wqkvl, bqkv, nullptr, qkv, nullptr, nullptr,
                    BT, QKVN, DMODEL, 0);

        dim3 agrid(TT, NH, BB);
        attn_kernel<<<agrid, 128>>>(qkv, ath, atl);

        {
            const int n = DMODEL * DMODEL;
            prep_T_kernel<<<(n + 255) / 256, 256>>>(Wo + (size_t)l * DMODEL * DMODEL, woh, wol, DMODEL, DMODEL);
        }
        launch_gemm(ath, atl, woh, wol, bo + l * DMODEL, x, x, nullptr, nullptr,
                    BT, DMODEL, DMODEL, 0);

        ln_split_kernel<<<BT, 256>>>(x, ln2_s + l * DMODEL, ln2_b + l * DMODEL, hh, hl);
        {
            const int n = FF * DMODEL;
            prep_T_kernel<<<(n + 255) / 256, 256>>>(W1 + (size_t)l * DMODEL * FF, w1h, w1l, DMODEL, FF);
        }
        launch_gemm(hh, hl, w1h, w1l, b1 + l * FF, nullptr, nullptr, ffh, ffl,
                    BT, FF, DMODEL, 1);                     // GELU + split
        {
            const int n = DMODEL * FF;
            prep_T_kernel<<<(n + 255) / 256, 256>>>(W2 + (size_t)l * FF * DMODEL, w2h, w2l, FF, DMODEL);
        }
        launch_gemm(ffh, ffl, w2h, w2l, b2 + l * DMODEL, x, x, nullptr, nullptr,
                    BT, DMODEL, FF, 0);
    }

    ln_split_kernel<<<BT, 256>>>(x, lnf_s, lnf_b, hh, hl);

    // logits = h @ wte^T
    launch_gemm(hh, hl, wteh, wtel, nullptr, nullptr, out, nullptr, nullptr,
                BT, VOCAB, DMODEL, 0);

    const long long NL = (long long)BT * VOCAB;
    lossrow_kernel<<<BT, 256>>>(out, targets, rowloss);
    if ((long long)out_size > NL)
        lossred_kernel<<<1, 256>>>(rowloss, out + NL);
}

// round 9
// speedup vs baseline: 2.1610x; 1.6876x over previous
#include <cuda_runtime.h>
#include <cuda_bf16.h>
#include <math.h>
#include <stdint.h>

// ---------------- problem constants ----------------
#define LAYERS 2
#define NH     12
#define DMODEL 768
#define HS     64
#define FF     3072
#define VOCAB  50257
#define BB     4
#define TT     512
#define BT     2048
#define QKVN   2304      // fused q|k|v output width

// ---------------- device scratch ----------------
__device__ float g_x[BT*DMODEL];
__device__ float g_qkv[BT*QKVN];
__device__ float g_rowloss[BT];
__device__ float g_bqkv[QKVN];

__device__ __nv_bfloat16 g_hh[BT*DMODEL],  g_hl[BT*DMODEL];
__device__ __nv_bfloat16 g_ffh[BT*FF],     g_ffl[BT*FF];
__device__ __nv_bfloat16 g_ath[BT*DMODEL], g_atl[BT*DMODEL];
__device__ __nv_bfloat16 g_wqkvh[QKVN*DMODEL], g_wqkvl[QKVN*DMODEL];
__device__ __nv_bfloat16 g_woh[DMODEL*DMODEL], g_wol[DMODEL*DMODEL];
__device__ __nv_bfloat16 g_w1h[FF*DMODEL],     g_w1l[FF*DMODEL];
__device__ __nv_bfloat16 g_w2h[DMODEL*FF],     g_w2l[DMODEL*FF];
__device__ __nv_bfloat16 g_wteh[VOCAB*DMODEL], g_wtel[VOCAB*DMODEL];

// ---------------- helpers ----------------
__device__ __forceinline__ uint32_t smem_u32(const void* p) {
    uint32_t a;
    asm("{ .reg .u64 t; cvta.to.shared.u64 t, %1; cvt.u32.u64 %0, t; }" : "=r"(a) : "l"(p));
    return a;
}
__device__ __forceinline__ void cp_async16(uint32_t saddr, const void* gptr, int src_bytes) {
    asm volatile("cp.async.cg.shared.global [%0], [%1], 16, %2;"
                 :: "r"(saddr), "l"(gptr), "r"(src_bytes) : "memory");
}
__device__ __forceinline__ void cp_commit() { asm volatile("cp.async.commit_group;" ::: "memory"); }
__device__ __forceinline__ void cp_wait1()  { asm volatile("cp.async.wait_group 1;" ::: "memory"); }

__device__ __forceinline__ void mma16816(float* c, const uint32_t* a, const uint32_t* b) {
    asm volatile(
        "mma.sync.aligned.m16n8k16.row.col.f32.bf16.bf16.f32 "
        "{%0,%1,%2,%3}, {%4,%5,%6,%7}, {%8,%9}, {%0,%1,%2,%3};"
        : "+f"(c[0]), "+f"(c[1]), "+f"(c[2]), "+f"(c[3])
        : "r"(a[0]), "r"(a[1]), "r"(a[2]), "r"(a[3]), "r"(b[0]), "r"(b[1]));
}

__device__ __forceinline__ void split2(float v, __nv_bfloat16* hi, __nv_bfloat16* lo) {
    __nv_bfloat16 h = __float2bfloat16(v);
    *hi = h;
    *lo = __float2bfloat16(v - __bfloat162float(h));
}

// ---------------- bf16 hi/lo split GEMM (double-buffered cp.async) ----------
#define BM 128
#define BN 128
#define BKC 32
#define PADK 40                              // SMEM row stride in bf16
#define TILE_BYTES (128*PADK*2)              // 10240
#define STAGE_BYTES (4*TILE_BYTES)           // 40960
#define GSMEM_BYTES (2*STAGE_BYTES)          // 81920

__global__ void __launch_bounds__(256)
mm_gemm(const __nv_bfloat16* __restrict__ Ah, const __nv_bfloat16* __restrict__ Al,
        const __nv_bfloat16* __restrict__ Bh, const __nv_bfloat16* __restrict__ Bl,
        const float* __restrict__ bias, const float* __restrict__ res,
        float* __restrict__ Cf, __nv_bfloat16* __restrict__ Chi, __nv_bfloat16* __restrict__ Clo,
        int M, int N, int K, int gelu_split)
{
    extern __shared__ char smem[];
    uint32_t sb = smem_u32(smem);

    int tid = threadIdx.x, warp = tid >> 5, lane = tid & 31;
    int g = lane >> 2, t = lane & 3;
    int wr = warp >> 2, wc = warp & 3;        // warp grid 2x4 -> warp tile 64x32
    int rowBase = blockIdx.x * BM;
    int colBase = blockIdx.y * BN;

    float acc[4][4][4];
#pragma unroll
    for (int mi = 0; mi < 4; mi++)
#pragma unroll
        for (int ni = 0; ni < 4; ni++)
#pragma unroll
            for (int v = 0; v < 4; v++) acc[mi][ni][v] = 0.f;

    // precompute per-thread load slots: 4 tiles x 2 slots, 16B each
    const __nv_bfloat16* srcs[4] = {Ah, Al, Bh, Bl};
    const __nv_bfloat16* gsrc[8];
    uint32_t soff[8];
    int okv[8];
#pragma unroll
    for (int tle = 0; tle < 4; tle++) {
#pragma unroll
        for (int j = 0; j < 2; j++) {
            int u = j * 256 + tid;            // 0..511
            int row = u >> 2;                 // 0..127
            int c = u & 3;                    // 16B chunk
            bool isB = (tle >= 2);
            int base = isB ? colBase : rowBase;
            int gr = base + row;
            bool ok = (!isB) || (gr < N);
            gsrc[tle * 2 + j] = srcs[tle] + ((size_t)(ok ? gr : base) * K + c * 8);
            soff[tle * 2 + j] = tle * TILE_BYTES + row * (PADK * 2) + c * 16;
            okv[tle * 2 + j] = ok ? 16 : 0;
        }
    }

    const int nch = K / BKC;

    // prologue: stage 0
#pragma unroll
    for (int e = 0; e < 8; e++) cp_async16(sb + soff[e], gsrc[e], okv[e]);
    cp_commit();

    for (int ck = 0; ck < nch; ck++) {
        int stage = ck & 1;
        // prefetch next chunk into other stage
        if (ck + 1 < nch) {
            uint32_t sdst = sb + (stage ^ 1) * STAGE_BYTES;
            size_t gstep = (size_t)(ck + 1) * BKC;
#pragma unroll
            for (int e = 0; e < 8; e++)
                cp_async16(sdst + soff[e], gsrc[e] + gstep, okv[e]);
        }
        cp_commit();
        cp_wait1();
        __syncthreads();

        const char* sp = smem + stage * STAGE_BYTES;
        const __nv_bfloat16* sAh = (const __nv_bfloat16*)sp;
        const __nv_bfloat16* sAl = (const __nv_bfloat16*)(sp + TILE_BYTES);
        const __nv_bfloat16* sBh = (const __nv_bfloat16*)(sp + 2 * TILE_BYTES);
        const __nv_bfloat16* sBl = (const __nv_bfloat16*)(sp + 3 * TILE_BYTES);

#pragma unroll
        for (int ks = 0; ks < 2; ks++) {
            int kk = ks * 16 + t * 2;
            uint32_t ah[4][4], al[4][4];
#pragma unroll
            for (int mi = 0; mi < 4; mi++) {
                int r = (wr * 64 + mi * 16 + g) * PADK;
                ah[mi][0] = *(const uint32_t*)&sAh[r + kk];
                ah[mi][1] = *(const uint32_t*)&sAh[r + 8 * PADK + kk];
                ah[mi][2] = *(const uint32_t*)&sAh[r + kk + 8];
                ah[mi][3] = *(const uint32_t*)&sAh[r + 8 * PADK + kk + 8];
                al[mi][0] = *(const uint32_t*)&sAl[r + kk];
                al[mi][1] = *(const uint32_t*)&sAl[r + 8 * PADK + kk];
                al[mi][2] = *(const uint32_t*)&sAl[r + kk + 8];
                al[mi][3] = *(const uint32_t*)&sAl[r + 8 * PADK + kk + 8];
            }
#pragma unroll
            for (int ni = 0; ni < 4; ni++) {
                int nb = (wc * 32 + ni * 8 + g) * PADK;
                uint32_t bh[2], bl[2];
                bh[0] = *(const uint32_t*)&sBh[nb + kk];
                bh[1] = *(const uint32_t*)&sBh[nb + kk + 8];
                bl[0] = *(const uint32_t*)&sBl[nb + kk];
                bl[1] = *(const uint32_t*)&sBl[nb + kk + 8];
#pragma unroll
                for (int mi = 0; mi < 4; mi++) {
                    mma16816(acc[mi][ni], ah[mi], bh);
                    mma16816(acc[mi][ni], ah[mi], bl);
                    mma16816(acc[mi][ni], al[mi], bh);
                }
            }
        }
        __syncthreads();
    }

    // ---- epilogue ----
    // Vector (8B) stores require N even so that row*N + even-col is 8B aligned.
    // N odd (logits, N=50257) falls back to scalar stores.
    const bool evenN = ((N & 1) == 0);
#pragma unroll
    for (int mi = 0; mi < 4; mi++) {
        int r0 = rowBase + wr * 64 + mi * 16 + g;
#pragma unroll
        for (int ni = 0; ni < 4; ni++) {
            int c0 = colBase + wc * 32 + ni * 8 + t * 2;
            if (c0 >= N) continue;
            bool full = (c0 + 1 < N);
#pragma unroll
            for (int half = 0; half < 2; half++) {
                int row = r0 + half * 8;
                float v0 = acc[mi][ni][half * 2 + 0];
                float v1 = acc[mi][ni][half * 2 + 1];
                if (bias) { v0 += bias[c0]; if (full) v1 += bias[c0 + 1]; }
                size_t o = (size_t)row * N + c0;
                if (gelu_split) {
                    // only used with even N (FF=3072)
                    v0 = 0.5f * v0 * (1.f + erff(v0 * 0.70710678118654752f));
                    v1 = 0.5f * v1 * (1.f + erff(v1 * 0.70710678118654752f));
                    __nv_bfloat16 h0 = __float2bfloat16(v0);
                    __nv_bfloat16 h1 = __float2bfloat16(v1);
                    __nv_bfloat16 l0 = __float2bfloat16(v0 - __bfloat162float(h0));
                    __nv_bfloat16 l1 = __float2bfloat16(v1 - __bfloat162float(h1));
                    if (full && evenN) {
                        *(__nv_bfloat162*)&Chi[o] = __nv_bfloat162(h0, h1);
                        *(__nv_bfloat162*)&Clo[o] = __nv_bfloat162(l0, l1);
                    } else {
                        Chi[o] = h0; Clo[o] = l0;
                        if (full) { Chi[o + 1] = h1; Clo[o + 1] = l1; }
                    }
                } else {
                    if (res) {
                        if (full && evenN) { float2 rr = *(const float2*)&res[o]; v0 += rr.x; v1 += rr.y; }
                        else { v0 += res[o]; if (full) v1 += res[o + 1]; }
                    }
                    if (full && evenN) {
                        *(float2*)&Cf[o] = make_float2(v0, v1);
                    } else {
                        Cf[o] = v0;
                        if (full) Cf[o + 1] = v1;
                    }
                }
            }
        }
    }
}

// ---------------- embedding ----------------
__global__ void embed_kernel(const int* __restrict__ idx,
                             const float* __restrict__ wte,
                             const float* __restrict__ wpe,
                             float* __restrict__ x)
{
    int bt = blockIdx.x;
    int t  = bt % TT;
    int tok = idx[bt];
    const float* te = wte + (size_t)tok * DMODEL;
    const float* pe = wpe + (size_t)t * DMODEL;
    float* xr = x + (size_t)bt * DMODEL;
    for (int d = threadIdx.x; d < DMODEL; d += blockDim.x)
        xr[d] = te[d] + pe[d];
}

// ---------------- layernorm with split bf16 output ----------------
__global__ void ln_split_kernel(const float* __restrict__ x,
                                const float* __restrict__ s,
                                const float* __restrict__ b,
                                __nv_bfloat16* __restrict__ yh,
                                __nv_bfloat16* __restrict__ yl)
{
    __shared__ float red[256];
    int row = blockIdx.x;
    const float* xr = x + (size_t)row * DMODEL;

    float sum = 0.f, sq = 0.f;
    for (int d = threadIdx.x; d < DMODEL; d += 256) {
        float v = xr[d];
        sum += v; sq += v * v;
    }
    red[threadIdx.x] = sum; __syncthreads();
    for (int o = 128; o > 0; o >>= 1) { if (threadIdx.x < o) red[threadIdx.x] += red[threadIdx.x + o]; __syncthreads(); }
    float mean = red[0] / DMODEL; __syncthreads();
    red[threadIdx.x] = sq; __syncthreads();
    for (int o = 128; o > 0; o >>= 1) { if (threadIdx.x < o) red[threadIdx.x] += red[threadIdx.x + o]; __syncthreads(); }
    float var = red[0] / DMODEL - mean * mean;
    float rstd = rsqrtf(var + 1e-5f);
    for (int d = threadIdx.x; d < DMODEL; d += 256) {
        float v = (xr[d] - mean) * rstd * s[d] + b[d];
        split2(v, &yh[(size_t)row * DMODEL + d], &yl[(size_t)row * DMODEL + d]);
    }
}

// ---------------- weight preparation ----------------
__global__ void prep_qkv_kernel(const float* __restrict__ Wq, const float* __restrict__ Wk,
                                const float* __restrict__ Wv,
                                const float* __restrict__ bq, const float* __restrict__ bk,
                                const float* __restrict__ bv, int layer,
                                __nv_bfloat16* __restrict__ wh, __nv_bfloat16* __restrict__ wl,
                                float* __restrict__ bqkv)
{
    int i = blockIdx.x * blockDim.x + threadIdx.x;
    if (i >= QKVN * DMODEL) return;
    int n = i / DMODEL, k = i % DMODEL;
    int sel = n / DMODEL;            // 0=q 1=k 2=v
    int r = n % DMODEL;
    int h = r / HS, e = r % HS;
    const float* W = (sel == 0) ? Wq : (sel == 1) ? Wk : Wv;
    float v = W[((((size_t)layer * NH + h) * DMODEL) + k) * HS + e];
    split2(v, &wh[i], &wl[i]);
    if (k == 0) {
        const float* bp = (sel == 0) ? bq : (sel == 1) ? bk : bv;
        bqkv[n] = bp[(size_t)layer * DMODEL + r];
    }
}

// tiled transpose+split: src [K,N] fp32 -> oh/ol K-major [N,K] bf16
__global__ void prep_T_kernel(const float* __restrict__ src,
                              __nv_bfloat16* __restrict__ oh, __nv_bfloat16* __restrict__ ol,
                              int K, int N)
{
    __shared__ float tile[32][33];
    int kb = blockIdx.x * 32, nb = blockIdx.y * 32;
    int tx = threadIdx.x, ty = threadIdx.y;   // 32 x 8
#pragma unroll
    for (int j = ty; j < 32; j += 8) {
        int k = kb + j, n = nb + tx;
        tile[j][tx] = (k < K && n < N) ? src[(size_t)k * N + n] : 0.f;
    }
    __syncthreads();
#pragma unroll
    for (int j = ty; j < 32; j += 8) {
        int n = nb + j, k = kb + tx;
        if (n < N && k < K)
            split2(tile[tx][j], &oh[(size_t)n * K + k], &ol[(size_t)n * K + k]);
    }
}

// wte split (vectorized x4): src fp32 [n], n % 4 == 0
__global__ void prep_split_kernel(const float* __restrict__ src,
                                  __nv_bfloat16* __restrict__ oh, __nv_bfloat16* __restrict__ ol,
                                  int n4)
{
    int i = blockIdx.x * blockDim.x + threadIdx.x;
    if (i >= n4) return;
    float4 v = *(const float4*)&src[i * 4];
    __nv_bfloat16 h[4], l[4];
    split2(v.x, &h[0], &l[0]);
    split2(v.y, &h[1], &l[1]);
    split2(v.z, &h[2], &l[2]);
    split2(v.w, &h[3], &l[3]);
    *(uint2*)&oh[i * 4] = *(uint2*)h;
    *(uint2*)&ol[i * 4] = *(uint2*)l;
}

// ---------------- attention ----------------
__global__ void attn_kernel(const float* __restrict__ qkv,
                            __nv_bfloat16* __restrict__ oh,
                            __nv_bfloat16* __restrict__ ol)
{
    __shared__ float qs[HS];
    __shared__ float sc[TT];
    __shared__ float red[128];

    int tq = blockIdx.x, h = blockIdx.y, b = blockIdx.z;
    int tid = threadIdx.x;
    size_t qrow = (size_t)(b * TT + tq) * QKVN;

    if (tid < HS) qs[tid] = qkv[qrow + h * HS + tid];
    __syncthreads();

    int n = tq + 1;
    for (int tk = tid; tk < n; tk += 128) {
        const float* kr = qkv + (size_t)(b * TT + tk) * QKVN + DMODEL + h * HS;
        float s = 0.f;
#pragma unroll
        for (int e = 0; e < HS; e++) s = fmaf(qs[e], kr[e], s);
        sc[tk] = s;
    }
    __syncthreads();

    float mx = -1e30f;
    for (int tk = tid; tk < n; tk += 128) mx = fmaxf(mx, sc[tk]);
    red[tid] = mx; __syncthreads();
    for (int off = 64; off > 0; off >>= 1) { if (tid < off) red[tid] = fmaxf(red[tid], red[tid + off]); __syncthreads(); }
    mx = red[0]; __syncthreads();

    float sum = 0.f;
    for (int tk = tid; tk < n; tk += 128) { float p = expf(sc[tk] - mx); sc[tk] = p; sum += p; }
    red[tid] = sum; __syncthreads();
    for (int off = 64; off > 0; off >>= 1) { if (tid < off) red[tid] += red[tid + off]; __syncthreads(); }
    float inv = 1.f / (red[0] * 8.0f);   // post-softmax / sqrt(HS)
    __syncthreads();

    int e = tid & 63;
    int half = tid >> 6;
    float accv = 0.f;
    for (int tk = half; tk < n; tk += 2)
        accv = fmaf(sc[tk], qkv[(size_t)(b * TT + tk) * QKVN + 2 * DMODEL + h * HS + e], accv);
    red[tid] = accv; __syncthreads();
    if (half == 0) {
        float o = (red[e] + red[e + 64]) * inv;
        size_t oo = (size_t)(b * TT + tq) * DMODEL + h * HS + e;
        split2(o, &oh[oo], &ol[oo]);
    }
}

// ---------------- loss (single-pass online softmax) ----------------
__global__ void lossrow_kernel(const float* __restrict__ logits,
                               const int* __restrict__ targets,
                               float* __restrict__ rowloss)
{
    __shared__ float rm[256], rs[256];
    int r = blockIdx.x;
    const float* p = logits + (size_t)r * VOCAB;

    float m = -1e30f, s = 0.f;
    for (int i = threadIdx.x; i < VOCAB; i += 256) {
        float v = p[i];
        float nm = fmaxf(m, v);
        s = s * expf(m - nm) + expf(v - nm);
        m = nm;
    }
    rm[threadIdx.x] = m; rs[threadIdx.x] = s; __syncthreads();
    for (int o = 128; o > 0; o >>= 1) {
        if (threadIdx.x < o) {
            float m2 = rm[threadIdx.x + o], s2 = rs[threadIdx.x + o];
            float nm = fmaxf(rm[threadIdx.x], m2);
            rs[threadIdx.x] = rs[threadIdx.x] * expf(rm[threadIdx.x] - nm) + s2 * expf(m2 - nm);
            rm[threadIdx.x] = nm;
        }
        __syncthreads();
    }
    if (threadIdx.x == 0) {
        int t = targets[r];
        rowloss[r] = -(p[t] - rm[0] - logf(rs[0]));
    }
}

__global__ void lossred_kernel(const float* __restrict__ rowloss, float* __restrict__ out)
{
    __shared__ float red[256];
    float s = 0.f;
    for (int i = threadIdx.x; i < BT; i += 256) s += rowloss[i];
    red[threadIdx.x] = s; __syncthreads();
    for (int o = 128; o > 0; o >>= 1) { if (threadIdx.x < o) red[threadIdx.x] += red[threadIdx.x + o]; __syncthreads(); }
    if (threadIdx.x == 0) out[0] = red[0] / (float)BT;
}

// ---------------- host ----------------
template <typename T>
static T* symaddr(const void* sym)
{
    void* p = nullptr;
    cudaGetSymbolAddress(&p, sym);
    return (T*)p;
}

static void launch_gemm(const __nv_bfloat16* Ah, const __nv_bfloat16* Al,
                        const __nv_bfloat16* Bh, const __nv_bfloat16* Bl,
                        const float* bias, const float* res,
                        float* Cf, __nv_bfloat16* Chi, __nv_bfloat16* Clo,
                        int M, int N, int K, int gelu_split)
{
    dim3 grid(M / BM, (N + BN - 1) / BN);
    mm_gemm<<<grid, 256, GSMEM_BYTES>>>(Ah, Al, Bh, Bl, bias, res, Cf, Chi, Clo, M, N, K, gelu_split);
}

extern "C" void kernel_launch(void* const* d_in, const int* in_sizes, int n_in,
                              void* d_out, int out_size)
{
    const int*   idx     = (const int*)d_in[0];
    const int*   targets = (const int*)d_in[1];
    const float* wte     = (const float*)d_in[2];
    const float* wpe     = (const float*)d_in[3];
    const float* ln1_s   = (const float*)d_in[4];
    const float* ln1_b   = (const float*)d_in[5];
    const float* ln2_s   = (const float*)d_in[6];
    const float* ln2_b   = (const float*)d_in[7];
    const float* Wq      = (const float*)d_in[8];
    const float* bq      = (const float*)d_in[9];
    const float* Wk      = (const float*)d_in[10];
    const float* bk      = (const float*)d_in[11];
    const float* Wv      = (const float*)d_in[12];
    const float* bv      = (const float*)d_in[13];
    const float* Wo      = (const float*)d_in[14];
    const float* bo      = (const float*)d_in[15];
    const float* W1      = (const float*)d_in[16];
    const float* b1      = (const float*)d_in[17];
    const float* W2      = (const float*)d_in[18];
    const float* b2      = (const float*)d_in[19];
    const float* lnf_s   = (const float*)d_in[20];
    const float* lnf_b   = (const float*)d_in[21];

    float* out = (float*)d_out;

    (void)cudaFuncSetAttribute(mm_gemm, cudaFuncAttributeMaxDynamicSharedMemorySize, GSMEM_BYTES);

    float* x    = symaddr<float>(g_x);
    float* qkv  = symaddr<float>(g_qkv);
    float* bqkv = symaddr<float>(g_bqkv);
    float* rowloss = symaddr<float>(g_rowloss);
    __nv_bfloat16* hh  = symaddr<__nv_bfloat16>(g_hh);
    __nv_bfloat16* hl  = symaddr<__nv_bfloat16>(g_hl);
    __nv_bfloat16* ffh = symaddr<__nv_bfloat16>(g_ffh);
    __nv_bfloat16* ffl = symaddr<__nv_bfloat16>(g_ffl);
    __nv_bfloat16* ath = symaddr<__nv_bfloat16>(g_ath);
    __nv_bfloat16* atl = symaddr<__nv_bfloat16>(g_atl);
    __nv_bfloat16* wqkvh = symaddr<__nv_bfloat16>(g_wqkvh);
    __nv_bfloat16* wqkvl = symaddr<__nv_bfloat16>(g_wqkvl);
    __nv_bfloat16* woh = symaddr<__nv_bfloat16>(g_woh);
    __nv_bfloat16* wol = symaddr<__nv_bfloat16>(g_wol);
    __nv_bfloat16* w1h = symaddr<__nv_bfloat16>(g_w1h);
    __nv_bfloat16* w1l = symaddr<__nv_bfloat16>(g_w1l);
    __nv_bfloat16* w2h = symaddr<__nv_bfloat16>(g_w2h);
    __nv_bfloat16* w2l = symaddr<__nv_bfloat16>(g_w2l);
    __nv_bfloat16* wteh = symaddr<__nv_bfloat16>(g_wteh);
    __nv_bfloat16* wtel = symaddr<__nv_bfloat16>(g_wtel);

    // embeddings + wte split
    embed_kernel<<<BT, 256>>>(idx, wte, wpe, x);
    {
        const int n4 = (VOCAB * DMODEL) / 4;
        prep_split_kernel<<<(n4 + 255) / 256, 256>>>(wte, wteh, wtel, n4);
    }

    for (int l = 0; l < LAYERS; l++) {
        ln_split_kernel<<<BT, 256>>>(x, ln1_s + l * DMODEL, ln1_b + l * DMODEL, hh, hl);

        {
            const int n = QKVN * DMODEL;
            prep_qkv_kernel<<<(n + 255) / 256, 256>>>(Wq, Wk, Wv, bq, bk, bv, l, wqkvh, wqkvl, bqkv);
        }
        launch_gemm(hh, hl, wqkvh, wqkvl, bqkv, nullptr, qkv, nullptr, nullptr,
                    BT, QKVN, DMODEL, 0);

        dim3 agrid(TT, NH, BB);
        attn_kernel<<<agrid, 128>>>(qkv, ath, atl);

        {
            dim3 tg(DMODEL / 32, DMODEL / 32);
            prep_T_kernel<<<tg, dim3(32, 8)>>>(Wo + (size_t)l * DMODEL * DMODEL, woh, wol, DMODEL, DMODEL);
        }
        launch_gemm(ath, atl, woh, wol, bo + l * DMODEL, x, x, nullptr, nullptr,
                    BT, DMODEL, DMODEL, 0);

        ln_split_kernel<<<BT, 256>>>(x, ln2_s + l * DMODEL, ln2_b + l * DMODEL, hh, hl);
        {
            dim3 tg(DMODEL / 32, FF / 32);
            prep_T_kernel<<<tg, dim3(32, 8)>>>(W1 + (size_t)l * DMODEL * FF, w1h, w1l, DMODEL, FF);
        }
        launch_gemm(hh, hl, w1h, w1l, b1 + l * FF, nullptr, nullptr, ffh, ffl,
                    BT, FF, DMODEL, 1);                     // GELU + split
        {
            dim3 tg(FF / 32, DMODEL / 32);
            prep_T_kernel<<<tg, dim3(32, 8)>>>(W2 + (size_t)l * FF * DMODEL, w2h, w2l, FF, DMODEL);
        }
        launch_gemm(ffh, ffl, w2h, w2l, b2 + l * DMODEL, x, x, nullptr, nullptr,
                    BT, DMODEL, FF, 0);
    }

    ln_split_kernel<<<BT, 256>>>(x, lnf_s, lnf_b, hh, hl);

    // logits = h @ wte^T  (N odd -> scalar epilogue path)
    launch_gemm(hh, hl, wteh, wtel, nullptr, nullptr, out, nullptr, nullptr,
                BT, VOCAB, DMODEL, 0);

    const long long NL = (long long)BT * VOCAB;
    lossrow_kernel<<<BT, 256>>>(out, targets, rowloss);
    if ((long long)out_size > NL)
        lossred_kernel<<<1, 256>>>(rowloss, out + NL);
}

// round 10
// speedup vs baseline: 2.2368x; 1.0351x over previous
#include <cuda_runtime.h>
#include <cuda_bf16.h>
#include <math.h>
#include <stdint.h>

// ---------------- problem constants ----------------
#define LAYERS 2
#define NH     12
#define DMODEL 768
#define HS     64
#define FF     3072
#define VOCAB  50257
#define BB     4
#define TT     512
#define BT     2048
#define QKVN   2304      // fused q|k|v output width

// ---------------- device scratch ----------------
__device__ float g_x[BT*DMODEL];
__device__ float g_qkv[BT*QKVN];
__device__ float g_rowloss[BT];
__device__ float g_bqkv[QKVN];

__device__ __nv_bfloat16 g_hh[BT*DMODEL],  g_hl[BT*DMODEL];
__device__ __nv_bfloat16 g_ffh[BT*FF],     g_ffl[BT*FF];
__device__ __nv_bfloat16 g_ath[BT*DMODEL], g_atl[BT*DMODEL];
__device__ __nv_bfloat16 g_wqkvh[QKVN*DMODEL], g_wqkvl[QKVN*DMODEL];
__device__ __nv_bfloat16 g_woh[DMODEL*DMODEL], g_wol[DMODEL*DMODEL];
__device__ __nv_bfloat16 g_w1h[FF*DMODEL],     g_w1l[FF*DMODEL];
__device__ __nv_bfloat16 g_w2h[DMODEL*FF],     g_w2l[DMODEL*FF];
__device__ __nv_bfloat16 g_wteh[VOCAB*DMODEL], g_wtel[VOCAB*DMODEL];

// ---------------- helpers ----------------
__device__ __forceinline__ uint32_t smem_u32(const void* p) {
    uint32_t a;
    asm("{ .reg .u64 t; cvta.to.shared.u64 t, %1; cvt.u32.u64 %0, t; }" : "=r"(a) : "l"(p));
    return a;
}
__device__ __forceinline__ void cp_async16(uint32_t saddr, const void* gptr, int src_bytes) {
    asm volatile("cp.async.cg.shared.global [%0], [%1], 16, %2;"
                 :: "r"(saddr), "l"(gptr), "r"(src_bytes) : "memory");
}
__device__ __forceinline__ void cp_commit() { asm volatile("cp.async.commit_group;" ::: "memory"); }
__device__ __forceinline__ void cp_wait1()  { asm volatile("cp.async.wait_group 1;" ::: "memory"); }

__device__ __forceinline__ void ldsm_x4(uint32_t* r, uint32_t addr) {
    asm volatile("ldmatrix.sync.aligned.m8n8.x4.shared.b16 {%0,%1,%2,%3}, [%4];"
                 : "=r"(r[0]), "=r"(r[1]), "=r"(r[2]), "=r"(r[3]) : "r"(addr));
}

__device__ __forceinline__ void mma16816(float* c, const uint32_t* a, uint32_t b0, uint32_t b1) {
    asm volatile(
        "mma.sync.aligned.m16n8k16.row.col.f32.bf16.bf16.f32 "
        "{%0,%1,%2,%3}, {%4,%5,%6,%7}, {%8,%9}, {%0,%1,%2,%3};"
        : "+f"(c[0]), "+f"(c[1]), "+f"(c[2]), "+f"(c[3])
        : "r"(a[0]), "r"(a[1]), "r"(a[2]), "r"(a[3]), "r"(b0), "r"(b1));
}

__device__ __forceinline__ void split2(float v, __nv_bfloat16* hi, __nv_bfloat16* lo) {
    __nv_bfloat16 h = __float2bfloat16(v);
    *hi = h;
    *lo = __float2bfloat16(v - __bfloat162float(h));
}

// ---------------- bf16 hi/lo split GEMM (double-buffered cp.async + ldmatrix) --
#define BM 128
#define BN 128
#define BKC 32
#define PADK 40                              // SMEM row stride in bf16 (80 B)
#define TILE_BYTES (128*PADK*2)              // 10240
#define STAGE_BYTES (4*TILE_BYTES)           // 40960
#define GSMEM_BYTES (2*STAGE_BYTES)          // 81920

__global__ void __launch_bounds__(256, 2)
mm_gemm(const __nv_bfloat16* __restrict__ Ah, const __nv_bfloat16* __restrict__ Al,
        const __nv_bfloat16* __restrict__ Bh, const __nv_bfloat16* __restrict__ Bl,
        const float* __restrict__ bias, const float* __restrict__ res,
        float* __restrict__ Cf, __nv_bfloat16* __restrict__ Chi, __nv_bfloat16* __restrict__ Clo,
        int M, int N, int K, int gelu_split)
{
    extern __shared__ char smem[];
    uint32_t sb = smem_u32(smem);

    int tid = threadIdx.x, warp = tid >> 5, lane = tid & 31;
    int wr = warp >> 2, wc = warp & 3;        // warp grid 2x4 -> warp tile 64x32
    int rowBase = blockIdx.x * BM;
    int colBase = blockIdx.y * BN;

    float acc[4][4][4];
#pragma unroll
    for (int mi = 0; mi < 4; mi++)
#pragma unroll
        for (int ni = 0; ni < 4; ni++)
#pragma unroll
            for (int v = 0; v < 4; v++) acc[mi][ni][v] = 0.f;

    // ldmatrix per-lane byte offsets (within a tile)
    uint32_t aoff[4], boff[2];
#pragma unroll
    for (int mi = 0; mi < 4; mi++)
        aoff[mi] = (uint32_t)(wr * 64 + mi * 16 + (lane & 15)) * (PADK * 2) + (lane >> 4) * 16;
#pragma unroll
    for (int p = 0; p < 2; p++)
        boff[p] = (uint32_t)(wc * 32 + p * 16 + (lane & 15)) * (PADK * 2) + (lane >> 4) * 16;

    // precompute per-thread load slots: 4 tiles x 2 slots, 16B each
    const __nv_bfloat16* srcs[4] = {Ah, Al, Bh, Bl};
    const __nv_bfloat16* gsrc[8];
    uint32_t soff[8];
    int okv[8];
#pragma unroll
    for (int tle = 0; tle < 4; tle++) {
#pragma unroll
        for (int j = 0; j < 2; j++) {
            int u = j * 256 + tid;            // 0..511
            int row = u >> 2;                 // 0..127
            int c = u & 3;                    // 16B chunk
            bool isB = (tle >= 2);
            int base = isB ? colBase : rowBase;
            int gr = base + row;
            bool ok = (!isB) || (gr < N);
            gsrc[tle * 2 + j] = srcs[tle] + ((size_t)(ok ? gr : base) * K + c * 8);
            soff[tle * 2 + j] = tle * TILE_BYTES + row * (PADK * 2) + c * 16;
            okv[tle * 2 + j] = ok ? 16 : 0;
        }
    }

    const int nch = K / BKC;

    // prologue: stage 0
#pragma unroll
    for (int e = 0; e < 8; e++) cp_async16(sb + soff[e], gsrc[e], okv[e]);
    cp_commit();

    for (int ck = 0; ck < nch; ck++) {
        int stage = ck & 1;
        // prefetch next chunk into other stage
        if (ck + 1 < nch) {
            uint32_t sdst = sb + (stage ^ 1) * STAGE_BYTES;
            size_t gstep = (size_t)(ck + 1) * BKC;
#pragma unroll
            for (int e = 0; e < 8; e++)
                cp_async16(sdst + soff[e], gsrc[e] + gstep, okv[e]);
        }
        cp_commit();
        cp_wait1();
        __syncthreads();

        uint32_t sAh = sb + stage * STAGE_BYTES;
        uint32_t sAl = sAh + TILE_BYTES;
        uint32_t sBh = sAh + 2 * TILE_BYTES;
        uint32_t sBl = sAh + 3 * TILE_BYTES;

#pragma unroll
        for (int ks = 0; ks < 2; ks++) {
            uint32_t ko = ks * 32;            // 16 bf16 = 32 bytes per k16 step
            // B fragments for all 4 ni (2 x ldmatrix.x4 per hi/lo)
            uint32_t bh[2][4], bl[2][4];
#pragma unroll
            for (int p = 0; p < 2; p++) {
                ldsm_x4(bh[p], sBh + boff[p] + ko);
                ldsm_x4(bl[p], sBl + boff[p] + ko);
            }
#pragma unroll
            for (int mi = 0; mi < 4; mi++) {
                uint32_t ahf[4], alf[4];
                ldsm_x4(ahf, sAh + aoff[mi] + ko);
                ldsm_x4(alf, sAl + aoff[mi] + ko);
#pragma unroll
                for (int ni = 0; ni < 4; ni++) {
                    int p = ni >> 1, w = ni & 1;
                    uint32_t b0h = bh[p][w], b1h = bh[p][w + 2];
                    uint32_t b0l = bl[p][w], b1l = bl[p][w + 2];
                    mma16816(acc[mi][ni], ahf, b0h, b1h);
                    mma16816(acc[mi][ni], ahf, b0l, b1l);
                    mma16816(acc[mi][ni], alf, b0h, b1h);
                }
            }
        }
        __syncthreads();
    }

    // ---- epilogue ----
    // Vector (8B) stores require N even (row*N + even-col stays 8B aligned).
    // N odd (logits, N=50257) falls back to scalar stores.
    int g = lane >> 2, t = lane & 3;
    const bool evenN = ((N & 1) == 0);
#pragma unroll
    for (int mi = 0; mi < 4; mi++) {
        int r0 = rowBase + wr * 64 + mi * 16 + g;
#pragma unroll
        for (int ni = 0; ni < 4; ni++) {
            int c0 = colBase + wc * 32 + ni * 8 + t * 2;
            if (c0 >= N) continue;
            bool full = (c0 + 1 < N);
#pragma unroll
            for (int half = 0; half < 2; half++) {
                int row = r0 + half * 8;
                float v0 = acc[mi][ni][half * 2 + 0];
                float v1 = acc[mi][ni][half * 2 + 1];
                if (bias) { v0 += bias[c0]; if (full) v1 += bias[c0 + 1]; }
                size_t o = (size_t)row * N + c0;
                if (gelu_split) {
                    // only used with even N (FF=3072)
                    v0 = 0.5f * v0 * (1.f + erff(v0 * 0.70710678118654752f));
                    v1 = 0.5f * v1 * (1.f + erff(v1 * 0.70710678118654752f));
                    __nv_bfloat16 h0 = __float2bfloat16(v0);
                    __nv_bfloat16 h1 = __float2bfloat16(v1);
                    __nv_bfloat16 l0 = __float2bfloat16(v0 - __bfloat162float(h0));
                    __nv_bfloat16 l1 = __float2bfloat16(v1 - __bfloat162float(h1));
                    if (full && evenN) {
                        *(__nv_bfloat162*)&Chi[o] = __nv_bfloat162(h0, h1);
                        *(__nv_bfloat162*)&Clo[o] = __nv_bfloat162(l0, l1);
                    } else {
                        Chi[o] = h0; Clo[o] = l0;
                        if (full) { Chi[o + 1] = h1; Clo[o + 1] = l1; }
                    }
                } else {
                    if (res) {
                        if (full && evenN) { float2 rr = *(const float2*)&res[o]; v0 += rr.x; v1 += rr.y; }
                        else { v0 += res[o]; if (full) v1 += res[o + 1]; }
                    }
                    if (full && evenN) {
                        *(float2*)&Cf[o] = make_float2(v0, v1);
                    } else {
                        Cf[o] = v0;
                        if (full) Cf[o + 1] = v1;
                    }
                }
            }
        }
    }
}

// ---------------- embedding ----------------
__global__ void embed_kernel(const int* __restrict__ idx,
                             const float* __restrict__ wte,
                             const float* __restrict__ wpe,
                             float* __restrict__ x)
{
    int bt = blockIdx.x;
    int t  = bt % TT;
    int tok = idx[bt];
    const float* te = wte + (size_t)tok * DMODEL;
    const float* pe = wpe + (size_t)t * DMODEL;
    float* xr = x + (size_t)bt * DMODEL;
    for (int d = threadIdx.x; d < DMODEL; d += blockDim.x)
        xr[d] = te[d] + pe[d];
}

// ---------------- layernorm with split bf16 output ----------------
__global__ void ln_split_kernel(const float* __restrict__ x,
                                const float* __restrict__ s,
                                const float* __restrict__ b,
                                __nv_bfloat16* __restrict__ yh,
                                __nv_bfloat16* __restrict__ yl)
{
    __shared__ float red[256];
    int row = blockIdx.x;
    const float* xr = x + (size_t)row * DMODEL;

    float sum = 0.f, sq = 0.f;
    for (int d = threadIdx.x; d < DMODEL; d += 256) {
        float v = xr[d];
        sum += v; sq += v * v;
    }
    red[threadIdx.x] = sum; __syncthreads();
    for (int o = 128; o > 0; o >>= 1) { if (threadIdx.x < o) red[threadIdx.x] += red[threadIdx.x + o]; __syncthreads(); }
    float mean = red[0] / DMODEL; __syncthreads();
    red[threadIdx.x] = sq; __syncthreads();
    for (int o = 128; o > 0; o >>= 1) { if (threadIdx.x < o) red[threadIdx.x] += red[threadIdx.x + o]; __syncthreads(); }
    float var = red[0] / DMODEL - mean * mean;
    float rstd = rsqrtf(var + 1e-5f);
    for (int d = threadIdx.x; d < DMODEL; d += 256) {
        float v = (xr[d] - mean) * rstd * s[d] + b[d];
        split2(v, &yh[(size_t)row * DMODEL + d], &yl[(size_t)row * DMODEL + d]);
    }
}

// ---------------- weight preparation ----------------
__global__ void prep_qkv_kernel(const float* __restrict__ Wq, const float* __restrict__ Wk,
                                const float* __restrict__ Wv,
                                const float* __restrict__ bq, const float* __restrict__ bk,
                                const float* __restrict__ bv, int layer,
                                __nv_bfloat16* __restrict__ wh, __nv_bfloat16* __restrict__ wl,
                                float* __restrict__ bqkv)
{
    int i = blockIdx.x * blockDim.x + threadIdx.x;
    if (i >= QKVN * DMODEL) return;
    int n = i / DMODEL, k = i % DMODEL;
    int sel = n / DMODEL;            // 0=q 1=k 2=v
    int r = n % DMODEL;
    int h = r / HS, e = r % HS;
    const float* W = (sel == 0) ? Wq : (sel == 1) ? Wk : Wv;
    float v = W[((((size_t)layer * NH + h) * DMODEL) + k) * HS + e];
    split2(v, &wh[i], &wl[i]);
    if (k == 0) {
        const float* bp = (sel == 0) ? bq : (sel == 1) ? bk : bv;
        bqkv[n] = bp[(size_t)layer * DMODEL + r];
    }
}

// tiled transpose+split: src [K,N] fp32 -> oh/ol K-major [N,K] bf16
__global__ void prep_T_kernel(const float* __restrict__ src,
                              __nv_bfloat16* __restrict__ oh, __nv_bfloat16* __restrict__ ol,
                              int K, int N)
{
    __shared__ float tile[32][33];
    int kb = blockIdx.x * 32, nb = blockIdx.y * 32;
    int tx = threadIdx.x, ty = threadIdx.y;   // 32 x 8
#pragma unroll
    for (int j = ty; j < 32; j += 8) {
        int k = kb + j, n = nb + tx;
        tile[j][tx] = (k < K && n < N) ? src[(size_t)k * N + n] : 0.f;
    }
    __syncthreads();
#pragma unroll
    for (int j = ty; j < 32; j += 8) {
        int n = nb + j, k = kb + tx;
        if (n < N && k < K)
            split2(tile[tx][j], &oh[(size_t)n * K + k], &ol[(size_t)n * K + k]);
    }
}

// wte split (vectorized x4): src fp32 [n], n % 4 == 0
__global__ void prep_split_kernel(const float* __restrict__ src,
                                  __nv_bfloat16* __restrict__ oh, __nv_bfloat16* __restrict__ ol,
                                  int n4)
{
    int i = blockIdx.x * blockDim.x + threadIdx.x;
    if (i >= n4) return;
    float4 v = *(const float4*)&src[i * 4];
    __nv_bfloat16 h[4], l[4];
    split2(v.x, &h[0], &l[0]);
    split2(v.y, &h[1], &l[1]);
    split2(v.z, &h[2], &l[2]);
    split2(v.w, &h[3], &l[3]);
    *(uint2*)&oh[i * 4] = *(uint2*)h;
    *(uint2*)&ol[i * 4] = *(uint2*)l;
}

// ---------------- attention ----------------
__global__ void attn_kernel(const float* __restrict__ qkv,
                            __nv_bfloat16* __restrict__ oh,
                            __nv_bfloat16* __restrict__ ol)
{
    __shared__ float qs[HS];
    __shared__ float sc[TT];
    __shared__ float red[128];

    int tq = blockIdx.x, h = blockIdx.y, b = blockIdx.z;
    int tid = threadIdx.x;
    size_t qrow = (size_t)(b * TT + tq) * QKVN;

    if (tid < HS) qs[tid] = qkv[qrow + h * HS + tid];
    __syncthreads();

    int n = tq + 1;
    for (int tk = tid; tk < n; tk += 128) {
        const float* kr = qkv + (size_t)(b * TT + tk) * QKVN + DMODEL + h * HS;
        float s = 0.f;
#pragma unroll
        for (int e = 0; e < HS; e++) s = fmaf(qs[e], kr[e], s);
        sc[tk] = s;
    }
    __syncthreads();

    float mx = -1e30f;
    for (int tk = tid; tk < n; tk += 128) mx = fmaxf(mx, sc[tk]);
    red[tid] = mx; __syncthreads();
    for (int off = 64; off > 0; off >>= 1) { if (tid < off) red[tid] = fmaxf(red[tid], red[tid + off]); __syncthreads(); }
    mx = red[0]; __syncthreads();

    float sum = 0.f;
    for (int tk = tid; tk < n; tk += 128) { float p = expf(sc[tk] - mx); sc[tk] = p; sum += p; }
    red[tid] = sum; __syncthreads();
    for (int off = 64; off > 0; off >>= 1) { if (tid < off) red[tid] += red[tid + off]; __syncthreads(); }
    float inv = 1.f / (red[0] * 8.0f);   // post-softmax / sqrt(HS)
    __syncthreads();

    int e = tid & 63;
    int half = tid >> 6;
    float accv = 0.f;
    for (int tk = half; tk < n; tk += 2)
        accv = fmaf(sc[tk], qkv[(size_t)(b * TT + tk) * QKVN + 2 * DMODEL + h * HS + e], accv);
    red[tid] = accv; __syncthreads();
    if (half == 0) {
        float o = (red[e] + red[e + 64]) * inv;
        size_t oo = (size_t)(b * TT + tq) * DMODEL + h * HS + e;
        split2(o, &oh[oo], &ol[oo]);
    }
}

// ---------------- loss (single-pass online softmax) ----------------
__global__ void lossrow_kernel(const float* __restrict__ logits,
                               const int* __restrict__ targets,
                               float* __restrict__ rowloss)
{
    __shared__ float rm[256], rs[256];
    int r = blockIdx.x;
    const float* p = logits + (size_t)r * VOCAB;

    float m = -1e30f, s = 0.f;
    for (int i = threadIdx.x; i < VOCAB; i += 256) {
        float v = p[i];
        float nm = fmaxf(m, v);
        s = s * expf(m - nm) + expf(v - nm);
        m = nm;
    }
    rm[threadIdx.x] = m; rs[threadIdx.x] = s; __syncthreads();
    for (int o = 128; o > 0; o >>= 1) {
        if (threadIdx.x < o) {
            float m2 = rm[threadIdx.x + o], s2 = rs[threadIdx.x + o];
            float nm = fmaxf(rm[threadIdx.x], m2);
            rs[threadIdx.x] = rs[threadIdx.x] * expf(rm[threadIdx.x] - nm) + s2 * expf(m2 - nm);
            rm[threadIdx.x] = nm;
        }
        __syncthreads();
    }
    if (threadIdx.x == 0) {
        int t = targets[r];
        rowloss[r] = -(p[t] - rm[0] - logf(rs[0]));
    }
}

__global__ void lossred_kernel(const float* __restrict__ rowloss, float* __restrict__ out)
{
    __shared__ float red[256];
    float s = 0.f;
    for (int i = threadIdx.x; i < BT; i += 256) s += rowloss[i];
    red[threadIdx.x] = s; __syncthreads();
    for (int o = 128; o > 0; o >>= 1) { if (threadIdx.x < o) red[threadIdx.x] += red[threadIdx.x + o]; __syncthreads(); }
    if (threadIdx.x == 0) out[0] = red[0] / (float)BT;
}

// ---------------- host ----------------
template <typename T>
static T* symaddr(const void* sym)
{
    void* p = nullptr;
    cudaGetSymbolAddress(&p, sym);
    return (T*)p;
}

static void launch_gemm(const __nv_bfloat16* Ah, const __nv_bfloat16* Al,
                        const __nv_bfloat16* Bh, const __nv_bfloat16* Bl,
                        const float* bias, const float* res,
                        float* Cf, __nv_bfloat16* Chi, __nv_bfloat16* Clo,
                        int M, int N, int K, int gelu_split)
{
    dim3 grid(M / BM, (N + BN - 1) / BN);
    mm_gemm<<<grid, 256, GSMEM_BYTES>>>(Ah, Al, Bh, Bl, bias, res, Cf, Chi, Clo, M, N, K, gelu_split);
}

extern "C" void kernel_launch(void* const* d_in, const int* in_sizes, int n_in,
                              void* d_out, int out_size)
{
    const int*   idx     = (const int*)d_in[0];
    const int*   targets = (const int*)d_in[1];
    const float* wte     = (const float*)d_in[2];
    const float* wpe     = (const float*)d_in[3];
    const float* ln1_s   = (const float*)d_in[4];
    const float* ln1_b   = (const float*)d_in[5];
    const float* ln2_s   = (const float*)d_in[6];
    const float* ln2_b   = (const float*)d_in[7];
    const float* Wq      = (const float*)d_in[8];
    const float* bq      = (const float*)d_in[9];
    const float* Wk      = (const float*)d_in[10];
    const float* bk      = (const float*)d_in[11];
    const float* Wv      = (const float*)d_in[12];
    const float* bv      = (const float*)d_in[13];
    const float* Wo      = (const float*)d_in[14];
    const float* bo      = (const float*)d_in[15];
    const float* W1      = (const float*)d_in[16];
    const float* b1      = (const float*)d_in[17];
    const float* W2      = (const float*)d_in[18];
    const float* b2      = (const float*)d_in[19];
    const float* lnf_s   = (const float*)d_in[20];
    const float* lnf_b   = (const float*)d_in[21];

    float* out = (float*)d_out;

    (void)cudaFuncSetAttribute(mm_gemm, cudaFuncAttributeMaxDynamicSharedMemorySize, GSMEM_BYTES);

    float* x    = symaddr<float>(g_x);
    float* qkv  = symaddr<float>(g_qkv);
    float* bqkv = symaddr<float>(g_bqkv);
    float* rowloss = symaddr<float>(g_rowloss);
    __nv_bfloat16* hh  = symaddr<__nv_bfloat16>(g_hh);
    __nv_bfloat16* hl  = symaddr<__nv_bfloat16>(g_hl);
    __nv_bfloat16* ffh = symaddr<__nv_bfloat16>(g_ffh);
    __nv_bfloat16* ffl = symaddr<__nv_bfloat16>(g_ffl);
    __nv_bfloat16* ath = symaddr<__nv_bfloat16>(g_ath);
    __nv_bfloat16* atl = symaddr<__nv_bfloat16>(g_atl);
    __nv_bfloat16* wqkvh = symaddr<__nv_bfloat16>(g_wqkvh);
    __nv_bfloat16* wqkvl = symaddr<__nv_bfloat16>(g_wqkvl);
    __nv_bfloat16* woh = symaddr<__nv_bfloat16>(g_woh);
    __nv_bfloat16* wol = symaddr<__nv_bfloat16>(g_wol);
    __nv_bfloat16* w1h = symaddr<__nv_bfloat16>(g_w1h);
    __nv_bfloat16* w1l = symaddr<__nv_bfloat16>(g_w1l);
    __nv_bfloat16* w2h = symaddr<__nv_bfloat16>(g_w2h);
    __nv_bfloat16* w2l = symaddr<__nv_bfloat16>(g_w2l);
    __nv_bfloat16* wteh = symaddr<__nv_bfloat16>(g_wteh);
    __nv_bfloat16* wtel = symaddr<__nv_bfloat16>(g_wtel);

    // Launch order: index 3 is the QKV mm_gemm so the fixed ncu window
    // (observed to capture launch index 3) profiles the GEMM next round.
    embed_kernel<<<BT, 256>>>(idx, wte, wpe, x);                                   // 0

    for (int l = 0; l < LAYERS; l++) {
        ln_split_kernel<<<BT, 256>>>(x, ln1_s + l * DMODEL, ln1_b + l * DMODEL, hh, hl);   // 1

        {
            const int n = QKVN * DMODEL;
            prep_qkv_kernel<<<(n + 255) / 256, 256>>>(Wq, Wk, Wv, bq, bk, bv, l, wqkvh, wqkvl, bqkv); // 2
        }
        launch_gemm(hh, hl, wqkvh, wqkvl, bqkv, nullptr, qkv, nullptr, nullptr,
                    BT, QKVN, DMODEL, 0);                                          // 3  <- profiled

        dim3 agrid(TT, NH, BB);
        attn_kernel<<<agrid, 128>>>(qkv, ath, atl);

        {
            dim3 tg(DMODEL / 32, DMODEL / 32);
            prep_T_kernel<<<tg, dim3(32, 8)>>>(Wo + (size_t)l * DMODEL * DMODEL, woh, wol, DMODEL, DMODEL);
        }
        launch_gemm(ath, atl, woh, wol, bo + l * DMODEL, x, x, nullptr, nullptr,
                    BT, DMODEL, DMODEL, 0);

        ln_split_kernel<<<BT, 256>>>(x, ln2_s + l * DMODEL, ln2_b + l * DMODEL, hh, hl);
        {
            dim3 tg(DMODEL / 32, FF / 32);
            prep_T_kernel<<<tg, dim3(32, 8)>>>(W1 + (size_t)l * DMODEL * FF, w1h, w1l, DMODEL, FF);
        }
        launch_gemm(hh, hl, w1h, w1l, b1 + l * FF, nullptr, nullptr, ffh, ffl,
                    BT, FF, DMODEL, 1);                     // GELU + split
        {
            dim3 tg(FF / 32, DMODEL / 32);
            prep_T_kernel<<<tg, dim3(32, 8)>>>(W2 + (size_t)l * FF * DMODEL, w2h, w2l, FF, DMODEL);
        }
        launch_gemm(ffh, ffl, w2h, w2l, b2 + l * DMODEL, x, x, nullptr, nullptr,
                    BT, DMODEL, FF, 0);
    }

    ln_split_kernel<<<BT, 256>>>(x, lnf_s, lnf_b, hh, hl);

    // wte split just before use (keeps early launch indices stable)
    {
        const int n4 = (VOCAB * DMODEL) / 4;
        prep_split_kernel<<<(n4 + 255) / 256, 256>>>(wte, wteh, wtel, n4);
    }

    // logits = h @ wte^T  (N odd -> scalar epilogue path)
    launch_gemm(hh, hl, wteh, wtel, nullptr, nullptr, out, nullptr, nullptr,
                BT, VOCAB, DMODEL, 0);

    const long long NL = (long long)BT * VOCAB;
    lossrow_kernel<<<BT, 256>>>(out, targets, rowloss);
    if ((long long)out_size > NL)
        lossred_kernel<<<1, 256>>>(rowloss, out + NL);
}

// round 12
// speedup vs baseline: 3.4795x; 1.5556x over previous
#include <cuda_runtime.h>
#include <cuda_bf16.h>
#include <math.h>
#include <stdint.h>

// ---------------- problem constants ----------------
#define LAYERS 2
#define NH     12
#define DMODEL 768
#define HS     64
#define FF     3072
#define VOCAB  50257
#define BB     4
#define TT     512
#define BT     2048
#define QKVN   2304      // fused q|k|v output width

// ---------------- device scratch ----------------
__device__ float g_x[BT*DMODEL];
__device__ float g_qkv[BT*QKVN];
__device__ float g_rowloss[BT];
__device__ float g_bqkv[QKVN];

__device__ __nv_bfloat16 g_hh[BT*DMODEL],  g_hl[BT*DMODEL];
__device__ __nv_bfloat16 g_ffh[BT*FF],     g_ffl[BT*FF];
__device__ __nv_bfloat16 g_ath[BT*DMODEL], g_atl[BT*DMODEL];
__device__ __nv_bfloat16 g_wqkvh[QKVN*DMODEL], g_wqkvl[QKVN*DMODEL];
__device__ __nv_bfloat16 g_woh[DMODEL*DMODEL], g_wol[DMODEL*DMODEL];
__device__ __nv_bfloat16 g_w1h[FF*DMODEL],     g_w1l[FF*DMODEL];
__device__ __nv_bfloat16 g_w2h[DMODEL*FF],     g_w2l[DMODEL*FF];
__device__ __nv_bfloat16 g_wteh[VOCAB*DMODEL], g_wtel[VOCAB*DMODEL];

// ---------------- helpers ----------------
__device__ __forceinline__ uint32_t smem_u32(const void* p) {
    uint32_t a;
    asm("{ .reg .u64 t; cvta.to.shared.u64 t, %1; cvt.u32.u64 %0, t; }" : "=r"(a) : "l"(p));
    return a;
}
__device__ __forceinline__ void cp_async16(uint32_t saddr, const void* gptr, int src_bytes) {
    asm volatile("cp.async.cg.shared.global [%0], [%1], 16, %2;"
                 :: "r"(saddr), "l"(gptr), "r"(src_bytes) : "memory");
}
__device__ __forceinline__ void cp_commit() { asm volatile("cp.async.commit_group;" ::: "memory"); }
__device__ __forceinline__ void cp_wait1()  { asm volatile("cp.async.wait_group 1;" ::: "memory"); }

__device__ __forceinline__ void ldsm_x4(uint32_t* r, uint32_t addr) {
    asm volatile("ldmatrix.sync.aligned.m8n8.x4.shared.b16 {%0,%1,%2,%3}, [%4];"
                 : "=r"(r[0]), "=r"(r[1]), "=r"(r[2]), "=r"(r[3]) : "r"(addr));
}

// NOTE: intentionally NOT volatile — pure register dataflow; lets ptxas
// schedule independent MMAs between same-accumulator dependents.
__device__ __forceinline__ void mma16816(float* c, const uint32_t* a, uint32_t b0, uint32_t b1) {
    asm("mma.sync.aligned.m16n8k16.row.col.f32.bf16.bf16.f32 "
        "{%0,%1,%2,%3}, {%4,%5,%6,%7}, {%8,%9}, {%0,%1,%2,%3};"
        : "+f"(c[0]), "+f"(c[1]), "+f"(c[2]), "+f"(c[3])
        : "r"(a[0]), "r"(a[1]), "r"(a[2]), "r"(a[3]), "r"(b0), "r"(b1));
}

__device__ __forceinline__ void split2(float v, __nv_bfloat16* hi, __nv_bfloat16* lo) {
    __nv_bfloat16 h = __float2bfloat16(v);
    *hi = h;
    *lo = __float2bfloat16(v - __bfloat162float(h));
}

// ---------------- bf16 hi/lo split GEMM (double-buffered cp.async + ldmatrix) --
#define BM 128
#define BN 128
#define BKC 32
#define PADK 40                              // SMEM row stride in bf16 (80 B)
#define TILE_BYTES (128*PADK*2)              // 10240
#define STAGE_BYTES (4*TILE_BYTES)           // 40960
#define GSMEM_BYTES (2*STAGE_BYTES)          // 81920

__global__ void __launch_bounds__(256, 2)
mm_gemm(const __nv_bfloat16* __restrict__ Ah, const __nv_bfloat16* __restrict__ Al,
        const __nv_bfloat16* __restrict__ Bh, const __nv_bfloat16* __restrict__ Bl,
        const float* __restrict__ bias, const float* __restrict__ res,
        float* __restrict__ Cf, __nv_bfloat16* __restrict__ Chi, __nv_bfloat16* __restrict__ Clo,
        int M, int N, int K, int gelu_split)
{
    extern __shared__ char smem[];
    uint32_t sb = smem_u32(smem);

    int tid = threadIdx.x, warp = tid >> 5, lane = tid & 31;
    int wr = warp >> 2, wc = warp & 3;        // warp grid 2x4 -> warp tile 64x32
    int rowBase = blockIdx.x * BM;
    int colBase = blockIdx.y * BN;

    float acc[4][4][4];
#pragma unroll
    for (int mi = 0; mi < 4; mi++)
#pragma unroll
        for (int ni = 0; ni < 4; ni++)
#pragma unroll
            for (int v = 0; v < 4; v++) acc[mi][ni][v] = 0.f;

    // ldmatrix per-lane byte offsets (within a tile)
    uint32_t aoff[4], boff[2];
#pragma unroll
    for (int mi = 0; mi < 4; mi++)
        aoff[mi] = (uint32_t)(wr * 64 + mi * 16 + (lane & 15)) * (PADK * 2) + (lane >> 4) * 16;
#pragma unroll
    for (int p = 0; p < 2; p++)
        boff[p] = (uint32_t)(wc * 32 + p * 16 + (lane & 15)) * (PADK * 2) + (lane >> 4) * 16;

    // precompute per-thread load slots: 4 tiles x 2 slots, 16B each
    const __nv_bfloat16* srcs[4] = {Ah, Al, Bh, Bl};
    const __nv_bfloat16* gsrc[8];
    uint32_t soff[8];
    int okv[8];
#pragma unroll
    for (int tle = 0; tle < 4; tle++) {
#pragma unroll
        for (int j = 0; j < 2; j++) {
            int u = j * 256 + tid;            // 0..511
            int row = u >> 2;                 // 0..127
            int c = u & 3;                    // 16B chunk
            bool isB = (tle >= 2);
            int base = isB ? colBase : rowBase;
            int gr = base + row;
            bool ok = (!isB) || (gr < N);
            gsrc[tle * 2 + j] = srcs[tle] + ((size_t)(ok ? gr : base) * K + c * 8);
            soff[tle * 2 + j] = tle * TILE_BYTES + row * (PADK * 2) + c * 16;
            okv[tle * 2 + j] = ok ? 16 : 0;
        }
    }

    const int nch = K / BKC;

    // prologue: stage 0
#pragma unroll
    for (int e = 0; e < 8; e++) cp_async16(sb + soff[e], gsrc[e], okv[e]);
    cp_commit();

    for (int ck = 0; ck < nch; ck++) {
        int stage = ck & 1;
        // prefetch next chunk into other stage
        if (ck + 1 < nch) {
            uint32_t sdst = sb + (stage ^ 1) * STAGE_BYTES;
            size_t gstep = (size_t)(ck + 1) * BKC;
#pragma unroll
            for (int e = 0; e < 8; e++)
                cp_async16(sdst + soff[e], gsrc[e] + gstep, okv[e]);
        }
        cp_commit();
        cp_wait1();
        __syncthreads();

        uint32_t sAh = sb + stage * STAGE_BYTES;
        uint32_t sAl = sAh + TILE_BYTES;
        uint32_t sBh = sAh + 2 * TILE_BYTES;
        uint32_t sBl = sAh + 3 * TILE_BYTES;

#pragma unroll
        for (int ks = 0; ks < 2; ks++) {
            uint32_t ko = ks * 32;            // 16 bf16 = 32 bytes per k16 step
            // B fragments for all 4 ni (2 x ldmatrix.x4 per hi/lo)
            uint32_t bh[2][4], bl[2][4];
#pragma unroll
            for (int p = 0; p < 2; p++) {
                ldsm_x4(bh[p], sBh + boff[p] + ko);
                ldsm_x4(bl[p], sBl + boff[p] + ko);
            }
#pragma unroll
            for (int mi = 0; mi < 4; mi++) {
                uint32_t ahf[4], alf[4];
                ldsm_x4(ahf, sAh + aoff[mi] + ko);
                ldsm_x4(alf, sAl + aoff[mi] + ko);
                // term-major: same-accumulator MMAs are 4 apart (RAW chain broken)
#pragma unroll
                for (int ni = 0; ni < 4; ni++) {
                    int p = ni >> 1, w = ni & 1;
                    mma16816(acc[mi][ni], ahf, bh[p][w], bh[p][w + 2]);
                }
#pragma unroll
                for (int ni = 0; ni < 4; ni++) {
                    int p = ni >> 1, w = ni & 1;
                    mma16816(acc[mi][ni], ahf, bl[p][w], bl[p][w + 2]);
                }
#pragma unroll
                for (int ni = 0; ni < 4; ni++) {
                    int p = ni >> 1, w = ni & 1;
                    mma16816(acc[mi][ni], alf, bh[p][w], bh[p][w + 2]);
                }
            }
        }
        __syncthreads();
    }

    // ---- epilogue ----
    // Vector (8B) stores require N even (row*N + even-col stays 8B aligned).
    // N odd (logits, N=50257) falls back to scalar stores.
    int g = lane >> 2, t = lane & 3;
    const bool evenN = ((N & 1) == 0);
#pragma unroll
    for (int mi = 0; mi < 4; mi++) {
        int r0 = rowBase + wr * 64 + mi * 16 + g;
#pragma unroll
        for (int ni = 0; ni < 4; ni++) {
            int c0 = colBase + wc * 32 + ni * 8 + t * 2;
            if (c0 >= N) continue;
            bool full = (c0 + 1 < N);
#pragma unroll
            for (int half = 0; half < 2; half++) {
                int row = r0 + half * 8;
                float v0 = acc[mi][ni][half * 2 + 0];
                float v1 = acc[mi][ni][half * 2 + 1];
                if (bias) { v0 += bias[c0]; if (full) v1 += bias[c0 + 1]; }
                size_t o = (size_t)row * N + c0;
                if (gelu_split) {
                    // only used with even N (FF=3072)
                    v0 = 0.5f * v0 * (1.f + erff(v0 * 0.70710678118654752f));
                    v1 = 0.5f * v1 * (1.f + erff(v1 * 0.70710678118654752f));
                    __nv_bfloat16 h0 = __float2bfloat16(v0);
                    __nv_bfloat16 h1 = __float2bfloat16(v1);
                    __nv_bfloat16 l0 = __float2bfloat16(v0 - __bfloat162float(h0));
                    __nv_bfloat16 l1 = __float2bfloat16(v1 - __bfloat162float(h1));
                    if (full && evenN) {
                        *(__nv_bfloat162*)&Chi[o] = __nv_bfloat162(h0, h1);
                        *(__nv_bfloat162*)&Clo[o] = __nv_bfloat162(l0, l1);
                    } else {
                        Chi[o] = h0; Clo[o] = l0;
                        if (full) { Chi[o + 1] = h1; Clo[o + 1] = l1; }
                    }
                } else {
                    if (res) {
                        if (full && evenN) { float2 rr = *(const float2*)&res[o]; v0 += rr.x; v1 += rr.y; }
                        else { v0 += res[o]; if (full) v1 += res[o + 1]; }
                    }
                    if (full && evenN) {
                        *(float2*)&Cf[o] = make_float2(v0, v1);
                    } else {
                        Cf[o] = v0;
                        if (full) Cf[o + 1] = v1;
                    }
                }
            }
        }
    }
}

// ---------------- embedding ----------------
__global__ void embed_kernel(const int* __restrict__ idx,
                             const float* __restrict__ wte,
                             const float* __restrict__ wpe,
                             float* __restrict__ x)
{
    int bt = blockIdx.x;
    int t  = bt % TT;
    int tok = idx[bt];
    const float* te = wte + (size_t)tok * DMODEL;
    const float* pe = wpe + (size_t)t * DMODEL;
    float* xr = x + (size_t)bt * DMODEL;
    for (int d = threadIdx.x; d < DMODEL; d += blockDim.x)
        xr[d] = te[d] + pe[d];
}

// ---------------- layernorm with split bf16 output ----------------
__global__ void ln_split_kernel(const float* __restrict__ x,
                                const float* __restrict__ s,
                                const float* __restrict__ b,
                                __nv_bfloat16* __restrict__ yh,
                                __nv_bfloat16* __restrict__ yl)
{
    __shared__ float red[256];
    int row = blockIdx.x;
    const float* xr = x + (size_t)row * DMODEL;

    float sum = 0.f, sq = 0.f;
    for (int d = threadIdx.x; d < DMODEL; d += 256) {
        float v = xr[d];
        sum += v; sq += v * v;
    }
    red[threadIdx.x] = sum; __syncthreads();
    for (int o = 128; o > 0; o >>= 1) { if (threadIdx.x < o) red[threadIdx.x] += red[threadIdx.x + o]; __syncthreads(); }
    float mean = red[0] / DMODEL; __syncthreads();
    red[threadIdx.x] = sq; __syncthreads();
    for (int o = 128; o > 0; o >>= 1) { if (threadIdx.x < o) red[threadIdx.x] += red[threadIdx.x + o]; __syncthreads(); }
    float var = red[0] / DMODEL - mean * mean;
    float rstd = rsqrtf(var + 1e-5f);
    for (int d = threadIdx.x; d < DMODEL; d += 256) {
        float v = (xr[d] - mean) * rstd * s[d] + b[d];
        split2(v, &yh[(size_t)row * DMODEL + d], &yl[(size_t)row * DMODEL + d]);
    }
}

// ---------------- weight preparation ----------------
__global__ void prep_qkv_kernel(const float* __restrict__ Wq, const float* __restrict__ Wk,
                                const float* __restrict__ Wv,
                                const float* __restrict__ bq, const float* __restrict__ bk,
                                const float* __restrict__ bv, int layer,
                                __nv_bfloat16* __restrict__ wh, __nv_bfloat16* __restrict__ wl,
                                float* __restrict__ bqkv)
{
    int i = blockIdx.x * blockDim.x + threadIdx.x;
    if (i >= QKVN * DMODEL) return;
    int n = i / DMODEL, k = i % DMODEL;
    int sel = n / DMODEL;            // 0=q 1=k 2=v
    int r = n % DMODEL;
    int h = r / HS, e = r % HS;
    const float* W = (sel == 0) ? Wq : (sel == 1) ? Wk : Wv;
    float v = W[((((size_t)layer * NH + h) * DMODEL) + k) * HS + e];
    split2(v, &wh[i], &wl[i]);
    if (k == 0) {
        const float* bp = (sel == 0) ? bq : (sel == 1) ? bk : bv;
        bqkv[n] = bp[(size_t)layer * DMODEL + r];
    }
}

// tiled transpose+split: src [K,N] fp32 -> oh/ol K-major [N,K] bf16
__global__ void prep_T_kernel(const float* __restrict__ src,
                              __nv_bfloat16* __restrict__ oh, __nv_bfloat16* __restrict__ ol,
                              int K, int N)
{
    __shared__ float tile[32][33];
    int kb = blockIdx.x * 32, nb = blockIdx.y * 32;
    int tx = threadIdx.x, ty = threadIdx.y;   // 32 x 8
#pragma unroll
    for (int j = ty; j < 32; j += 8) {
        int k = kb + j, n = nb + tx;
        tile[j][tx] = (k < K && n < N) ? src[(size_t)k * N + n] : 0.f;
    }
    __syncthreads();
#pragma unroll
    for (int j = ty; j < 32; j += 8) {
        int n = nb + j, k = kb + tx;
        if (n < N && k < K)
            split2(tile[tx][j], &oh[(size_t)n * K + k], &ol[(size_t)n * K + k]);
    }
}

// wte split (vectorized x4): src fp32 [n], n % 4 == 0
__global__ void prep_split_kernel(const float* __restrict__ src,
                                  __nv_bfloat16* __restrict__ oh, __nv_bfloat16* __restrict__ ol,
                                  int n4)
{
    int i = blockIdx.x * blockDim.x + threadIdx.x;
    if (i >= n4) return;
    float4 v = *(const float4*)&src[i * 4];
    __nv_bfloat16 h[4], l[4];
    split2(v.x, &h[0], &l[0]);
    split2(v.y, &h[1], &l[1]);
    split2(v.z, &h[2], &l[2]);
    split2(v.w, &h[3], &l[3]);
    *(uint2*)&oh[i * 4] = *(uint2*)h;
    *(uint2*)&ol[i * 4] = *(uint2*)l;
}

// ---------------- attention ----------------
__global__ void attn_kernel(const float* __restrict__ qkv,
                            __nv_bfloat16* __restrict__ oh,
                            __nv_bfloat16* __restrict__ ol)
{
    __shared__ float qs[HS];
    __shared__ float sc[TT];
    __shared__ float red[128];

    int tq = blockIdx.x, h = blockIdx.y, b = blockIdx.z;
    int tid = threadIdx.x;
    size_t qrow = (size_t)(b * TT + tq) * QKVN;

    if (tid < HS) qs[tid] = qkv[qrow + h * HS + tid];
    __syncthreads();

    int n = tq + 1;
    for (int tk = tid; tk < n; tk += 128) {
        const float4* kr = (const float4*)(qkv + (size_t)(b * TT + tk) * QKVN + DMODEL + h * HS);
        float s = 0.f;
#pragma unroll
        for (int e4 = 0; e4 < HS / 4; e4++) {
            float4 kv = kr[e4];
            const float4* q4 = (const float4*)&qs[e4 * 4];
            s = fmaf(q4->x, kv.x, s);
            s = fmaf(q4->y, kv.y, s);
            s = fmaf(q4->z, kv.z, s);
            s = fmaf(q4->w, kv.w, s);
        }
        sc[tk] = s;
    }
    __syncthreads();

    float mx = -1e30f;
    for (int tk = tid; tk < n; tk += 128) mx = fmaxf(mx, sc[tk]);
    red[tid] = mx; __syncthreads();
    for (int off = 64; off > 0; off >>= 1) { if (tid < off) red[tid] = fmaxf(red[tid], red[tid + off]); __syncthreads(); }
    mx = red[0]; __syncthreads();

    float sum = 0.f;
    for (int tk = tid; tk < n; tk += 128) { float p = expf(sc[tk] - mx); sc[tk] = p; sum += p; }
    red[tid] = sum; __syncthreads();
    for (int off = 64; off > 0; off >>= 1) { if (tid < off) red[tid] += red[tid + off]; __syncthreads(); }
    float inv = 1.f / (red[0] * 8.0f);   // post-softmax / sqrt(HS)
    __syncthreads();

    int e = tid & 63;
    int half = tid >> 6;
    float accv = 0.f;
    for (int tk = half; tk < n; tk += 2)
        accv = fmaf(sc[tk], qkv[(size_t)(b * TT + tk) * QKVN + 2 * DMODEL + h * HS + e], accv);
    red[tid] = accv; __syncthreads();
    if (half == 0) {
        float o = (red[e] + red[e + 64]) * inv;
        size_t oo = (size_t)(b * TT + tq) * DMODEL + h * HS + e;
        split2(o, &oh[oo], &ol[oo]);
    }
}

// ---------------- loss (single-pass online softmax) ----------------
__global__ void lossrow_kernel(const float* __restrict__ logits,
                               const int* __restrict__ targets,
                               float* __restrict__ rowloss)
{
    __shared__ float rm[256], rs[256];
    int r = blockIdx.x;
    const float* p = logits + (size_t)r * VOCAB;

    float m = -1e30f, s = 0.f;
    for (int i = threadIdx.x; i < VOCAB; i += 256) {
        float v = p[i];
        float nm = fmaxf(m, v);
        s = s * expf(m - nm) + expf(v - nm);
        m = nm;
    }
    rm[threadIdx.x] = m; rs[threadIdx.x] = s; __syncthreads();
    for (int o = 128; o > 0; o >>= 1) {
        if (threadIdx.x < o) {
            float m2 = rm[threadIdx.x + o], s2 = rs[threadIdx.x + o];
            float nm = fmaxf(rm[threadIdx.x], m2);
            rs[threadIdx.x] = rs[threadIdx.x] * expf(rm[threadIdx.x] - nm) + s2 * expf(m2 - nm);
            rm[threadIdx.x] = nm;
        }
        __syncthreads();
    }
    if (threadIdx.x == 0) {
        int t = targets[r];
        rowloss[r] = -(p[t] - rm[0] - logf(rs[0]));
    }
}

__global__ void lossred_kernel(const float* __restrict__ rowloss, float* __restrict__ out)
{
    __shared__ float red[256];
    float s = 0.f;
    for (int i = threadIdx.x; i < BT; i += 256) s += rowloss[i];
    red[threadIdx.x] = s; __syncthreads();
    for (int o = 128; o > 0; o >>= 1) { if (threadIdx.x < o) red[threadIdx.x] += red[threadIdx.x + o]; __syncthreads(); }
    if (threadIdx.x == 0) out[0] = red[0] / (float)BT;
}

// ---------------- host ----------------
template <typename T>
static T* symaddr(const void* sym)
{
    void* p = nullptr;
    cudaGetSymbolAddress(&p, sym);
    return (T*)p;
}

static void launch_gemm(const __nv_bfloat16* Ah, const __nv_bfloat16* Al,
                        const __nv_bfloat16* Bh, const __nv_bfloat16* Bl,
                        const float* bias, const float* res,
                        float* Cf, __nv_bfloat16* Chi, __nv_bfloat16* Clo,
                        int M, int N, int K, int gelu_split)
{
    dim3 grid(M / BM, (N + BN - 1) / BN);
    mm_gemm<<<grid, 256, GSMEM_BYTES>>>(Ah, Al, Bh, Bl, bias, res, Cf, Chi, Clo, M, N, K, gelu_split);
}

extern "C" void kernel_launch(void* const* d_in, const int* in_sizes, int n_in,
                              void* d_out, int out_size)
{
    const int*   idx     = (const int*)d_in[0];
    const int*   targets = (const int*)d_in[1];
    const float* wte     = (const float*)d_in[2];
    const float* wpe     = (const float*)d_in[3];
    const float* ln1_s   = (const float*)d_in[4];
    const float* ln1_b   = (const float*)d_in[5];
    const float* ln2_s   = (const float*)d_in[6];
    const float* ln2_b   = (const float*)d_in[7];
    const float* Wq      = (const float*)d_in[8];
    const float* bq      = (const float*)d_in[9];
    const float* Wk      = (const float*)d_in[10];
    const float* bk      = (const float*)d_in[11];
    const float* Wv      = (const float*)d_in[12];
    const float* bv      = (const float*)d_in[13];
    const float* Wo      = (const float*)d_in[14];
    const float* bo      = (const float*)d_in[15];
    const float* W1      = (const float*)d_in[16];
    const float* b1      = (const float*)d_in[17];
    const float* W2      = (const float*)d_in[18];
    const float* b2      = (const float*)d_in[19];
    const float* lnf_s   = (const float*)d_in[20];
    const float* lnf_b   = (const float*)d_in[21];

    float* out = (float*)d_out;

    (void)cudaFuncSetAttribute(mm_gemm, cudaFuncAttributeMaxDynamicSharedMemorySize, GSMEM_BYTES);

    float* x    = symaddr<float>(g_x);
    float* qkv  = symaddr<float>(g_qkv);
    float* bqkv = symaddr<float>(g_bqkv);
    float* rowloss = symaddr<float>(g_rowloss);
    __nv_bfloat16* hh  = symaddr<__nv_bfloat16>(g_hh);
    __nv_bfloat16* hl  = symaddr<__nv_bfloat16>(g_hl);
    __nv_bfloat16* ffh = symaddr<__nv_bfloat16>(g_ffh);
    __nv_bfloat16* ffl = symaddr<__nv_bfloat16>(g_ffl);
    __nv_bfloat16* ath = symaddr<__nv_bfloat16>(g_ath);
    __nv_bfloat16* atl = symaddr<__nv_bfloat16>(g_atl);
    __nv_bfloat16* wqkvh = symaddr<__nv_bfloat16>(g_wqkvh);
    __nv_bfloat16* wqkvl = symaddr<__nv_bfloat16>(g_wqkvl);
    __nv_bfloat16* woh = symaddr<__nv_bfloat16>(g_woh);
    __nv_bfloat16* wol = symaddr<__nv_bfloat16>(g_wol);
    __nv_bfloat16* w1h = symaddr<__nv_bfloat16>(g_w1h);
    __nv_bfloat16* w1l = symaddr<__nv_bfloat16>(g_w1l);
    __nv_bfloat16* w2h = symaddr<__nv_bfloat16>(g_w2h);
    __nv_bfloat16* w2l = symaddr<__nv_bfloat16>(g_w2l);
    __nv_bfloat16* wteh = symaddr<__nv_bfloat16>(g_wteh);
    __nv_bfloat16* wtel = symaddr<__nv_bfloat16>(g_wtel);

    // Launch order: index 3 is the QKV mm_gemm (ncu window profiles index 3).
    embed_kernel<<<BT, 256>>>(idx, wte, wpe, x);                                   // 0

    for (int l = 0; l < LAYERS; l++) {
        ln_split_kernel<<<BT, 256>>>(x, ln1_s + l * DMODEL, ln1_b + l * DMODEL, hh, hl);   // 1

        {
            const int n = QKVN * DMODEL;
            prep_qkv_kernel<<<(n + 255) / 256, 256>>>(Wq, Wk, Wv, bq, bk, bv, l, wqkvh, wqkvl, bqkv); // 2
        }
        launch_gemm(hh, hl, wqkvh, wqkvl, bqkv, nullptr, qkv, nullptr, nullptr,
                    BT, QKVN, DMODEL, 0);                                          // 3  <- profiled

        dim3 agrid(TT, NH, BB);
        attn_kernel<<<agrid, 128>>>(qkv, ath, atl);

        {
            dim3 tg(DMODEL / 32, DMODEL / 32);
            prep_T_kernel<<<tg, dim3(32, 8)>>>(Wo + (size_t)l * DMODEL * DMODEL, woh, wol, DMODEL, DMODEL);
        }
        launch_gemm(ath, atl, woh, wol, bo + l * DMODEL, x, x, nullptr, nullptr,
                    BT, DMODEL, DMODEL, 0);

        ln_split_kernel<<<BT, 256>>>(x, ln2_s + l * DMODEL, ln2_b + l * DMODEL, hh, hl);
        {
            dim3 tg(DMODEL / 32, FF / 32);
            prep_T_kernel<<<tg, dim3(32, 8)>>>(W1 + (size_t)l * DMODEL * FF, w1h, w1l, DMODEL, FF);
        }
        launch_gemm(hh, hl, w1h, w1l, b1 + l * FF, nullptr, nullptr, ffh, ffl,
                    BT, FF, DMODEL, 1);                     // GELU + split
        {
            dim3 tg(FF / 32, DMODEL / 32);
            prep_T_kernel<<<tg, dim3(32, 8)>>>(W2 + (size_t)l * FF * DMODEL, w2h, w2l, FF, DMODEL);
        }
        launch_gemm(ffh, ffl, w2h, w2l, b2 + l * DMODEL, x, x, nullptr, nullptr,
                    BT, DMODEL, FF, 0);
    }

    ln_split_kernel<<<BT, 256>>>(x, lnf_s, lnf_b, hh, hl);

    // wte split just before use (keeps early launch indices stable)
    {
        const int n4 = (VOCAB * DMODEL) / 4;
        prep_split_kernel<<<(n4 + 255) / 256, 256>>>(wte, wteh, wtel, n4);
    }

    // logits = h @ wte^T  (N odd -> scalar epilogue path)
    launch_gemm(hh, hl, wteh, wtel, nullptr, nullptr, out, nullptr, nullptr,
                BT, VOCAB, DMODEL, 0);

    const long long NL = (long long)BT * VOCAB;
    lossrow_kernel<<<BT, 256>>>(out, targets, rowloss);
    if ((long long)out_size > NL)
        lossred_kernel<<<1, 256>>>(rowloss, out + NL);
}

// round 14
// speedup vs baseline: 3.5582x; 1.0226x over previous
#include <cuda_runtime.h>
#include <cuda_bf16.h>
#include <math.h>
#include <stdint.h>

// ---------------- problem constants ----------------
#define LAYERS 2
#define NH     12
#define DMODEL 768
#define HS     64
#define FF     3072
#define VOCAB  50257
#define BB     4
#define TT     512
#define BT     2048
#define QKVN   2304      // fused q|k|v output width

// ---------------- device scratch ----------------
__device__ float g_x[BT*DMODEL];
__device__ float g_qkv[BT*QKVN];
__device__ float g_rowloss[BT];
__device__ float g_bqkv[QKVN];

__device__ __nv_bfloat16 g_hh[BT*DMODEL],  g_hl[BT*DMODEL];
__device__ __nv_bfloat16 g_ffh[BT*FF],     g_ffl[BT*FF];
__device__ __nv_bfloat16 g_ath[BT*DMODEL], g_atl[BT*DMODEL];
__device__ __nv_bfloat16 g_wqkvh[QKVN*DMODEL], g_wqkvl[QKVN*DMODEL];
__device__ __nv_bfloat16 g_woh[DMODEL*DMODEL], g_wol[DMODEL*DMODEL];
__device__ __nv_bfloat16 g_w1h[FF*DMODEL],     g_w1l[FF*DMODEL];
__device__ __nv_bfloat16 g_w2h[DMODEL*FF],     g_w2l[DMODEL*FF];
__device__ __nv_bfloat16 g_wteh[VOCAB*DMODEL], g_wtel[VOCAB*DMODEL];

// ---------------- helpers ----------------
__device__ __forceinline__ uint32_t smem_u32(const void* p) {
    uint32_t a;
    asm("{ .reg .u64 t; cvta.to.shared.u64 t, %1; cvt.u32.u64 %0, t; }" : "=r"(a) : "l"(p));
    return a;
}
__device__ __forceinline__ void cp_async16(uint32_t saddr, const void* gptr, int src_bytes) {
    asm volatile("cp.async.cg.shared.global [%0], [%1], 16, %2;"
                 :: "r"(saddr), "l"(gptr), "r"(src_bytes) : "memory");
}
__device__ __forceinline__ void cp_commit() { asm volatile("cp.async.commit_group;" ::: "memory"); }
__device__ __forceinline__ void cp_wait1()  { asm volatile("cp.async.wait_group 1;" ::: "memory"); }

__device__ __forceinline__ void ldsm_x4(uint32_t* r, uint32_t addr) {
    asm volatile("ldmatrix.sync.aligned.m8n8.x4.shared.b16 {%0,%1,%2,%3}, [%4];"
                 : "=r"(r[0]), "=r"(r[1]), "=r"(r[2]), "=r"(r[3]) : "r"(addr));
}

__device__ __forceinline__ void mma16816(float* c, const uint32_t* a, uint32_t b0, uint32_t b1) {
    asm("mma.sync.aligned.m16n8k16.row.col.f32.bf16.bf16.f32 "
        "{%0,%1,%2,%3}, {%4,%5,%6,%7}, {%8,%9}, {%0,%1,%2,%3};"
        : "+f"(c[0]), "+f"(c[1]), "+f"(c[2]), "+f"(c[3])
        : "r"(a[0]), "r"(a[1]), "r"(a[2]), "r"(a[3]), "r"(b0), "r"(b1));
}

__device__ __forceinline__ void split2(float v, __nv_bfloat16* hi, __nv_bfloat16* lo) {
    __nv_bfloat16 h = __float2bfloat16(v);
    *hi = h;
    *lo = __float2bfloat16(v - __bfloat162float(h));
}

// fast exp on the FMA pipe (input <= 0 after softmax shift); rel err ~1.5e-4
__device__ __forceinline__ float fast_exp(float x) {
    float t = x * 1.4426950408889634f;          // log2(e)
    t = fmaxf(t, -120.f);
    int   ni = __float2int_rd(t);
    float f  = t - (float)ni;
    float p = fmaf(f, 0.00133335581f, 0.00961812911f);
    p = fmaf(f, p, 0.0555041086f);
    p = fmaf(f, p, 0.240226507f);
    p = fmaf(f, p, 0.693147180f);
    p = fmaf(f, p, 1.0f);
    return __int_as_float(__float_as_int(p) + (ni << 23));
}

// SW128 swizzle (byte offset within a 128B-row tile)
__device__ __forceinline__ uint32_t swz(uint32_t b) { return b ^ ((b >> 3) & 0x70); }

// ---------------- bf16 hi/lo split GEMM: 3-stage pipeline, SW128, 1 bar/chunk --
// SMEM tile layout: [128 rows][128B], row = hi(64B)|lo(64B) of a 32-col K-chunk.
#define BM 128
#define BN 128
#define BKC 32
#define TILEB 16384                           // one operand tile (A or B)
#define STAGEB (2*TILEB)                      // A + B
#define GSTAGES 3
#define GSMEM_BYTES (GSTAGES*STAGEB)          // 98304

__global__ void __launch_bounds__(256, 2)
mm_gemm(const __nv_bfloat16* __restrict__ Ah, const __nv_bfloat16* __restrict__ Al,
        const __nv_bfloat16* __restrict__ Bh, const __nv_bfloat16* __restrict__ Bl,
        const float* __restrict__ bias, const float* __restrict__ res,
        float* __restrict__ Cf, __nv_bfloat16* __restrict__ Chi, __nv_bfloat16* __restrict__ Clo,
        int M, int N, int K, int gelu_split)
{
    extern __shared__ char smem[];
    uint32_t sb = smem_u32(smem);

    int tid = threadIdx.x, warp = tid >> 5, lane = tid & 31;
    int wr = warp >> 2, wc = warp & 3;        // warp grid 2x4 -> warp tile 64x32
    int rowBase = blockIdx.x * BM;
    int colBase = blockIdx.y * BN;

    float acc[4][4][4];
#pragma unroll
    for (int mi = 0; mi < 4; mi++)
#pragma unroll
        for (int ni = 0; ni < 4; ni++)
#pragma unroll
            for (int v = 0; v < 4; v++) acc[mi][ni][v] = 0.f;

    // ldmatrix unswizzled base offsets (hi section; +64 for lo, +32 for ks=1)
    uint32_t arow[4], brow[2];
#pragma unroll
    for (int mi = 0; mi < 4; mi++)
        arow[mi] = (uint32_t)(wr * 64 + mi * 16 + (lane & 15)) * 128 + (lane >> 4) * 16;
#pragma unroll
    for (int p = 0; p < 2; p++)
        brow[p] = (uint32_t)(wc * 32 + p * 16 + (lane & 15)) * 128 + (lane >> 4) * 16;

    // per-thread load slots: 2 tiles x 128 rows x 8 c16-chunks = 2048; 8 per thread
    const __nv_bfloat16* gsrc[8];
    uint32_t soff[8];
    int okmask = 0;
#pragma unroll
    for (int e = 0; e < 8; e++) {
        int u = e * 256 + tid;                // 0..2047
        int tile = u >> 10;                   // 0:A  1:B
        int rem = u & 1023;
        int row = rem >> 3;
        int c16 = rem & 7;                    // 0-3 hi, 4-7 lo
        bool isLo = (c16 >= 4);
        int cc = c16 & 3;
        const __nv_bfloat16* sp = (tile == 0) ? (isLo ? Al : Ah) : (isLo ? Bl : Bh);
        int base = tile ? colBase : rowBase;
        int gr = base + row;
        bool ok = (tile == 0) || (gr < N);
        gsrc[e] = sp + ((size_t)(ok ? gr : base) * K + cc * 8);
        soff[e] = tile * TILEB + swz((uint32_t)row * 128 + c16 * 16);
        if (ok) okmask |= (1 << e);
    }

    const int nch = K / BKC;

    // prologue: chunks 0,1 -> stages 0,1
#pragma unroll
    for (int s = 0; s < 2; s++) {
        uint32_t dst = sb + s * STAGEB;
#pragma unroll
        for (int e = 0; e < 8; e++)
            cp_async16(dst + soff[e], gsrc[e] + (size_t)s * BKC, ((okmask >> e) & 1) ? 16 : 0);
        cp_commit();
    }

    int stage = 0;
    for (int ck = 0; ck < nch; ck++) {
        cp_wait1();
        __syncthreads();

        uint32_t sA = sb + stage * STAGEB;
        uint32_t sB = sA + TILEB;

#pragma unroll
        for (int ks = 0; ks < 2; ks++) {
            uint32_t ko = ks * 32;
            uint32_t bh[2][4], bl[2][4];
#pragma unroll
            for (int p = 0; p < 2; p++) {
                ldsm_x4(bh[p], sB + swz(brow[p] + ko));
                ldsm_x4(bl[p], sB + swz(brow[p] + ko + 64));
            }
#pragma unroll
            for (int mi = 0; mi < 4; mi++) {
                uint32_t ahf[4], alf[4];
                ldsm_x4(ahf, sA + swz(arow[mi] + ko));
                ldsm_x4(alf, sA + swz(arow[mi] + ko + 64));
#pragma unroll
                for (int ni = 0; ni < 4; ni++) {
                    int p = ni >> 1, w = ni & 1;
                    mma16816(acc[mi][ni], ahf, bh[p][w], bh[p][w + 2]);
                }
#pragma unroll
                for (int ni = 0; ni < 4; ni++) {
                    int p = ni >> 1, w = ni & 1;
                    mma16816(acc[mi][ni], ahf, bl[p][w], bl[p][w + 2]);
                }
#pragma unroll
                for (int ni = 0; ni < 4; ni++) {
                    int p = ni >> 1, w = ni & 1;
                    mma16816(acc[mi][ni], alf, bh[p][w], bh[p][w + 2]);
                }
            }
        }

        // prefetch chunk ck+2 into the stage freed at iteration ck-1
        if (ck + 2 < nch) {
            int ps = stage + 2; if (ps >= GSTAGES) ps -= GSTAGES;
            uint32_t dst = sb + ps * STAGEB;
            size_t step = (size_t)(ck + 2) * BKC;
#pragma unroll
            for (int e = 0; e < 8; e++)
                cp_async16(dst + soff[e], gsrc[e] + step, ((okmask >> e) & 1) ? 16 : 0);
        }
        cp_commit();   // always commit (possibly empty group) to keep wait distance

        if (++stage == GSTAGES) stage = 0;
    }

    // ---- epilogue ----
    int g = lane >> 2, t = lane & 3;
    const bool evenN = ((N & 1) == 0);
#pragma unroll
    for (int mi = 0; mi < 4; mi++) {
        int r0 = rowBase + wr * 64 + mi * 16 + g;
#pragma unroll
        for (int ni = 0; ni < 4; ni++) {
            int c0 = colBase + wc * 32 + ni * 8 + t * 2;
            if (c0 >= N) continue;
            bool full = (c0 + 1 < N);
#pragma unroll
            for (int half = 0; half < 2; half++) {
                int row = r0 + half * 8;
                float v0 = acc[mi][ni][half * 2 + 0];
                float v1 = acc[mi][ni][half * 2 + 1];
                if (bias) { v0 += bias[c0]; if (full) v1 += bias[c0 + 1]; }
                size_t o = (size_t)row * N + c0;
                if (gelu_split) {
                    v0 = 0.5f * v0 * (1.f + erff(v0 * 0.70710678118654752f));
                    v1 = 0.5f * v1 * (1.f + erff(v1 * 0.70710678118654752f));
                    __nv_bfloat16 h0 = __float2bfloat16(v0);
                    __nv_bfloat16 h1 = __float2bfloat16(v1);
                    __nv_bfloat16 l0 = __float2bfloat16(v0 - __bfloat162float(h0));
                    __nv_bfloat16 l1 = __float2bfloat16(v1 - __bfloat162float(h1));
                    if (full && evenN) {
                        *(__nv_bfloat162*)&Chi[o] = __nv_bfloat162(h0, h1);
                        *(__nv_bfloat162*)&Clo[o] = __nv_bfloat162(l0, l1);
                    } else {
                        Chi[o] = h0; Clo[o] = l0;
                        if (full) { Chi[o + 1] = h1; Clo[o + 1] = l1; }
                    }
                } else {
                    if (res) {
                        if (full && evenN) { float2 rr = *(const float2*)&res[o]; v0 += rr.x; v1 += rr.y; }
                        else { v0 += res[o]; if (full) v1 += res[o + 1]; }
                    }
                    if (full && evenN) {
                        *(float2*)&Cf[o] = make_float2(v0, v1);
                    } else {
                        Cf[o] = v0;
                        if (full) Cf[o + 1] = v1;
                    }
                }
            }
        }
    }
}

// ---------------- embedding ----------------
__global__ void embed_kernel(const int* __restrict__ idx,
                             const float* __restrict__ wte,
                             const float* __restrict__ wpe,
                             float* __restrict__ x)
{
    int bt = blockIdx.x;
    int t  = bt % TT;
    int tok = idx[bt];
    const float* te = wte + (size_t)tok * DMODEL;
    const float* pe = wpe + (size_t)t * DMODEL;
    float* xr = x + (size_t)bt * DMODEL;
    for (int d = threadIdx.x; d < DMODEL; d += blockDim.x)
        xr[d] = te[d] + pe[d];
}

// ---------------- layernorm with split bf16 output ----------------
__global__ void ln_split_kernel(const float* __restrict__ x,
                                const float* __restrict__ s,
                                const float* __restrict__ b,
                                __nv_bfloat16* __restrict__ yh,
                                __nv_bfloat16* __restrict__ yl)
{
    __shared__ float red[256];
    int row = blockIdx.x;
    const float* xr = x + (size_t)row * DMODEL;

    float sum = 0.f, sq = 0.f;
    for (int d = threadIdx.x; d < DMODEL; d += 256) {
        float v = xr[d];
        sum += v; sq += v * v;
    }
    red[threadIdx.x] = sum; __syncthreads();
    for (int o = 128; o > 0; o >>= 1) { if (threadIdx.x < o) red[threadIdx.x] += red[threadIdx.x + o]; __syncthreads(); }
    float mean = red[0] / DMODEL; __syncthreads();
    red[threadIdx.x] = sq; __syncthreads();
    for (int o = 128; o > 0; o >>= 1) { if (threadIdx.x < o) red[threadIdx.x] += red[threadIdx.x + o]; __syncthreads(); }
    float var = red[0] / DMODEL - mean * mean;
    float rstd = rsqrtf(var + 1e-5f);
    for (int d = threadIdx.x; d < DMODEL; d += 256) {
        float v = (xr[d] - mean) * rstd * s[d] + b[d];
        split2(v, &yh[(size_t)row * DMODEL + d], &yl[(size_t)row * DMODEL + d]);
    }
}

// ---------------- weight preparation ----------------
__global__ void prep_qkv_kernel(const float* __restrict__ Wq, const float* __restrict__ Wk,
                                const float* __restrict__ Wv,
                                const float* __restrict__ bq, const float* __restrict__ bk,
                                const float* __restrict__ bv, int layer,
                                __nv_bfloat16* __restrict__ wh, __nv_bfloat16* __restrict__ wl,
                                float* __restrict__ bqkv)
{
    int i = blockIdx.x * blockDim.x + threadIdx.x;
    if (i >= QKVN * DMODEL) return;
    int n = i / DMODEL, k = i % DMODEL;
    int sel = n / DMODEL;            // 0=q 1=k 2=v
    int r = n % DMODEL;
    int h = r / HS, e = r % HS;
    const float* W = (sel == 0) ? Wq : (sel == 1) ? Wk : Wv;
    float v = W[((((size_t)layer * NH + h) * DMODEL) + k) * HS + e];
    split2(v, &wh[i], &wl[i]);
    if (k == 0) {
        const float* bp = (sel == 0) ? bq : (sel == 1) ? bk : bv;
        bqkv[n] = bp[(size_t)layer * DMODEL + r];
    }
}

// tiled transpose+split: src [K,N] fp32 -> oh/ol K-major [N,K] bf16
__global__ void prep_T_kernel(const float* __restrict__ src,
                              __nv_bfloat16* __restrict__ oh, __nv_bfloat16* __restrict__ ol,
                              int K, int N)
{
    __shared__ float tile[32][33];
    int kb = blockIdx.x * 32, nb = blockIdx.y * 32;
    int tx = threadIdx.x, ty = threadIdx.y;   // 32 x 8
#pragma unroll
    for (int j = ty; j < 32; j += 8) {
        int k = kb + j, n = nb + tx;
        tile[j][tx] = (k < K && n < N) ? src[(size_t)k * N + n] : 0.f;
    }
    __syncthreads();
#pragma unroll
    for (int j = ty; j < 32; j += 8) {
        int n = nb + j, k = kb + tx;
        if (n < N && k < K)
            split2(tile[tx][j], &oh[(size_t)n * K + k], &ol[(size_t)n * K + k]);
    }
}

// wte split (vectorized x4)
__global__ void prep_split_kernel(const float* __restrict__ src,
                                  __nv_bfloat16* __restrict__ oh, __nv_bfloat16* __restrict__ ol,
                                  int n4)
{
    int i = blockIdx.x * blockDim.x + threadIdx.x;
    if (i >= n4) return;
    float4 v = *(const float4*)&src[i * 4];
    __nv_bfloat16 h[4], l[4];
    split2(v.x, &h[0], &l[0]);
    split2(v.y, &h[1], &l[1]);
    split2(v.z, &h[2], &l[2]);
    split2(v.w, &h[3], &l[3]);
    *(uint2*)&oh[i * 4] = *(uint2*)h;
    *(uint2*)&ol[i * 4] = *(uint2*)l;
}

// ---------------- attention ----------------
__global__ void attn_kernel(const float* __restrict__ qkv,
                            __nv_bfloat16* __restrict__ oh,
                            __nv_bfloat16* __restrict__ ol)
{
    __shared__ float qs[HS];
    __shared__ float sc[TT];
    __shared__ float red[128];

    int tq = blockIdx.x, h = blockIdx.y, b = blockIdx.z;
    int tid = threadIdx.x;
    size_t qrow = (size_t)(b * TT + tq) * QKVN;

    if (tid < HS) qs[tid] = qkv[qrow + h * HS + tid];
    __syncthreads();

    int n = tq + 1;
    for (int tk = tid; tk < n; tk += 128) {
        const float4* kr = (const float4*)(qkv + (size_t)(b * TT + tk) * QKVN + DMODEL + h * HS);
        float s = 0.f;
#pragma unroll
        for (int e4 = 0; e4 < HS / 4; e4++) {
            float4 kv = kr[e4];
            const float4* q4 = (const float4*)&qs[e4 * 4];
            s = fmaf(q4->x, kv.x, s);
            s = fmaf(q4->y, kv.y, s);
            s = fmaf(q4->z, kv.z, s);
            s = fmaf(q4->w, kv.w, s);
        }
        sc[tk] = s;
    }
    __syncthreads();

    float mx = -1e30f;
    for (int tk = tid; tk < n; tk += 128) mx = fmaxf(mx, sc[tk]);
    red[tid] = mx; __syncthreads();
    for (int off = 64; off > 0; off >>= 1) { if (tid < off) red[tid] = fmaxf(red[tid], red[tid + off]); __syncthreads(); }
    mx = red[0]; __syncthreads();

    float sum = 0.f;
    for (int tk = tid; tk < n; tk += 128) { float p = fast_exp(sc[tk] - mx); sc[tk] = p; sum += p; }
    red[tid] = sum; __syncthreads();
    for (int off = 64; off > 0; off >>= 1) { if (tid < off) red[tid] += red[tid + off]; __syncthreads(); }
    float inv = 1.f / (red[0] * 8.0f);   // post-softmax / sqrt(HS)
    __syncthreads();

    int e = tid & 63;
    int half = tid >> 6;
    float accv = 0.f;
    for (int tk = half; tk < n; tk += 2)
        accv = fmaf(sc[tk], qkv[(size_t)(b * TT + tk) * QKVN + 2 * DMODEL + h * HS + e], accv);
    red[tid] = accv; __syncthreads();
    if (half == 0) {
        float o = (red[e] + red[e + 64]) * inv;
        size_t oo = (size_t)(b * TT + tq) * DMODEL + h * HS + e;
        split2(o, &oh[oo], &ol[oo]);
    }
}

// ---------------- loss (single-pass online softmax, fast_exp) ----------------
__global__ void lossrow_kernel(const float* __restrict__ logits,
                               const int* __restrict__ targets,
                               float* __restrict__ rowloss)
{
    __shared__ float rm[256], rs[256];
    int r = blockIdx.x;
    const float* p = logits + (size_t)r * VOCAB;

    float m = -1e30f, s = 0.f;
    for (int i = threadIdx.x; i < VOCAB; i += 256) {
        float v = p[i];
        if (v <= m) {
            s += fast_exp(v - m);
        } else {
            s = fmaf(s, fast_exp(m - v), 1.f);
            m = v;
        }
    }
    rm[threadIdx.x] = m; rs[threadIdx.x] = s; __syncthreads();
    for (int o = 128; o > 0; o >>= 1) {
        if (threadIdx.x < o) {
            float m2 = rm[threadIdx.x + o], s2 = rs[threadIdx.x + o];
            float nm = fmaxf(rm[threadIdx.x], m2);
            rs[threadIdx.x] = rs[threadIdx.x] * fast_exp(rm[threadIdx.x] - nm) + s2 * fast_exp(m2 - nm);
            rm[threadIdx.x] = nm;
        }
        __syncthreads();
    }
    if (threadIdx.x == 0) {
        int t = targets[r];
        rowloss[r] = -(p[t] - rm[0] - logf(rs[0]));
    }
}

__global__ void lossred_kernel(const float* __restrict__ rowloss, float* __restrict__ out)
{
    __shared__ float red[256];
    float s = 0.f;
    for (int i = threadIdx.x; i < BT; i += 256) s += rowloss[i];
    red[threadIdx.x] = s; __syncthreads();
    for (int o = 128; o > 0; o >>= 1) { if (threadIdx.x < o) red[threadIdx.x] += red[threadIdx.x + o]; __syncthreads(); }
    if (threadIdx.x == 0) out[0] = red[0] / (float)BT;
}

// ---------------- host ----------------
template <typename T>
static T* symaddr(const void* sym)
{
    void* p = nullptr;
    cudaGetSymbolAddress(&p, sym);
    return (T*)p;
}

static void launch_gemm(const __nv_bfloat16* Ah, const __nv_bfloat16* Al,
                        const __nv_bfloat16* Bh, const __nv_bfloat16* Bl,
                        const float* bias, const float* res,
                        float* Cf, __nv_bfloat16* Chi, __nv_bfloat16* Clo,
                        int M, int N, int K, int gelu_split)
{
    dim3 grid(M / BM, (N + BN - 1) / BN);
    mm_gemm<<<grid, 256, GSMEM_BYTES>>>(Ah, Al, Bh, Bl, bias, res, Cf, Chi, Clo, M, N, K, gelu_split);
}

extern "C" void kernel_launch(void* const* d_in, const int* in_sizes, int n_in,
                              void* d_out, int out_size)
{
    const int*   idx     = (const int*)d_in[0];
    const int*   targets = (const int*)d_in[1];
    const float* wte     = (const float*)d_in[2];
    const float* wpe     = (const float*)d_in[3];
    const float* ln1_s   = (const float*)d_in[4];
    const float* ln1_b   = (const float*)d_in[5];
    const float* ln2_s   = (const float*)d_in[6];
    const float* ln2_b   = (const float*)d_in[7];
    const float* Wq      = (const float*)d_in[8];
    const float* bq      = (const float*)d_in[9];
    const float* Wk      = (const float*)d_in[10];
    const float* bk      = (const float*)d_in[11];
    const float* Wv      = (const float*)d_in[12];
    const float* bv      = (const float*)d_in[13];
    const float* Wo      = (const float*)d_in[14];
    const float* bo      = (const float*)d_in[15];
    const float* W1      = (const float*)d_in[16];
    const float* b1      = (const float*)d_in[17];
    const float* W2      = (const float*)d_in[18];
    const float* b2      = (const float*)d_in[19];
    const float* lnf_s   = (const float*)d_in[20];
    const float* lnf_b   = (const float*)d_in[21];

    float* out = (float*)d_out;

    (void)cudaFuncSetAttribute(mm_gemm, cudaFuncAttributeMaxDynamicSharedMemorySize, GSMEM_BYTES);

    float* x    = symaddr<float>(g_x);
    float* qkv  = symaddr<float>(g_qkv);
    float* bqkv = symaddr<float>(g_bqkv);
    float* rowloss = symaddr<float>(g_rowloss);
    __nv_bfloat16* hh  = symaddr<__nv_bfloat16>(g_hh);
    __nv_bfloat16* hl  = symaddr<__nv_bfloat16>(g_hl);
    __nv_bfloat16* ffh = symaddr<__nv_bfloat16>(g_ffh);
    __nv_bfloat16* ffl = symaddr<__nv_bfloat16>(g_ffl);
    __nv_bfloat16* ath = symaddr<__nv_bfloat16>(g_ath);
    __nv_bfloat16* atl = symaddr<__nv_bfloat16>(g_atl);
    __nv_bfloat16* wqkvh = symaddr<__nv_bfloat16>(g_wqkvh);
    __nv_bfloat16* wqkvl = symaddr<__nv_bfloat16>(g_wqkvl);
    __nv_bfloat16* woh = symaddr<__nv_bfloat16>(g_woh);
    __nv_bfloat16* wol = symaddr<__nv_bfloat16>(g_wol);
    __nv_bfloat16* w1h = symaddr<__nv_bfloat16>(g_w1h);
    __nv_bfloat16* w1l = symaddr<__nv_bfloat16>(g_w1l);
    __nv_bfloat16* w2h = symaddr<__nv_bfloat16>(g_w2h);
    __nv_bfloat16* w2l = symaddr<__nv_bfloat16>(g_w2l);
    __nv_bfloat16* wteh = symaddr<__nv_bfloat16>(g_wteh);
    __nv_bfloat16* wtel = symaddr<__nv_bfloat16>(g_wtel);

    // Launch order: index 3 is the QKV mm_gemm (ncu window profiles index 3).
    embed_kernel<<<BT, 256>>>(idx, wte, wpe, x);                                   // 0

    for (int l = 0; l < LAYERS; l++) {
        ln_split_kernel<<<BT, 256>>>(x, ln1_s + l * DMODEL, ln1_b + l * DMODEL, hh, hl);   // 1

        {
            const int n = QKVN * DMODEL;
            prep_qkv_kernel<<<(n + 255) / 256, 256>>>(Wq, Wk, Wv, bq, bk, bv, l, wqkvh, wqkvl, bqkv); // 2
        }
        launch_gemm(hh, hl, wqkvh, wqkvl, bqkv, nullptr, qkv, nullptr, nullptr,
                    BT, QKVN, DMODEL, 0);                                          // 3  <- profiled

        dim3 agrid(TT, NH, BB);
        attn_kernel<<<agrid, 128>>>(qkv, ath, atl);

        {
            dim3 tg(DMODEL / 32, DMODEL / 32);
            prep_T_kernel<<<tg, dim3(32, 8)>>>(Wo + (size_t)l * DMODEL * DMODEL, woh, wol, DMODEL, DMODEL);
        }
        launch_gemm(ath, atl, woh, wol, bo + l * DMODEL, x, x, nullptr, nullptr,
                    BT, DMODEL, DMODEL, 0);

        ln_split_kernel<<<BT, 256>>>(x, ln2_s + l * DMODEL, ln2_b + l * DMODEL, hh, hl);
        {
            dim3 tg(DMODEL / 32, FF / 32);
            prep_T_kernel<<<tg, dim3(32, 8)>>>(W1 + (size_t)l * DMODEL * FF, w1h, w1l, DMODEL, FF);
        }
        launch_gemm(hh, hl, w1h, w1l, b1 + l * FF, nullptr, nullptr, ffh, ffl,
                    BT, FF, DMODEL, 1);                     // GELU + split
        {
            dim3 tg(FF / 32, DMODEL / 32);
            prep_T_kernel<<<tg, dim3(32, 8)>>>(W2 + (size_t)l * FF * DMODEL, w2h, w2l, FF, DMODEL);
        }
        launch_gemm(ffh, ffl, w2h, w2l, b2 + l * DMODEL, x, x, nullptr, nullptr,
                    BT, DMODEL, FF, 0);
    }

    ln_split_kernel<<<BT, 256>>>(x, lnf_s, lnf_b, hh, hl);

    {
        const int n4 = (VOCAB * DMODEL) / 4;
        prep_split_kernel<<<(n4 + 255) / 256, 256>>>(wte, wteh, wtel, n4);
    }

    // logits = h @ wte^T  (N odd -> scalar epilogue path)
    launch_gemm(hh, hl, wteh, wtel, nullptr, nullptr, out, nullptr, nullptr,
                BT, VOCAB, DMODEL, 0);

    const long long NL = (long long)BT * VOCAB;
    lossrow_kernel<<<BT, 256>>>(out, targets, rowloss);
    if ((long long)out_size > NL)
        lossred_kernel<<<1, 256>>>(rowloss, out + NL);
}

// round 15
// speedup vs baseline: 3.6120x; 1.0151x over previous
#include <cuda_runtime.h>
#include <cuda_bf16.h>
#include <math.h>
#include <stdint.h>

// ---------------- problem constants ----------------
#define LAYERS 2
#define NH     12
#define DMODEL 768
#define HS     64
#define FF     3072
#define VOCAB  50257
#define BB     4
#define TT     512
#define BT     2048
#define QKVN   2304      // fused q|k|v output width

// ---------------- device scratch ----------------
__device__ float g_x[BT*DMODEL];
__device__ float g_qkv[BT*QKVN];
__device__ float g_rowloss[BT];
__device__ float g_bqkv[QKVN];

__device__ __nv_bfloat16 g_hh[BT*DMODEL],  g_hl[BT*DMODEL];
__device__ __nv_bfloat16 g_ffh[BT*FF],     g_ffl[BT*FF];
__device__ __nv_bfloat16 g_ath[BT*DMODEL], g_atl[BT*DMODEL];
__device__ __nv_bfloat16 g_wqkvh[QKVN*DMODEL], g_wqkvl[QKVN*DMODEL];
__device__ __nv_bfloat16 g_woh[DMODEL*DMODEL], g_wol[DMODEL*DMODEL];
__device__ __nv_bfloat16 g_w1h[FF*DMODEL],     g_w1l[FF*DMODEL];
__device__ __nv_bfloat16 g_w2h[DMODEL*FF],     g_w2l[DMODEL*FF];
__device__ __nv_bfloat16 g_wteh[VOCAB*DMODEL], g_wtel[VOCAB*DMODEL];

// ---------------- helpers ----------------
__device__ __forceinline__ uint32_t smem_u32(const void* p) {
    uint32_t a;
    asm("{ .reg .u64 t; cvta.to.shared.u64 t, %1; cvt.u32.u64 %0, t; }" : "=r"(a) : "l"(p));
    return a;
}
__device__ __forceinline__ void cp_async16(uint32_t saddr, const void* gptr, int src_bytes) {
    asm volatile("cp.async.cg.shared.global [%0], [%1], 16, %2;"
                 :: "r"(saddr), "l"(gptr), "r"(src_bytes) : "memory");
}
__device__ __forceinline__ void cp_commit() { asm volatile("cp.async.commit_group;" ::: "memory"); }
__device__ __forceinline__ void cp_wait1()  { asm volatile("cp.async.wait_group 1;" ::: "memory"); }

__device__ __forceinline__ void ldsm_x4(uint32_t* r, uint32_t addr) {
    asm volatile("ldmatrix.sync.aligned.m8n8.x4.shared.b16 {%0,%1,%2,%3}, [%4];"
                 : "=r"(r[0]), "=r"(r[1]), "=r"(r[2]), "=r"(r[3]) : "r"(addr));
}

__device__ __forceinline__ void mma16816(float* c, const uint32_t* a, uint32_t b0, uint32_t b1) {
    asm("mma.sync.aligned.m16n8k16.row.col.f32.bf16.bf16.f32 "
        "{%0,%1,%2,%3}, {%4,%5,%6,%7}, {%8,%9}, {%0,%1,%2,%3};"
        : "+f"(c[0]), "+f"(c[1]), "+f"(c[2]), "+f"(c[3])
        : "r"(a[0]), "r"(a[1]), "r"(a[2]), "r"(a[3]), "r"(b0), "r"(b1));
}

__device__ __forceinline__ void split2(float v, __nv_bfloat16* hi, __nv_bfloat16* lo) {
    __nv_bfloat16 h = __float2bfloat16(v);
    *hi = h;
    *lo = __float2bfloat16(v - __bfloat162float(h));
}

// fast exp on the FMA pipe (input <= 0 after softmax shift); rel err ~1.5e-4
__device__ __forceinline__ float fast_exp(float x) {
    float t = x * 1.4426950408889634f;          // log2(e)
    t = fmaxf(t, -120.f);
    int   ni = __float2int_rd(t);
    float f  = t - (float)ni;
    float p = fmaf(f, 0.00133335581f, 0.00961812911f);
    p = fmaf(f, p, 0.0555041086f);
    p = fmaf(f, p, 0.240226507f);
    p = fmaf(f, p, 0.693147180f);
    p = fmaf(f, p, 1.0f);
    return __int_as_float(__float_as_int(p) + (ni << 23));
}

// SW128 swizzle (byte offset within a 128B-row tile)
__device__ __forceinline__ uint32_t swz(uint32_t b) { return b ^ ((b >> 3) & 0x70); }

// ---------------- bf16 hi/lo split GEMM: 3-stage pipeline, SW128, 1 bar/chunk --
// SMEM tile layout: [128 rows][128B], row = hi(64B)|lo(64B) of a 32-col K-chunk.
// Fragment addressing uses swz(base+d) = swz(base)^d  (valid: low7(base)<=16,
// d in {0,32,64,96} touches only bits 5-6, stage bases 128B-aligned).
#define BM 128
#define BN 128
#define BKC 32
#define TILEB 16384                           // one operand tile (A or B)
#define STAGEB (2*TILEB)                      // A + B
#define GSTAGES 3
#define GSMEM_BYTES (GSTAGES*STAGEB + 128)    // +128 alignment slack

__global__ void __launch_bounds__(256, 2)
mm_gemm(const __nv_bfloat16* __restrict__ Ah, const __nv_bfloat16* __restrict__ Al,
        const __nv_bfloat16* __restrict__ Bh, const __nv_bfloat16* __restrict__ Bl,
        const float* __restrict__ bias, const float* __restrict__ res,
        float* __restrict__ Cf, __nv_bfloat16* __restrict__ Chi, __nv_bfloat16* __restrict__ Clo,
        int M, int N, int K, int gelu_split)
{
    extern __shared__ char smem[];
    uint32_t sb = (smem_u32(smem) + 127u) & ~127u;   // 128B-aligned stage base

    int tid = threadIdx.x, warp = tid >> 5, lane = tid & 31;
    int wr = warp >> 2, wc = warp & 3;        // warp grid 2x4 -> warp tile 64x32
    int rowBase = blockIdx.x * BM;
    int colBase = blockIdx.y * BN;

    float acc[4][4][4];
#pragma unroll
    for (int mi = 0; mi < 4; mi++)
#pragma unroll
        for (int ni = 0; ni < 4; ni++)
#pragma unroll
            for (int v = 0; v < 4; v++) acc[mi][ni][v] = 0.f;

    // pre-swizzled ldmatrix base offsets (hi, ks=0); variants via ^32 / ^64 / ^96
    uint32_t swzA[4], swzB[2];
#pragma unroll
    for (int mi = 0; mi < 4; mi++)
        swzA[mi] = swz((uint32_t)(wr * 64 + mi * 16 + (lane & 15)) * 128 + (lane >> 4) * 16);
#pragma unroll
    for (int p = 0; p < 2; p++)
        swzB[p] = swz((uint32_t)(wc * 32 + p * 16 + (lane & 15)) * 128 + (lane >> 4) * 16);

    // per-thread load slots: 2 tiles x 128 rows x 8 c16-chunks = 2048; 8 per thread
    const __nv_bfloat16* gsrc[8];
    uint32_t soff[8];
    int okmask = 0;
#pragma unroll
    for (int e = 0; e < 8; e++) {
        int u = e * 256 + tid;                // 0..2047
        int tile = u >> 10;                   // 0:A  1:B
        int rem = u & 1023;
        int row = rem >> 3;
        int c16 = rem & 7;                    // 0-3 hi, 4-7 lo
        bool isLo = (c16 >= 4);
        int cc = c16 & 3;
        const __nv_bfloat16* sp = (tile == 0) ? (isLo ? Al : Ah) : (isLo ? Bl : Bh);
        int base = tile ? colBase : rowBase;
        int gr = base + row;
        bool ok = (tile == 0) || (gr < N);
        gsrc[e] = sp + ((size_t)(ok ? gr : base) * K + cc * 8);
        soff[e] = tile * TILEB + swz((uint32_t)row * 128 + c16 * 16);
        if (ok) okmask |= (1 << e);
    }

    const int nch = K / BKC;

    // prologue: chunks 0,1 -> stages 0,1
#pragma unroll
    for (int s = 0; s < 2; s++) {
        uint32_t dst = sb + s * STAGEB;
#pragma unroll
        for (int e = 0; e < 8; e++)
            cp_async16(dst + soff[e], gsrc[e] + (size_t)s * BKC, ((okmask >> e) & 1) ? 16 : 0);
        cp_commit();
    }

    int stage = 0;
    for (int ck = 0; ck < nch; ck++) {
        cp_wait1();
        __syncthreads();

        uint32_t sA = sb + stage * STAGEB;
        uint32_t sB = sA + TILEB;
        uint32_t aA0 = sA + swzA[0], aA1 = sA + swzA[1];
        uint32_t aA2 = sA + swzA[2], aA3 = sA + swzA[3];
        uint32_t aB0 = sB + swzB[0], aB1 = sB + swzB[1];
        uint32_t aA[4] = {aA0, aA1, aA2, aA3};
        uint32_t aB[2] = {aB0, aB1};

#pragma unroll
        for (int ks = 0; ks < 2; ks++) {
            uint32_t ko = ks * 32;
            uint32_t bh[2][4], bl[2][4];
#pragma unroll
            for (int p = 0; p < 2; p++) {
                ldsm_x4(bh[p], aB[p] ^ ko);
                ldsm_x4(bl[p], aB[p] ^ (ko + 64));
            }
#pragma unroll
            for (int mi = 0; mi < 4; mi++) {
                uint32_t ahf[4], alf[4];
                ldsm_x4(ahf, aA[mi] ^ ko);
                ldsm_x4(alf, aA[mi] ^ (ko + 64));
#pragma unroll
                for (int ni = 0; ni < 4; ni++) {
                    int p = ni >> 1, w = ni & 1;
                    mma16816(acc[mi][ni], ahf, bh[p][w], bh[p][w + 2]);
                }
#pragma unroll
                for (int ni = 0; ni < 4; ni++) {
                    int p = ni >> 1, w = ni & 1;
                    mma16816(acc[mi][ni], ahf, bl[p][w], bl[p][w + 2]);
                }
#pragma unroll
                for (int ni = 0; ni < 4; ni++) {
                    int p = ni >> 1, w = ni & 1;
                    mma16816(acc[mi][ni], alf, bh[p][w], bh[p][w + 2]);
                }
            }
        }

        // prefetch chunk ck+2 into the stage freed at iteration ck-1
        if (ck + 2 < nch) {
            int ps = stage + 2; if (ps >= GSTAGES) ps -= GSTAGES;
            uint32_t dst = sb + ps * STAGEB;
            size_t step = (size_t)(ck + 2) * BKC;
#pragma unroll
            for (int e = 0; e < 8; e++)
                cp_async16(dst + soff[e], gsrc[e] + step, ((okmask >> e) & 1) ? 16 : 0);
        }
        cp_commit();   // always commit (possibly empty group) to keep wait distance

        if (++stage == GSTAGES) stage = 0;
    }

    // ---- epilogue ----
    int g = lane >> 2, t = lane & 3;
    const bool evenN = ((N & 1) == 0);
#pragma unroll
    for (int mi = 0; mi < 4; mi++) {
        int r0 = rowBase + wr * 64 + mi * 16 + g;
#pragma unroll
        for (int ni = 0; ni < 4; ni++) {
            int c0 = colBase + wc * 32 + ni * 8 + t * 2;
            if (c0 >= N) continue;
            bool full = (c0 + 1 < N);
#pragma unroll
            for (int half = 0; half < 2; half++) {
                int row = r0 + half * 8;
                float v0 = acc[mi][ni][half * 2 + 0];
                float v1 = acc[mi][ni][half * 2 + 1];
                if (bias) { v0 += bias[c0]; if (full) v1 += bias[c0 + 1]; }
                size_t o = (size_t)row * N + c0;
                if (gelu_split) {
                    v0 = 0.5f * v0 * (1.f + erff(v0 * 0.70710678118654752f));
                    v1 = 0.5f * v1 * (1.f + erff(v1 * 0.70710678118654752f));
                    __nv_bfloat16 h0 = __float2bfloat16(v0);
                    __nv_bfloat16 h1 = __float2bfloat16(v1);
                    __nv_bfloat16 l0 = __float2bfloat16(v0 - __bfloat162float(h0));
                    __nv_bfloat16 l1 = __float2bfloat16(v1 - __bfloat162float(h1));
                    if (full && evenN) {
                        *(__nv_bfloat162*)&Chi[o] = __nv_bfloat162(h0, h1);
                        *(__nv_bfloat162*)&Clo[o] = __nv_bfloat162(l0, l1);
                    } else {
                        Chi[o] = h0; Clo[o] = l0;
                        if (full) { Chi[o + 1] = h1; Clo[o + 1] = l1; }
                    }
                } else {
                    if (res) {
                        if (full && evenN) { float2 rr = *(const float2*)&res[o]; v0 += rr.x; v1 += rr.y; }
                        else { v0 += res[o]; if (full) v1 += res[o + 1]; }
                    }
                    if (full && evenN) {
                        *(float2*)&Cf[o] = make_float2(v0, v1);
                    } else {
                        Cf[o] = v0;
                        if (full) Cf[o + 1] = v1;
                    }
                }
            }
        }
    }
}

// ---------------- embedding ----------------
__global__ void embed_kernel(const int* __restrict__ idx,
                             const float* __restrict__ wte,
                             const float* __restrict__ wpe,
                             float* __restrict__ x)
{
    int bt = blockIdx.x;
    int t  = bt % TT;
    int tok = idx[bt];
    const float* te = wte + (size_t)tok * DMODEL;
    const float* pe = wpe + (size_t)t * DMODEL;
    float* xr = x + (size_t)bt * DMODEL;
    for (int d = threadIdx.x; d < DMODEL; d += blockDim.x)
        xr[d] = te[d] + pe[d];
}

// ---------------- layernorm with split bf16 output ----------------
__global__ void ln_split_kernel(const float* __restrict__ x,
                                const float* __restrict__ s,
                                const float* __restrict__ b,
                                __nv_bfloat16* __restrict__ yh,
                                __nv_bfloat16* __restrict__ yl)
{
    __shared__ float red[256];
    int row = blockIdx.x;
    const float* xr = x + (size_t)row * DMODEL;

    float sum = 0.f, sq = 0.f;
    for (int d = threadIdx.x; d < DMODEL; d += 256) {
        float v = xr[d];
        sum += v; sq += v * v;
    }
    red[threadIdx.x] = sum; __syncthreads();
    for (int o = 128; o > 0; o >>= 1) { if (threadIdx.x < o) red[threadIdx.x] += red[threadIdx.x + o]; __syncthreads(); }
    float mean = red[0] / DMODEL; __syncthreads();
    red[threadIdx.x] = sq; __syncthreads();
    for (int o = 128; o > 0; o >>= 1) { if (threadIdx.x < o) red[threadIdx.x] += red[threadIdx.x + o]; __syncthreads(); }
    float var = red[0] / DMODEL - mean * mean;
    float rstd = rsqrtf(var + 1e-5f);
    for (int d = threadIdx.x; d < DMODEL; d += 256) {
        float v = (xr[d] - mean) * rstd * s[d] + b[d];
        split2(v, &yh[(size_t)row * DMODEL + d], &yl[(size_t)row * DMODEL + d]);
    }
}

// ---------------- weight preparation ----------------
__global__ void prep_qkv_kernel(const float* __restrict__ Wq, const float* __restrict__ Wk,
                                const float* __restrict__ Wv,
                                const float* __restrict__ bq, const float* __restrict__ bk,
                                const float* __restrict__ bv, int layer,
                                __nv_bfloat16* __restrict__ wh, __nv_bfloat16* __restrict__ wl,
                                float* __restrict__ bqkv)
{
    int i = blockIdx.x * blockDim.x + threadIdx.x;
    if (i >= QKVN * DMODEL) return;
    int n = i / DMODEL, k = i % DMODEL;
    int sel = n / DMODEL;            // 0=q 1=k 2=v
    int r = n % DMODEL;
    int h = r / HS, e = r % HS;
    const float* W = (sel == 0) ? Wq : (sel == 1) ? Wk : Wv;
    float v = W[((((size_t)layer * NH + h) * DMODEL) + k) * HS + e];
    split2(v, &wh[i], &wl[i]);
    if (k == 0) {
        const float* bp = (sel == 0) ? bq : (sel == 1) ? bk : bv;
        bqkv[n] = bp[(size_t)layer * DMODEL + r];
    }
}

// tiled transpose+split: src [K,N] fp32 -> oh/ol K-major [N,K] bf16
__global__ void prep_T_kernel(const float* __restrict__ src,
                              __nv_bfloat16* __restrict__ oh, __nv_bfloat16* __restrict__ ol,
                              int K, int N)
{
    __shared__ float tile[32][33];
    int kb = blockIdx.x * 32, nb = blockIdx.y * 32;
    int tx = threadIdx.x, ty = threadIdx.y;   // 32 x 8
#pragma unroll
    for (int j = ty; j < 32; j += 8) {
        int k = kb + j, n = nb + tx;
        tile[j][tx] = (k < K && n < N) ? src[(size_t)k * N + n] : 0.f;
    }
    __syncthreads();
#pragma unroll
    for (int j = ty; j < 32; j += 8) {
        int n = nb + j, k = kb + tx;
        if (n < N && k < K)
            split2(tile[tx][j], &oh[(size_t)n * K + k], &ol[(size_t)n * K + k]);
    }
}

// wte split (vectorized x4)
__global__ void prep_split_kernel(const float* __restrict__ src,
                                  __nv_bfloat16* __restrict__ oh, __nv_bfloat16* __restrict__ ol,
                                  int n4)
{
    int i = blockIdx.x * blockDim.x + threadIdx.x;
    if (i >= n4) return;
    float4 v = *(const float4*)&src[i * 4];
    __nv_bfloat16 h[4], l[4];
    split2(v.x, &h[0], &l[0]);
    split2(v.y, &h[1], &l[1]);
    split2(v.z, &h[2], &l[2]);
    split2(v.w, &h[3], &l[3]);
    *(uint2*)&oh[i * 4] = *(uint2*)h;
    *(uint2*)&ol[i * 4] = *(uint2*)l;
}

// ---------------- attention ----------------
__global__ void attn_kernel(const float* __restrict__ qkv,
                            __nv_bfloat16* __restrict__ oh,
                            __nv_bfloat16* __restrict__ ol)
{
    __shared__ float qs[HS];
    __shared__ float sc[TT];
    __shared__ float red[128];

    int tq = blockIdx.x, h = blockIdx.y, b = blockIdx.z;
    int tid = threadIdx.x;
    size_t qrow = (size_t)(b * TT + tq) * QKVN;

    if (tid < HS) qs[tid] = qkv[qrow + h * HS + tid];
    __syncthreads();

    int n = tq + 1;
    for (int tk = tid; tk < n; tk += 128) {
        const float4* kr = (const float4*)(qkv + (size_t)(b * TT + tk) * QKVN + DMODEL + h * HS);
        float s = 0.f;
#pragma unroll
        for (int e4 = 0; e4 < HS / 4; e4++) {
            float4 kv = kr[e4];
            const float4* q4 = (const float4*)&qs[e4 * 4];
            s = fmaf(q4->x, kv.x, s);
            s = fmaf(q4->y, kv.y, s);
            s = fmaf(q4->z, kv.z, s);
            s = fmaf(q4->w, kv.w, s);
        }
        sc[tk] = s;
    }
    __syncthreads();

    float mx = -1e30f;
    for (int tk = tid; tk < n; tk += 128) mx = fmaxf(mx, sc[tk]);
    red[tid] = mx; __syncthreads();
    for (int off = 64; off > 0; off >>= 1) { if (tid < off) red[tid] = fmaxf(red[tid], red[tid + off]); __syncthreads(); }
    mx = red[0]; __syncthreads();

    float sum = 0.f;
    for (int tk = tid; tk < n; tk += 128) { float p = fast_exp(sc[tk] - mx); sc[tk] = p; sum += p; }
    red[tid] = sum; __syncthreads();
    for (int off = 64; off > 0; off >>= 1) { if (tid < off) red[tid] += red[tid + off]; __syncthreads(); }
    float inv = 1.f / (red[0] * 8.0f);   // post-softmax / sqrt(HS)
    __syncthreads();

    int e = tid & 63;
    int half = tid >> 6;
    float accv = 0.f;
    for (int tk = half; tk < n; tk += 2)
        accv = fmaf(sc[tk], qkv[(size_t)(b * TT + tk) * QKVN + 2 * DMODEL + h * HS + e], accv);
    red[tid] = accv; __syncthreads();
    if (half == 0) {
        float o = (red[e] + red[e + 64]) * inv;
        size_t oo = (size_t)(b * TT + tq) * DMODEL + h * HS + e;
        split2(o, &oh[oo], &ol[oo]);
    }
}

// ---------------- loss (single-pass online softmax, fast_exp) ----------------
__global__ void lossrow_kernel(const float* __restrict__ logits,
                               const int* __restrict__ targets,
                               float* __restrict__ rowloss)
{
    __shared__ float rm[256], rs[256];
    int r = blockIdx.x;
    const float* p = logits + (size_t)r * VOCAB;

    float m = -1e30f, s = 0.f;
    for (int i = threadIdx.x; i < VOCAB; i += 256) {
        float v = p[i];
        if (v <= m) {
            s += fast_exp(v - m);
        } else {
            s = fmaf(s, fast_exp(m - v), 1.f);
            m = v;
        }
    }
    rm[threadIdx.x] = m; rs[threadIdx.x] = s; __syncthreads();
    for (int o = 128; o > 0; o >>= 1) {
        if (threadIdx.x < o) {
            float m2 = rm[threadIdx.x + o], s2 = rs[threadIdx.x + o];
            float nm = fmaxf(rm[threadIdx.x], m2);
            rs[threadIdx.x] = rs[threadIdx.x] * fast_exp(rm[threadIdx.x] - nm) + s2 * fast_exp(m2 - nm);
            rm[threadIdx.x] = nm;
        }
        __syncthreads();
    }
    if (threadIdx.x == 0) {
        int t = targets[r];
        rowloss[r] = -(p[t] - rm[0] - logf(rs[0]));
    }
}

__global__ void lossred_kernel(const float* __restrict__ rowloss, float* __restrict__ out)
{
    __shared__ float red[256];
    float s = 0.f;
    for (int i = threadIdx.x; i < BT; i += 256) s += rowloss[i];
    red[threadIdx.x] = s; __syncthreads();
    for (int o = 128; o > 0; o >>= 1) { if (threadIdx.x < o) red[threadIdx.x] += red[threadIdx.x + o]; __syncthreads(); }
    if (threadIdx.x == 0) out[0] = red[0] / (float)BT;
}

// ---------------- host ----------------
template <typename T>
static T* symaddr(const void* sym)
{
    void* p = nullptr;
    cudaGetSymbolAddress(&p, sym);
    return (T*)p;
}

static void launch_gemm(const __nv_bfloat16* Ah, const __nv_bfloat16* Al,
                        const __nv_bfloat16* Bh, const __nv_bfloat16* Bl,
                        const float* bias, const float* res,
                        float* Cf, __nv_bfloat16* Chi, __nv_bfloat16* Clo,
                        int M, int N, int K, int gelu_split)
{
    dim3 grid(M / BM, (N + BN - 1) / BN);
    mm_gemm<<<grid, 256, GSMEM_BYTES>>>(Ah, Al, Bh, Bl, bias, res, Cf, Chi, Clo, M, N, K, gelu_split);
}

extern "C" void kernel_launch(void* const* d_in, const int* in_sizes, int n_in,
                              void* d_out, int out_size)
{
    const int*   idx     = (const int*)d_in[0];
    const int*   targets = (const int*)d_in[1];
    const float* wte     = (const float*)d_in[2];
    const float* wpe     = (const float*)d_in[3];
    const float* ln1_s   = (const float*)d_in[4];
    const float* ln1_b   = (const float*)d_in[5];
    const float* ln2_s   = (const float*)d_in[6];
    const float* ln2_b   = (const float*)d_in[7];
    const float* Wq      = (const float*)d_in[8];
    const float* bq      = (const float*)d_in[9];
    const float* Wk      = (const float*)d_in[10];
    const float* bk      = (const float*)d_in[11];
    const float* Wv      = (const float*)d_in[12];
    const float* bv      = (const float*)d_in[13];
    const float* Wo      = (const float*)d_in[14];
    const float* bo      = (const float*)d_in[15];
    const float* W1      = (const float*)d_in[16];
    const float* b1      = (const float*)d_in[17];
    const float* W2      = (const float*)d_in[18];
    const float* b2      = (const float*)d_in[19];
    const float* lnf_s   = (const float*)d_in[20];
    const float* lnf_b   = (const float*)d_in[21];

    float* out = (float*)d_out;

    (void)cudaFuncSetAttribute(mm_gemm, cudaFuncAttributeMaxDynamicSharedMemorySize, GSMEM_BYTES);

    float* x    = symaddr<float>(g_x);
    float* qkv  = symaddr<float>(g_qkv);
    float* bqkv = symaddr<float>(g_bqkv);
    float* rowloss = symaddr<float>(g_rowloss);
    __nv_bfloat16* hh  = symaddr<__nv_bfloat16>(g_hh);
    __nv_bfloat16* hl  = symaddr<__nv_bfloat16>(g_hl);
    __nv_bfloat16* ffh = symaddr<__nv_bfloat16>(g_ffh);
    __nv_bfloat16* ffl = symaddr<__nv_bfloat16>(g_ffl);
    __nv_bfloat16* ath = symaddr<__nv_bfloat16>(g_ath);
    __nv_bfloat16* atl = symaddr<__nv_bfloat16>(g_atl);
    __nv_bfloat16* wqkvh = symaddr<__nv_bfloat16>(g_wqkvh);
    __nv_bfloat16* wqkvl = symaddr<__nv_bfloat16>(g_wqkvl);
    __nv_bfloat16* woh = symaddr<__nv_bfloat16>(g_woh);
    __nv_bfloat16* wol = symaddr<__nv_bfloat16>(g_wol);
    __nv_bfloat16* w1h = symaddr<__nv_bfloat16>(g_w1h);
    __nv_bfloat16* w1l = symaddr<__nv_bfloat16>(g_w1l);
    __nv_bfloat16* w2h = symaddr<__nv_bfloat16>(g_w2h);
    __nv_bfloat16* w2l = symaddr<__nv_bfloat16>(g_w2l);
    __nv_bfloat16* wteh = symaddr<__nv_bfloat16>(g_wteh);
    __nv_bfloat16* wtel = symaddr<__nv_bfloat16>(g_wtel);

    // Launch order: index 3 is the QKV mm_gemm (ncu window profiles index 3).
    embed_kernel<<<BT, 256>>>(idx, wte, wpe, x);                                   // 0

    for (int l = 0; l < LAYERS; l++) {
        ln_split_kernel<<<BT, 256>>>(x, ln1_s + l * DMODEL, ln1_b + l * DMODEL, hh, hl);   // 1

        {
            const int n = QKVN * DMODEL;
            prep_qkv_kernel<<<(n + 255) / 256, 256>>>(Wq, Wk, Wv, bq, bk, bv, l, wqkvh, wqkvl, bqkv); // 2
        }
        launch_gemm(hh, hl, wqkvh, wqkvl, bqkv, nullptr, qkv, nullptr, nullptr,
                    BT, QKVN, DMODEL, 0);                                          // 3  <- profiled

        dim3 agrid(TT, NH, BB);
        attn_kernel<<<agrid, 128>>>(qkv, ath, atl);

        {
            dim3 tg(DMODEL / 32, DMODEL / 32);
            prep_T_kernel<<<tg, dim3(32, 8)>>>(Wo + (size_t)l * DMODEL * DMODEL, woh, wol, DMODEL, DMODEL);
        }
        launch_gemm(ath, atl, woh, wol, bo + l * DMODEL, x, x, nullptr, nullptr,
                    BT, DMODEL, DMODEL, 0);

        ln_split_kernel<<<BT, 256>>>(x, ln2_s + l * DMODEL, ln2_b + l * DMODEL, hh, hl);
        {
            dim3 tg(DMODEL / 32, FF / 32);
            prep_T_kernel<<<tg, dim3(32, 8)>>>(W1 + (size_t)l * DMODEL * FF, w1h, w1l, DMODEL, FF);
        }
        launch_gemm(hh, hl, w1h, w1l, b1 + l * FF, nullptr, nullptr, ffh, ffl,
                    BT, FF, DMODEL, 1);                     // GELU + split
        {
            dim3 tg(FF / 32, DMODEL / 32);
            prep_T_kernel<<<tg, dim3(32, 8)>>>(W2 + (size_t)l * FF * DMODEL, w2h, w2l, FF, DMODEL);
        }
        launch_gemm(ffh, ffl, w2h, w2l, b2 + l * DMODEL, x, x, nullptr, nullptr,
                    BT, DMODEL, FF, 0);
    }

    ln_split_kernel<<<BT, 256>>>(x, lnf_s, lnf_b, hh, hl);

    {
        const int n4 = (VOCAB * DMODEL) / 4;
        prep_split_kernel<<<(n4 + 255) / 256, 256>>>(wte, wteh, wtel, n4);
    }

    // logits = h @ wte^T  (N odd -> scalar epilogue path)
    launch_gemm(hh, hl, wteh, wtel, nullptr, nullptr, out, nullptr, nullptr,
                BT, VOCAB, DMODEL, 0);

    const long long NL = (long long)BT * VOCAB;
    lossrow_kernel<<<BT, 256>>>(out, targets, rowloss);
    if ((long long)out_size > NL)
        lossred_kernel<<<1, 256>>>(rowloss, out + NL);
}

// round 16
// speedup vs baseline: 3.6373x; 1.0070x over previous
#include <cuda_runtime.h>
#include <cuda_bf16.h>
#include <math.h>
#include <stdint.h>

// ---------------- problem constants ----------------
#define LAYERS 2
#define NH     12
#define DMODEL 768
#define HS     64
#define FF     3072
#define VOCAB  50257
#define BB     4
#define TT     512
#define BT     2048
#define QKVN   2304      // fused q|k|v output width

// ---------------- device scratch ----------------
__device__ float g_x[BT*DMODEL];
__device__ float g_qkv[BT*QKVN];
__device__ float g_rowloss[BT];
__device__ float g_bqkv[QKVN];

__device__ __nv_bfloat16 g_hh[BT*DMODEL],  g_hl[BT*DMODEL];
__device__ __nv_bfloat16 g_ffh[BT*FF],     g_ffl[BT*FF];
__device__ __nv_bfloat16 g_ath[BT*DMODEL], g_atl[BT*DMODEL];
__device__ __nv_bfloat16 g_wqkvh[QKVN*DMODEL], g_wqkvl[QKVN*DMODEL];
__device__ __nv_bfloat16 g_woh[DMODEL*DMODEL], g_wol[DMODEL*DMODEL];
__device__ __nv_bfloat16 g_w1h[FF*DMODEL],     g_w1l[FF*DMODEL];
__device__ __nv_bfloat16 g_w2h[DMODEL*FF],     g_w2l[DMODEL*FF];
__device__ __nv_bfloat16 g_wteh[VOCAB*DMODEL], g_wtel[VOCAB*DMODEL];

// ---------------- helpers ----------------
__device__ __forceinline__ uint32_t smem_u32(const void* p) {
    uint32_t a;
    asm("{ .reg .u64 t; cvta.to.shared.u64 t, %1; cvt.u32.u64 %0, t; }" : "=r"(a) : "l"(p));
    return a;
}
__device__ __forceinline__ void cp_async16(uint32_t saddr, const void* gptr, int src_bytes) {
    asm volatile("cp.async.cg.shared.global [%0], [%1], 16, %2;"
                 :: "r"(saddr), "l"(gptr), "r"(src_bytes) : "memory");
}
__device__ __forceinline__ void cp_commit() { asm volatile("cp.async.commit_group;" ::: "memory"); }
__device__ __forceinline__ void cp_wait1()  { asm volatile("cp.async.wait_group 1;" ::: "memory"); }

__device__ __forceinline__ void ldsm_x4(uint32_t* r, uint32_t addr) {
    asm volatile("ldmatrix.sync.aligned.m8n8.x4.shared.b16 {%0,%1,%2,%3}, [%4];"
                 : "=r"(r[0]), "=r"(r[1]), "=r"(r[2]), "=r"(r[3]) : "r"(addr));
}

__device__ __forceinline__ void mma16816(float* c, const uint32_t* a, uint32_t b0, uint32_t b1) {
    asm("mma.sync.aligned.m16n8k16.row.col.f32.bf16.bf16.f32 "
        "{%0,%1,%2,%3}, {%4,%5,%6,%7}, {%8,%9}, {%0,%1,%2,%3};"
        : "+f"(c[0]), "+f"(c[1]), "+f"(c[2]), "+f"(c[3])
        : "r"(a[0]), "r"(a[1]), "r"(a[2]), "r"(a[3]), "r"(b0), "r"(b1));
}

__device__ __forceinline__ void split2(float v, __nv_bfloat16* hi, __nv_bfloat16* lo) {
    __nv_bfloat16 h = __float2bfloat16(v);
    *hi = h;
    *lo = __float2bfloat16(v - __bfloat162float(h));
}

// fast exp on the FMA pipe; rel err ~1.5e-4
__device__ __forceinline__ float fast_exp(float x) {
    float t = x * 1.4426950408889634f;          // log2(e)
    t = fmaxf(t, -120.f);
    int   ni = __float2int_rd(t);
    float f  = t - (float)ni;
    float p = fmaf(f, 0.00133335581f, 0.00961812911f);
    p = fmaf(f, p, 0.0555041086f);
    p = fmaf(f, p, 0.240226507f);
    p = fmaf(f, p, 0.693147180f);
    p = fmaf(f, p, 1.0f);
    return __int_as_float(__float_as_int(p) + (ni << 23));
}

// SW128 swizzle (byte offset within a 128B-row tile)
__device__ __forceinline__ uint32_t swz(uint32_t b) { return b ^ ((b >> 3) & 0x70); }

// ---------------- bf16 hi/lo split GEMM: 3-stage pipeline, SW128 --------------
// Templated on MI (M-fragments/warp): MI=4 -> BM=128, MI=2 -> BM=64 (for N=768
// GEMMs whose BM=128 grid underfills the chip).
// SMEM tile row = hi(64B)|lo(64B) of a 32-col K-chunk.
// swz(base+d) = swz(base)^d  (low7(base)<=16, d in {0,32,64,96}, 128B-aligned base)
#define BN 128
#define BKC 32
#define GSTAGES 3

template<int MI>
__global__ void __launch_bounds__(256, 2)
mm_gemm_t(const __nv_bfloat16* __restrict__ Ah, const __nv_bfloat16* __restrict__ Al,
          const __nv_bfloat16* __restrict__ Bh, const __nv_bfloat16* __restrict__ Bl,
          const float* __restrict__ bias, const float* __restrict__ res,
          float* __restrict__ Cf, __nv_bfloat16* __restrict__ Chi, __nv_bfloat16* __restrict__ Clo,
          int M, int N, int K, int gelu_split)
{
    constexpr int BMt    = 32 * MI;
    constexpr int ATILEB = BMt * 128;         // A tile bytes
    constexpr int BTILEB = 16384;             // B tile bytes (128 rows x 128B)
    constexpr int STAGEB = ATILEB + BTILEB;
    constexpr int ASLOTS = BMt * 8;           // 16B slots in A tile
    constexpr int NSLOT  = (ASLOTS + 1024) / 256;  // per-thread cp.async slots

    extern __shared__ char smem[];
    uint32_t sb = (smem_u32(smem) + 127u) & ~127u;

    int tid = threadIdx.x, warp = tid >> 5, lane = tid & 31;
    int wr = warp >> 2, wc = warp & 3;        // warp grid 2x4
    int rowBase = blockIdx.x * BMt;
    int colBase = blockIdx.y * BN;

    float acc[MI][4][4];
#pragma unroll
    for (int mi = 0; mi < MI; mi++)
#pragma unroll
        for (int ni = 0; ni < 4; ni++)
#pragma unroll
            for (int v = 0; v < 4; v++) acc[mi][ni][v] = 0.f;

    // pre-swizzled ldmatrix base offsets (hi, ks=0); variants via ^32 / ^64 / ^96
    uint32_t swzA[MI], swzB[2];
#pragma unroll
    for (int mi = 0; mi < MI; mi++)
        swzA[mi] = swz((uint32_t)(wr * (16 * MI) + mi * 16 + (lane & 15)) * 128 + (lane >> 4) * 16);
#pragma unroll
    for (int p = 0; p < 2; p++)
        swzB[p] = swz((uint32_t)(wc * 32 + p * 16 + (lane & 15)) * 128 + (lane >> 4) * 16);

    // per-thread load slots
    const __nv_bfloat16* gsrc[NSLOT];
    uint32_t soff[NSLOT];
    int okmask = 0;
#pragma unroll
    for (int e = 0; e < NSLOT; e++) {
        int u = e * 256 + tid;
        bool isB = (u >= ASLOTS);
        int rem = isB ? (u - ASLOTS) : u;
        int row = rem >> 3;
        int c16 = rem & 7;                    // 0-3 hi, 4-7 lo
        bool isLo = (c16 >= 4);
        int cc = c16 & 3;
        const __nv_bfloat16* sp = (!isB) ? (isLo ? Al : Ah) : (isLo ? Bl : Bh);
        int base = isB ? colBase : rowBase;
        int gr = base + row;
        bool ok = (!isB) || (gr < N);
        gsrc[e] = sp + ((size_t)(ok ? gr : base) * K + cc * 8);
        soff[e] = (isB ? ATILEB : 0) + swz((uint32_t)row * 128 + c16 * 16);
        if (ok) okmask |= (1 << e);
    }

    const int nch = K / BKC;

    // prologue: chunks 0,1 -> stages 0,1
#pragma unroll
    for (int s = 0; s < 2; s++) {
        uint32_t dst = sb + s * STAGEB;
#pragma unroll
        for (int e = 0; e < NSLOT; e++)
            cp_async16(dst + soff[e], gsrc[e] + (size_t)s * BKC, ((okmask >> e) & 1) ? 16 : 0);
        cp_commit();
    }

    int stage = 0;
    for (int ck = 0; ck < nch; ck++) {
        cp_wait1();
        __syncthreads();

        uint32_t sA = sb + stage * STAGEB;
        uint32_t sB = sA + ATILEB;
        uint32_t aA[MI], aB[2];
#pragma unroll
        for (int mi = 0; mi < MI; mi++) aA[mi] = sA + swzA[mi];
#pragma unroll
        for (int p = 0; p < 2; p++) aB[p] = sB + swzB[p];

#pragma unroll
        for (int ks = 0; ks < 2; ks++) {
            uint32_t ko = ks * 32;
            uint32_t bh[2][4], bl[2][4];
#pragma unroll
            for (int p = 0; p < 2; p++) {
                ldsm_x4(bh[p], aB[p] ^ ko);
                ldsm_x4(bl[p], aB[p] ^ (ko + 64));
            }
#pragma unroll
            for (int mi = 0; mi < MI; mi++) {
                uint32_t ahf[4], alf[4];
                ldsm_x4(ahf, aA[mi] ^ ko);
                ldsm_x4(alf, aA[mi] ^ (ko + 64));
#pragma unroll
                for (int ni = 0; ni < 4; ni++) {
                    int p = ni >> 1, w = ni & 1;
                    mma16816(acc[mi][ni], ahf, bh[p][w], bh[p][w + 2]);
                }
#pragma unroll
                for (int ni = 0; ni < 4; ni++) {
                    int p = ni >> 1, w = ni & 1;
                    mma16816(acc[mi][ni], ahf, bl[p][w], bl[p][w + 2]);
                }
#pragma unroll
                for (int ni = 0; ni < 4; ni++) {
                    int p = ni >> 1, w = ni & 1;
                    mma16816(acc[mi][ni], alf, bh[p][w], bh[p][w + 2]);
                }
            }
        }

        // prefetch chunk ck+2 into the stage freed at iteration ck-1
        if (ck + 2 < nch) {
            int ps = stage + 2; if (ps >= GSTAGES) ps -= GSTAGES;
            uint32_t dst = sb + ps * STAGEB;
            size_t step = (size_t)(ck + 2) * BKC;
#pragma unroll
            for (int e = 0; e < NSLOT; e++)
                cp_async16(dst + soff[e], gsrc[e] + step, ((okmask >> e) & 1) ? 16 : 0);
        }
        cp_commit();   // always commit (possibly empty group) to keep wait distance

        if (++stage == GSTAGES) stage = 0;
    }

    // ---- epilogue ----
    int g = lane >> 2, t = lane & 3;
    const bool evenN = ((N & 1) == 0);
#pragma unroll
    for (int mi = 0; mi < MI; mi++) {
        int r0 = rowBase + wr * (16 * MI) + mi * 16 + g;
#pragma unroll
        for (int ni = 0; ni < 4; ni++) {
            int c0 = colBase + wc * 32 + ni * 8 + t * 2;
            if (c0 >= N) continue;
            bool full = (c0 + 1 < N);
#pragma unroll
            for (int half = 0; half < 2; half++) {
                int row = r0 + half * 8;
                float v0 = acc[mi][ni][half * 2 + 0];
                float v1 = acc[mi][ni][half * 2 + 1];
                if (bias) { v0 += bias[c0]; if (full) v1 += bias[c0 + 1]; }
                size_t o = (size_t)row * N + c0;
                if (gelu_split) {
                    v0 = 0.5f * v0 * (1.f + erff(v0 * 0.70710678118654752f));
                    v1 = 0.5f * v1 * (1.f + erff(v1 * 0.70710678118654752f));
                    __nv_bfloat16 h0 = __float2bfloat16(v0);
                    __nv_bfloat16 h1 = __float2bfloat16(v1);
                    __nv_bfloat16 l0 = __float2bfloat16(v0 - __bfloat162float(h0));
                    __nv_bfloat16 l1 = __float2bfloat16(v1 - __bfloat162float(h1));
                    if (full && evenN) {
                        *(__nv_bfloat162*)&Chi[o] = __nv_bfloat162(h0, h1);
                        *(__nv_bfloat162*)&Clo[o] = __nv_bfloat162(l0, l1);
                    } else {
                        Chi[o] = h0; Clo[o] = l0;
                        if (full) { Chi[o + 1] = h1; Clo[o + 1] = l1; }
                    }
                } else {
                    if (res) {
                        if (full && evenN) { float2 rr = *(const float2*)&res[o]; v0 += rr.x; v1 += rr.y; }
                        else { v0 += res[o]; if (full) v1 += res[o + 1]; }
                    }
                    if (full && evenN) {
                        *(float2*)&Cf[o] = make_float2(v0, v1);
                    } else {
                        Cf[o] = v0;
                        if (full) Cf[o + 1] = v1;
                    }
                }
            }
        }
    }
}

#define GSMEM4 (GSTAGES*(128*128 + 16384) + 128)   // 98432
#define GSMEM2 (GSTAGES*(64*128 + 16384) + 128)    // 73856

// ---------------- embedding ----------------
__global__ void embed_kernel(const int* __restrict__ idx,
                             const float* __restrict__ wte,
                             const float* __restrict__ wpe,
                             float* __restrict__ x)
{
    int bt = blockIdx.x;
    int t  = bt % TT;
    int tok = idx[bt];
    const float* te = wte + (size_t)tok * DMODEL;
    const float* pe = wpe + (size_t)t * DMODEL;
    float* xr = x + (size_t)bt * DMODEL;
    for (int d = threadIdx.x; d < DMODEL; d += blockDim.x)
        xr[d] = te[d] + pe[d];
}

// ---------------- layernorm with split bf16 output ----------------
__global__ void ln_split_kernel(const float* __restrict__ x,
                                const float* __restrict__ s,
                                const float* __restrict__ b,
                                __nv_bfloat16* __restrict__ yh,
                                __nv_bfloat16* __restrict__ yl)
{
    __shared__ float red[256];
    int row = blockIdx.x;
    const float* xr = x + (size_t)row * DMODEL;

    float sum = 0.f, sq = 0.f;
    for (int d = threadIdx.x; d < DMODEL; d += 256) {
        float v = xr[d];
        sum += v; sq += v * v;
    }
    red[threadIdx.x] = sum; __syncthreads();
    for (int o = 128; o > 0; o >>= 1) { if (threadIdx.x < o) red[threadIdx.x] += red[threadIdx.x + o]; __syncthreads(); }
    float mean = red[0] / DMODEL; __syncthreads();
    red[threadIdx.x] = sq; __syncthreads();
    for (int o = 128; o > 0; o >>= 1) { if (threadIdx.x < o) red[threadIdx.x] += red[threadIdx.x + o]; __syncthreads(); }
    float var = red[0] / DMODEL - mean * mean;
    float rstd = rsqrtf(var + 1e-5f);
    for (int d = threadIdx.x; d < DMODEL; d += 256) {
        float v = (xr[d] - mean) * rstd * s[d] + b[d];
        split2(v, &yh[(size_t)row * DMODEL + d], &yl[(size_t)row * DMODEL + d]);
    }
}

// ---------------- weight preparation ----------------
__global__ void prep_qkv_kernel(const float* __restrict__ Wq, const float* __restrict__ Wk,
                                const float* __restrict__ Wv,
                                const float* __restrict__ bq, const float* __restrict__ bk,
                                const float* __restrict__ bv, int layer,
                                __nv_bfloat16* __restrict__ wh, __nv_bfloat16* __restrict__ wl,
                                float* __restrict__ bqkv)
{
    int i = blockIdx.x * blockDim.x + threadIdx.x;
    if (i >= QKVN * DMODEL) return;
    int n = i / DMODEL, k = i % DMODEL;
    int sel = n / DMODEL;            // 0=q 1=k 2=v
    int r = n % DMODEL;
    int h = r / HS, e = r % HS;
    const float* W = (sel == 0) ? Wq : (sel == 1) ? Wk : Wv;
    float v = W[((((size_t)layer * NH + h) * DMODEL) + k) * HS + e];
    split2(v, &wh[i], &wl[i]);
    if (k == 0) {
        const float* bp = (sel == 0) ? bq : (sel == 1) ? bk : bv;
        bqkv[n] = bp[(size_t)layer * DMODEL + r];
    }
}

// tiled transpose+split: src [K,N] fp32 -> oh/ol K-major [N,K] bf16
__global__ void prep_T_kernel(const float* __restrict__ src,
                              __nv_bfloat16* __restrict__ oh, __nv_bfloat16* __restrict__ ol,
                              int K, int N)
{
    __shared__ float tile[32][33];
    int kb = blockIdx.x * 32, nb = blockIdx.y * 32;
    int tx = threadIdx.x, ty = threadIdx.y;   // 32 x 8
#pragma unroll
    for (int j = ty; j < 32; j += 8) {
        int k = kb + j, n = nb + tx;
        tile[j][tx] = (k < K && n < N) ? src[(size_t)k * N + n] : 0.f;
    }
    __syncthreads();
#pragma unroll
    for (int j = ty; j < 32; j += 8) {
        int n = nb + j, k = kb + tx;
        if (n < N && k < K)
            split2(tile[tx][j], &oh[(size_t)n * K + k], &ol[(size_t)n * K + k]);
    }
}

// wte split (vectorized x4)
__global__ void prep_split_kernel(const float* __restrict__ src,
                                  __nv_bfloat16* __restrict__ oh, __nv_bfloat16* __restrict__ ol,
                                  int n4)
{
    int i = blockIdx.x * blockDim.x + threadIdx.x;
    if (i >= n4) return;
    float4 v = *(const float4*)&src[i * 4];
    __nv_bfloat16 h[4], l[4];
    split2(v.x, &h[0], &l[0]);
    split2(v.y, &h[1], &l[1]);
    split2(v.z, &h[2], &l[2]);
    split2(v.w, &h[3], &l[3]);
    *(uint2*)&oh[i * 4] = *(uint2*)h;
    *(uint2*)&ol[i * 4] = *(uint2*)l;
}

// ---------------- attention ----------------
__global__ void attn_kernel(const float* __restrict__ qkv,
                            __nv_bfloat16* __restrict__ oh,
                            __nv_bfloat16* __restrict__ ol)
{
    __shared__ float qs[HS];
    __shared__ float sc[TT];
    __shared__ float red[128];

    int tq = blockIdx.x, h = blockIdx.y, b = blockIdx.z;
    int tid = threadIdx.x;
    size_t qrow = (size_t)(b * TT + tq) * QKVN;

    if (tid < HS) qs[tid] = qkv[qrow + h * HS + tid];
    __syncthreads();

    int n = tq + 1;
    for (int tk = tid; tk < n; tk += 128) {
        const float4* kr = (const float4*)(qkv + (size_t)(b * TT + tk) * QKVN + DMODEL + h * HS);
        float s = 0.f;
#pragma unroll
        for (int e4 = 0; e4 < HS / 4; e4++) {
            float4 kv = kr[e4];
            const float4* q4 = (const float4*)&qs[e4 * 4];
            s = fmaf(q4->x, kv.x, s);
            s = fmaf(q4->y, kv.y, s);
            s = fmaf(q4->z, kv.z, s);
            s = fmaf(q4->w, kv.w, s);
        }
        sc[tk] = s;
    }
    __syncthreads();

    float mx = -1e30f;
    for (int tk = tid; tk < n; tk += 128) mx = fmaxf(mx, sc[tk]);
    red[tid] = mx; __syncthreads();
    for (int off = 64; off > 0; off >>= 1) { if (tid < off) red[tid] = fmaxf(red[tid], red[tid + off]); __syncthreads(); }
    mx = red[0]; __syncthreads();

    float sum = 0.f;
    for (int tk = tid; tk < n; tk += 128) { float p = fast_exp(sc[tk] - mx); sc[tk] = p; sum += p; }
    red[tid] = sum; __syncthreads();
    for (int off = 64; off > 0; off >>= 1) { if (tid < off) red[tid] += red[tid + off]; __syncthreads(); }
    float inv = 1.f / (red[0] * 8.0f);   // post-softmax / sqrt(HS)
    __syncthreads();

    int e = tid & 63;
    int half = tid >> 6;
    float accv = 0.f;
    for (int tk = half; tk < n; tk += 2)
        accv = fmaf(sc[tk], qkv[(size_t)(b * TT + tk) * QKVN + 2 * DMODEL + h * HS + e], accv);
    red[tid] = accv; __syncthreads();
    if (half == 0) {
        float o = (red[e] + red[e + 64]) * inv;
        size_t oo = (size_t)(b * TT + tq) * DMODEL + h * HS + e;
        split2(o, &oh[oo], &ol[oo]);
    }
}

// ---------------- loss (single-pass online softmax, fast_exp) ----------------
__global__ void lossrow_kernel(const float* __restrict__ logits,
                               const int* __restrict__ targets,
                               float* __restrict__ rowloss)
{
    __shared__ float rm[256], rs[256];
    int r = blockIdx.x;
    const float* p = logits + (size_t)r * VOCAB;

    float m = -1e30f, s = 0.f;
    for (int i = threadIdx.x; i < VOCAB; i += 256) {
        float v = p[i];
        if (v <= m) {
            s += fast_exp(v - m);
        } else {
            s = fmaf(s, fast_exp(m - v), 1.f);
            m = v;
        }
    }
    rm[threadIdx.x] = m; rs[threadIdx.x] = s; __syncthreads();
    for (int o = 128; o > 0; o >>= 1) {
        if (threadIdx.x < o) {
            float m2 = rm[threadIdx.x + o], s2 = rs[threadIdx.x + o];
            float nm = fmaxf(rm[threadIdx.x], m2);
            rs[threadIdx.x] = rs[threadIdx.x] * fast_exp(rm[threadIdx.x] - nm) + s2 * fast_exp(m2 - nm);
            rm[threadIdx.x] = nm;
        }
        __syncthreads();
    }
    if (threadIdx.x == 0) {
        int t = targets[r];
        rowloss[r] = -(p[t] - rm[0] - logf(rs[0]));
    }
}

__global__ void lossred_kernel(const float* __restrict__ rowloss, float* __restrict__ out)
{
    __shared__ float red[256];
    float s = 0.f;
    for (int i = threadIdx.x; i < BT; i += 256) s += rowloss[i];
    red[threadIdx.x] = s; __syncthreads();
    for (int o = 128; o > 0; o >>= 1) { if (threadIdx.x < o) red[threadIdx.x] += red[threadIdx.x + o]; __syncthreads(); }
    if (threadIdx.x == 0) out[0] = red[0] / (float)BT;
}

// ---------------- host ----------------
template <typename T>
static T* symaddr(const void* sym)
{
    void* p = nullptr;
    cudaGetSymbolAddress(&p, sym);
    return (T*)p;
}

// bm64: use BM=64 variant (for N=768 GEMMs that underfill the chip at BM=128)
static void launch_gemm(const __nv_bfloat16* Ah, const __nv_bfloat16* Al,
                        const __nv_bfloat16* Bh, const __nv_bfloat16* Bl,
                        const float* bias, const float* res,
                        float* Cf, __nv_bfloat16* Chi, __nv_bfloat16* Clo,
                        int M, int N, int K, int gelu_split, int bm64)
{
    if (bm64) {
        dim3 grid(M / 64, (N + BN - 1) / BN);
        mm_gemm_t<2><<<grid, 256, GSMEM2>>>(Ah, Al, Bh, Bl, bias, res, Cf, Chi, Clo, M, N, K, gelu_split);
    } else {
        dim3 grid(M / 128, (N + BN - 1) / BN);
        mm_gemm_t<4><<<grid, 256, GSMEM4>>>(Ah, Al, Bh, Bl, bias, res, Cf, Chi, Clo, M, N, K, gelu_split);
    }
}

extern "C" void kernel_launch(void* const* d_in, const int* in_sizes, int n_in,
                              void* d_out, int out_size)
{
    const int*   idx     = (const int*)d_in[0];
    const int*   targets = (const int*)d_in[1];
    const float* wte     = (const float*)d_in[2];
    const float* wpe     = (const float*)d_in[3];
    const float* ln1_s   = (const float*)d_in[4];
    const float* ln1_b   = (const float*)d_in[5];
    const float* ln2_s   = (const float*)d_in[6];
    const float* ln2_b   = (const float*)d_in[7];
    const float* Wq      = (const float*)d_in[8];
    const float* bq      = (const float*)d_in[9];
    const float* Wk      = (const float*)d_in[10];
    const float* bk      = (const float*)d_in[11];
    const float* Wv      = (const float*)d_in[12];
    const float* bv      = (const float*)d_in[13];
    const float* Wo      = (const float*)d_in[14];
    const float* bo      = (const float*)d_in[15];
    const float* W1      = (const float*)d_in[16];
    const float* b1      = (const float*)d_in[17];
    const float* W2      = (const float*)d_in[18];
    const float* b2      = (const float*)d_in[19];
    const float* lnf_s   = (const float*)d_in[20];
    const float* lnf_b   = (const float*)d_in[21];

    float* out = (float*)d_out;

    (void)cudaFuncSetAttribute(mm_gemm_t<4>, cudaFuncAttributeMaxDynamicSharedMemorySize, GSMEM4);
    (void)cudaFuncSetAttribute(mm_gemm_t<2>, cudaFuncAttributeMaxDynamicSharedMemorySize, GSMEM2);

    float* x    = symaddr<float>(g_x);
    float* qkv  = symaddr<float>(g_qkv);
    float* bqkv = symaddr<float>(g_bqkv);
    float* rowloss = symaddr<float>(g_rowloss);
    __nv_bfloat16* hh  = symaddr<__nv_bfloat16>(g_hh);
    __nv_bfloat16* hl  = symaddr<__nv_bfloat16>(g_hl);
    __nv_bfloat16* ffh = symaddr<__nv_bfloat16>(g_ffh);
    __nv_bfloat16* ffl = symaddr<__nv_bfloat16>(g_ffl);
    __nv_bfloat16* ath = symaddr<__nv_bfloat16>(g_ath);
    __nv_bfloat16* atl = symaddr<__nv_bfloat16>(g_atl);
    __nv_bfloat16* wqkvh = symaddr<__nv_bfloat16>(g_wqkvh);
    __nv_bfloat16* wqkvl = symaddr<__nv_bfloat16>(g_wqkvl);
    __nv_bfloat16* woh = symaddr<__nv_bfloat16>(g_woh);
    __nv_bfloat16* wol = symaddr<__nv_bfloat16>(g_wol);
    __nv_bfloat16* w1h = symaddr<__nv_bfloat16>(g_w1h);
    __nv_bfloat16* w1l = symaddr<__nv_bfloat16>(g_w1l);
    __nv_bfloat16* w2h = symaddr<__nv_bfloat16>(g_w2h);
    __nv_bfloat16* w2l = symaddr<__nv_bfloat16>(g_w2l);
    __nv_bfloat16* wteh = symaddr<__nv_bfloat16>(g_wteh);
    __nv_bfloat16* wtel = symaddr<__nv_bfloat16>(g_wtel);

    // Launch order: index 3 is the QKV mm_gemm (ncu window profiles index 3).
    embed_kernel<<<BT, 256>>>(idx, wte, wpe, x);                                   // 0

    for (int l = 0; l < LAYERS; l++) {
        ln_split_kernel<<<BT, 256>>>(x, ln1_s + l * DMODEL, ln1_b + l * DMODEL, hh, hl);   // 1

        {
            const int n = QKVN * DMODEL;
            prep_qkv_kernel<<<(n + 255) / 256, 256>>>(Wq, Wk, Wv, bq, bk, bv, l, wqkvh, wqkvl, bqkv); // 2
        }
        launch_gemm(hh, hl, wqkvh, wqkvl, bqkv, nullptr, qkv, nullptr, nullptr,
                    BT, QKVN, DMODEL, 0, 0);                                       // 3  <- profiled

        dim3 agrid(TT, NH, BB);
        attn_kernel<<<agrid, 128>>>(qkv, ath, atl);

        {
            dim3 tg(DMODEL / 32, DMODEL / 32);
            prep_T_kernel<<<tg, dim3(32, 8)>>>(Wo + (size_t)l * DMODEL * DMODEL, woh, wol, DMODEL, DMODEL);
        }
        launch_gemm(ath, atl, woh, wol, bo + l * DMODEL, x, x, nullptr, nullptr,
                    BT, DMODEL, DMODEL, 0, 1);                 // BM=64

        ln_split_kernel<<<BT, 256>>>(x, ln2_s + l * DMODEL, ln2_b + l * DMODEL, hh, hl);
        {
            dim3 tg(DMODEL / 32, FF / 32);
            prep_T_kernel<<<tg, dim3(32, 8)>>>(W1 + (size_t)l * DMODEL * FF, w1h, w1l, DMODEL, FF);
        }
        launch_gemm(hh, hl, w1h, w1l, b1 + l * FF, nullptr, nullptr, ffh, ffl,
                    BT, FF, DMODEL, 1, 0);                     // GELU + split
        {
            dim3 tg(FF / 32, DMODEL / 32);
            prep_T_kernel<<<tg, dim3(32, 8)>>>(W2 + (size_t)l * FF * DMODEL, w2h, w2l, FF, DMODEL);
        }
        launch_gemm(ffh, ffl, w2h, w2l, b2 + l * DMODEL, x, x, nullptr, nullptr,
                    BT, DMODEL, FF, 0, 1);                     // BM=64
    }

    ln_split_kernel<<<BT, 256>>>(x, lnf_s, lnf_b, hh, hl);

    {
        const int n4 = (VOCAB * DMODEL) / 4;
        prep_split_kernel<<<(n4 + 255) / 256, 256>>>(wte, wteh, wtel, n4);
    }

    // logits = h @ wte^T  (N odd -> scalar epilogue path)
    launch_gemm(hh, hl, wteh, wtel, nullptr, nullptr, out, nullptr, nullptr,
                BT, VOCAB, DMODEL, 0, 0);

    const long long NL = (long long)BT * VOCAB;
    lossrow_kernel<<<BT, 256>>>(out, targets, rowloss);
    if ((long long)out_size > NL)
        lossred_kernel<<<1, 256>>>(rowloss, out + NL);
}

// round 17
// speedup vs baseline: 4.3665x; 1.2005x over previous
#include <cuda_runtime.h>
#include <cuda_fp16.h>
#include <math.h>
#include <stdint.h>

// ---------------- problem constants ----------------
#define LAYERS 2
#define NH     12
#define DMODEL 768
#define HS     64
#define FF     3072
#define VOCAB  50257
#define BB     4
#define TT     512
#define BT     2048
#define QKVN   2304      // fused q|k|v output width

// ---------------- device scratch ----------------
__device__ float g_x[BT*DMODEL];
__device__ float g_qkv[BT*QKVN];
__device__ float g_rowloss[BT];
__device__ float g_bqkv[QKVN];

// activations: hi+lo fp16 (A-side of GEMMs; lo carries bits 12..23)
__device__ __half g_hh[BT*DMODEL],  g_hl[BT*DMODEL];
__device__ __half g_ffh[BT*FF],     g_ffl[BT*FF];
__device__ __half g_ath[BT*DMODEL], g_atl[BT*DMODEL];
// weights: hi only fp16 (B-side; dropped B-lo term ~2^-12 relative)
__device__ __half g_wqkvh[QKVN*DMODEL];
__device__ __half g_woh[DMODEL*DMODEL];
__device__ __half g_w1h[FF*DMODEL];
__device__ __half g_w2h[DMODEL*FF];
__device__ __half g_wteh[VOCAB*DMODEL];

// ---------------- helpers ----------------
__device__ __forceinline__ uint32_t smem_u32(const void* p) {
    uint32_t a;
    asm("{ .reg .u64 t; cvta.to.shared.u64 t, %1; cvt.u32.u64 %0, t; }" : "=r"(a) : "l"(p));
    return a;
}
__device__ __forceinline__ void cp_async16(uint32_t saddr, const void* gptr, int src_bytes) {
    asm volatile("cp.async.cg.shared.global [%0], [%1], 16, %2;"
                 :: "r"(saddr), "l"(gptr), "r"(src_bytes) : "memory");
}
__device__ __forceinline__ void cp_commit() { asm volatile("cp.async.commit_group;" ::: "memory"); }
__device__ __forceinline__ void cp_wait1()  { asm volatile("cp.async.wait_group 1;" ::: "memory"); }

__device__ __forceinline__ void ldsm_x4(uint32_t* r, uint32_t addr) {
    asm volatile("ldmatrix.sync.aligned.m8n8.x4.shared.b16 {%0,%1,%2,%3}, [%4];"
                 : "=r"(r[0]), "=r"(r[1]), "=r"(r[2]), "=r"(r[3]) : "r"(addr));
}

// fp16 MMA, fp32 accumulate
__device__ __forceinline__ void mma16816(float* c, const uint32_t* a, uint32_t b0, uint32_t b1) {
    asm("mma.sync.aligned.m16n8k16.row.col.f32.f16.f16.f32 "
        "{%0,%1,%2,%3}, {%4,%5,%6,%7}, {%8,%9}, {%0,%1,%2,%3};"
        : "+f"(c[0]), "+f"(c[1]), "+f"(c[2]), "+f"(c[3])
        : "r"(a[0]), "r"(a[1]), "r"(a[2]), "r"(a[3]), "r"(b0), "r"(b1));
}

// split fp32 -> fp16 hi + lo
__device__ __forceinline__ void split2(float v, __half* hi, __half* lo) {
    __half h = __float2half(v);
    *hi = h;
    *lo = __float2half(v - __half2float(h));
}

// fast exp on the FMA pipe; rel err ~1.5e-4
__device__ __forceinline__ float fast_exp(float x) {
    float t = x * 1.4426950408889634f;          // log2(e)
    t = fmaxf(t, -120.f);
    int   ni = __float2int_rd(t);
    float f  = t - (float)ni;
    float p = fmaf(f, 0.00133335581f, 0.00961812911f);
    p = fmaf(f, p, 0.0555041086f);
    p = fmaf(f, p, 0.240226507f);
    p = fmaf(f, p, 0.693147180f);
    p = fmaf(f, p, 1.0f);
    return __int_as_float(__float_as_int(p) + (ni << 23));
}

// SW128 swizzle (byte offset within a 128B-row tile)
__device__ __forceinline__ uint32_t swz(uint32_t b) { return b ^ ((b >> 3) & 0x70); }

// -------- fp16 split GEMM: C = (Ah+Al) @ Bh^T, 3-stage pipeline, SW128 --------
// MI = M-fragments/warp: 4 -> BM=128, 2 -> BM=64.
// SMEM tile row = hi(64B)|lo(64B) of a 32-col K-chunk (B-lo slots zero, unused).
#define BN 128
#define BKC 32
#define GSTAGES 3

template<int MI>
__global__ void __launch_bounds__(256, 2)
mm_gemm_t(const __half* __restrict__ Ah, const __half* __restrict__ Al,
          const __half* __restrict__ Bh,
          const float* __restrict__ bias, const float* __restrict__ res,
          float* __restrict__ Cf, __half* __restrict__ Chi, __half* __restrict__ Clo,
          int M, int N, int K, int gelu_split)
{
    constexpr int BMt    = 32 * MI;
    constexpr int ATILEB = BMt * 128;
    constexpr int BTILEB = 16384;
    constexpr int STAGEB = ATILEB + BTILEB;
    constexpr int ASLOTS = BMt * 8;
    constexpr int NSLOT  = (ASLOTS + 1024) / 256;

    extern __shared__ char smem[];
    uint32_t sb = (smem_u32(smem) + 127u) & ~127u;

    int tid = threadIdx.x, warp = tid >> 5, lane = tid & 31;
    int wr = warp >> 2, wc = warp & 3;        // warp grid 2x4
    int rowBase = blockIdx.x * BMt;
    int colBase = blockIdx.y * BN;

    float acc[MI][4][4];
#pragma unroll
    for (int mi = 0; mi < MI; mi++)
#pragma unroll
        for (int ni = 0; ni < 4; ni++)
#pragma unroll
            for (int v = 0; v < 4; v++) acc[mi][ni][v] = 0.f;

    uint32_t swzA[MI], swzB[2];
#pragma unroll
    for (int mi = 0; mi < MI; mi++)
        swzA[mi] = swz((uint32_t)(wr * (16 * MI) + mi * 16 + (lane & 15)) * 128 + (lane >> 4) * 16);
#pragma unroll
    for (int p = 0; p < 2; p++)
        swzB[p] = swz((uint32_t)(wc * 32 + p * 16 + (lane & 15)) * 128 + (lane >> 4) * 16);

    // per-thread load slots; B-lo slots are zero-filled (unused)
    const __half* gsrc[NSLOT];
    uint32_t soff[NSLOT];
    int okmask = 0;
#pragma unroll
    for (int e = 0; e < NSLOT; e++) {
        int u = e * 256 + tid;
        bool isB = (u >= ASLOTS);
        int rem = isB ? (u - ASLOTS) : u;
        int row = rem >> 3;
        int c16 = rem & 7;                    // 0-3 hi, 4-7 lo
        bool isLo = (c16 >= 4);
        int cc = c16 & 3;
        const __half* sp = (!isB) ? (isLo ? Al : Ah) : Bh;
        int base = isB ? colBase : rowBase;
        int gr = base + row;
        bool ok = (!isB) || (!isLo && gr < N);
        gsrc[e] = sp + ((size_t)((isB && gr >= N) ? base : gr) * K + cc * 8);
        soff[e] = (isB ? ATILEB : 0) + swz((uint32_t)row * 128 + c16 * 16);
        if (ok) okmask |= (1 << e);
    }

    const int nch = K / BKC;

    // prologue: chunks 0,1 -> stages 0,1
#pragma unroll
    for (int s = 0; s < 2; s++) {
        uint32_t dst = sb + s * STAGEB;
#pragma unroll
        for (int e = 0; e < NSLOT; e++)
            cp_async16(dst + soff[e], gsrc[e] + (size_t)s * BKC, ((okmask >> e) & 1) ? 16 : 0);
        cp_commit();
    }

    int stage = 0;
    for (int ck = 0; ck < nch; ck++) {
        cp_wait1();
        __syncthreads();

        uint32_t sA = sb + stage * STAGEB;
        uint32_t sB = sA + ATILEB;
        uint32_t aA[MI], aB[2];
#pragma unroll
        for (int mi = 0; mi < MI; mi++) aA[mi] = sA + swzA[mi];
#pragma unroll
        for (int p = 0; p < 2; p++) aB[p] = sB + swzB[p];

#pragma unroll
        for (int ks = 0; ks < 2; ks++) {
            uint32_t ko = ks * 32;
            uint32_t bh[2][4];
#pragma unroll
            for (int p = 0; p < 2; p++)
                ldsm_x4(bh[p], aB[p] ^ ko);
#pragma unroll
            for (int mi = 0; mi < MI; mi++) {
                uint32_t ahf[4], alf[4];
                ldsm_x4(ahf, aA[mi] ^ ko);
                ldsm_x4(alf, aA[mi] ^ (ko + 64));
#pragma unroll
                for (int ni = 0; ni < 4; ni++) {
                    int p = ni >> 1, w = ni & 1;
                    mma16816(acc[mi][ni], ahf, bh[p][w], bh[p][w + 2]);
                }
#pragma unroll
                for (int ni = 0; ni < 4; ni++) {
                    int p = ni >> 1, w = ni & 1;
                    mma16816(acc[mi][ni], alf, bh[p][w], bh[p][w + 2]);
                }
            }
        }

        if (ck + 2 < nch) {
            int ps = stage + 2; if (ps >= GSTAGES) ps -= GSTAGES;
            uint32_t dst = sb + ps * STAGEB;
            size_t step = (size_t)(ck + 2) * BKC;
#pragma unroll
            for (int e = 0; e < NSLOT; e++)
                cp_async16(dst + soff[e], gsrc[e] + step, ((okmask >> e) & 1) ? 16 : 0);
        }
        cp_commit();

        if (++stage == GSTAGES) stage = 0;
    }

    // ---- epilogue ----
    int g = lane >> 2, t = lane & 3;
    const bool evenN = ((N & 1) == 0);
#pragma unroll
    for (int mi = 0; mi < MI; mi++) {
        int r0 = rowBase + wr * (16 * MI) + mi * 16 + g;
#pragma unroll
        for (int ni = 0; ni < 4; ni++) {
            int c0 = colBase + wc * 32 + ni * 8 + t * 2;
            if (c0 >= N) continue;
            bool full = (c0 + 1 < N);
#pragma unroll
            for (int half = 0; half < 2; half++) {
                int row = r0 + half * 8;
                float v0 = acc[mi][ni][half * 2 + 0];
                float v1 = acc[mi][ni][half * 2 + 1];
                if (bias) { v0 += bias[c0]; if (full) v1 += bias[c0 + 1]; }
                size_t o = (size_t)row * N + c0;
                if (gelu_split) {
                    v0 = 0.5f * v0 * (1.f + erff(v0 * 0.70710678118654752f));
                    v1 = 0.5f * v1 * (1.f + erff(v1 * 0.70710678118654752f));
                    __half h0, h1, l0, l1;
                    split2(v0, &h0, &l0);
                    split2(v1, &h1, &l1);
                    if (full && evenN) {
                        *(__half2*)&Chi[o] = __halves2half2(h0, h1);
                        *(__half2*)&Clo[o] = __halves2half2(l0, l1);
                    } else {
                        Chi[o] = h0; Clo[o] = l0;
                        if (full) { Chi[o + 1] = h1; Clo[o + 1] = l1; }
                    }
                } else {
                    if (res) {
                        if (full && evenN) { float2 rr = *(const float2*)&res[o]; v0 += rr.x; v1 += rr.y; }
                        else { v0 += res[o]; if (full) v1 += res[o + 1]; }
                    }
                    if (full && evenN) {
                        *(float2*)&Cf[o] = make_float2(v0, v1);
                    } else {
                        Cf[o] = v0;
                        if (full) Cf[o + 1] = v1;
                    }
                }
            }
        }
    }
}

#define GSMEM4 (GSTAGES*(128*128 + 16384) + 128)   // 98432
#define GSMEM2 (GSTAGES*(64*128 + 16384) + 128)    // 73856

// ---------------- embedding ----------------
__global__ void embed_kernel(const int* __restrict__ idx,
                             const float* __restrict__ wte,
                             const float* __restrict__ wpe,
                             float* __restrict__ x)
{
    int bt = blockIdx.x;
    int t  = bt % TT;
    int tok = idx[bt];
    const float* te = wte + (size_t)tok * DMODEL;
    const float* pe = wpe + (size_t)t * DMODEL;
    float* xr = x + (size_t)bt * DMODEL;
    for (int d = threadIdx.x; d < DMODEL; d += blockDim.x)
        xr[d] = te[d] + pe[d];
}

// ---------------- layernorm with split fp16 output ----------------
__global__ void ln_split_kernel(const float* __restrict__ x,
                                const float* __restrict__ s,
                                const float* __restrict__ b,
                                __half* __restrict__ yh,
                                __half* __restrict__ yl)
{
    __shared__ float red[256];
    int row = blockIdx.x;
    const float* xr = x + (size_t)row * DMODEL;

    float sum = 0.f, sq = 0.f;
    for (int d = threadIdx.x; d < DMODEL; d += 256) {
        float v = xr[d];
        sum += v; sq += v * v;
    }
    red[threadIdx.x] = sum; __syncthreads();
    for (int o = 128; o > 0; o >>= 1) { if (threadIdx.x < o) red[threadIdx.x] += red[threadIdx.x + o]; __syncthreads(); }
    float mean = red[0] / DMODEL; __syncthreads();
    red[threadIdx.x] = sq; __syncthreads();
    for (int o = 128; o > 0; o >>= 1) { if (threadIdx.x < o) red[threadIdx.x] += red[threadIdx.x + o]; __syncthreads(); }
    float var = red[0] / DMODEL - mean * mean;
    float rstd = rsqrtf(var + 1e-5f);
    for (int d = threadIdx.x; d < DMODEL; d += 256) {
        float v = (xr[d] - mean) * rstd * s[d] + b[d];
        split2(v, &yh[(size_t)row * DMODEL + d], &yl[(size_t)row * DMODEL + d]);
    }
}

// ---------------- weight preparation (hi only) ----------------
__global__ void prep_qkv_kernel(const float* __restrict__ Wq, const float* __restrict__ Wk,
                                const float* __restrict__ Wv,
                                const float* __restrict__ bq, const float* __restrict__ bk,
                                const float* __restrict__ bv, int layer,
                                __half* __restrict__ wh, float* __restrict__ bqkv)
{
    int i = blockIdx.x * blockDim.x + threadIdx.x;
    if (i >= QKVN * DMODEL) return;
    int n = i / DMODEL, k = i % DMODEL;
    int sel = n / DMODEL;            // 0=q 1=k 2=v
    int r = n % DMODEL;
    int h = r / HS, e = r % HS;
    const float* W = (sel == 0) ? Wq : (sel == 1) ? Wk : Wv;
    wh[i] = __float2half(W[((((size_t)layer * NH + h) * DMODEL) + k) * HS + e]);
    if (k == 0) {
        const float* bp = (sel == 0) ? bq : (sel == 1) ? bk : bv;
        bqkv[n] = bp[(size_t)layer * DMODEL + r];
    }
}

// tiled transpose: src [K,N] fp32 -> hi fp16 K-major [N,K]
__global__ void prep_T_kernel(const float* __restrict__ src,
                              __half* __restrict__ oh, int K, int N)
{
    __shared__ float tile[32][33];
    int kb = blockIdx.x * 32, nb = blockIdx.y * 32;
    int tx = threadIdx.x, ty = threadIdx.y;   // 32 x 8
#pragma unroll
    for (int j = ty; j < 32; j += 8) {
        int k = kb + j, n = nb + tx;
        tile[j][tx] = (k < K && n < N) ? src[(size_t)k * N + n] : 0.f;
    }
    __syncthreads();
#pragma unroll
    for (int j = ty; j < 32; j += 8) {
        int n = nb + j, k = kb + tx;
        if (n < N && k < K)
            oh[(size_t)n * K + k] = __float2half(tile[tx][j]);
    }
}

// wte hi conversion (vectorized x4)
__global__ void prep_split_kernel(const float* __restrict__ src,
                                  __half* __restrict__ oh, int n4)
{
    int i = blockIdx.x * blockDim.x + threadIdx.x;
    if (i >= n4) return;
    float4 v = *(const float4*)&src[i * 4];
    __half h[4];
    h[0] = __float2half(v.x);
    h[1] = __float2half(v.y);
    h[2] = __float2half(v.z);
    h[3] = __float2half(v.w);
    *(uint2*)&oh[i * 4] = *(uint2*)h;
}

// ---------------- attention ----------------
__global__ void attn_kernel(const float* __restrict__ qkv,
                            __half* __restrict__ oh,
                            __half* __restrict__ ol)
{
    __shared__ float qs[HS];
    __shared__ float sc[TT];
    __shared__ float red[128];

    int tq = blockIdx.x, h = blockIdx.y, b = blockIdx.z;
    int tid = threadIdx.x;
    size_t qrow = (size_t)(b * TT + tq) * QKVN;

    if (tid < HS) qs[tid] = qkv[qrow + h * HS + tid];
    __syncthreads();

    int n = tq + 1;
    for (int tk = tid; tk < n; tk += 128) {
        const float4* kr = (const float4*)(qkv + (size_t)(b * TT + tk) * QKVN + DMODEL + h * HS);
        float s = 0.f;
#pragma unroll
        for (int e4 = 0; e4 < HS / 4; e4++) {
            float4 kv = kr[e4];
            const float4* q4 = (const float4*)&qs[e4 * 4];
            s = fmaf(q4->x, kv.x, s);
            s = fmaf(q4->y, kv.y, s);
            s = fmaf(q4->z, kv.z, s);
            s = fmaf(q4->w, kv.w, s);
        }
        sc[tk] = s;
    }
    __syncthreads();

    float mx = -1e30f;
    for (int tk = tid; tk < n; tk += 128) mx = fmaxf(mx, sc[tk]);
    red[tid] = mx; __syncthreads();
    for (int off = 64; off > 0; off >>= 1) { if (tid < off) red[tid] = fmaxf(red[tid], red[tid + off]); __syncthreads(); }
    mx = red[0]; __syncthreads();

    float sum = 0.f;
    for (int tk = tid; tk < n; tk += 128) { float p = fast_exp(sc[tk] - mx); sc[tk] = p; sum += p; }
    red[tid] = sum; __syncthreads();
    for (int off = 64; off > 0; off >>= 1) { if (tid < off) red[tid] += red[tid + off]; __syncthreads(); }
    float inv = 1.f / (red[0] * 8.0f);   // post-softmax / sqrt(HS)
    __syncthreads();

    int e = tid & 63;
    int half = tid >> 6;
    float accv = 0.f;
    for (int tk = half; tk < n; tk += 2)
        accv = fmaf(sc[tk], qkv[(size_t)(b * TT + tk) * QKVN + 2 * DMODEL + h * HS + e], accv);
    red[tid] = accv; __syncthreads();
    if (half == 0) {
        float o = (red[e] + red[e + 64]) * inv;
        size_t oo = (size_t)(b * TT + tq) * DMODEL + h * HS + e;
        split2(o, &oh[oo], &ol[oo]);
    }
}

// ---------------- loss (single-pass online softmax, fast_exp) ----------------
__global__ void lossrow_kernel(const float* __restrict__ logits,
                               const int* __restrict__ targets,
                               float* __restrict__ rowloss)
{
    __shared__ float rm[256], rs[256];
    int r = blockIdx.x;
    const float* p = logits + (size_t)r * VOCAB;

    float m = -1e30f, s = 0.f;
    for (int i = threadIdx.x; i < VOCAB; i += 256) {
        float v = p[i];
        if (v <= m) {
            s += fast_exp(v - m);
        } else {
            s = fmaf(s, fast_exp(m - v), 1.f);
            m = v;
        }
    }
    rm[threadIdx.x] = m; rs[threadIdx.x] = s; __syncthreads();
    for (int o = 128; o > 0; o >>= 1) {
        if (threadIdx.x < o) {
            float m2 = rm[threadIdx.x + o], s2 = rs[threadIdx.x + o];
            float nm = fmaxf(rm[threadIdx.x], m2);
            rs[threadIdx.x] = rs[threadIdx.x] * fast_exp(rm[threadIdx.x] - nm) + s2 * fast_exp(m2 - nm);
            rm[threadIdx.x] = nm;
        }
        __syncthreads();
    }
    if (threadIdx.x == 0) {
        int t = targets[r];
        rowloss[r] = -(p[t] - rm[0] - logf(rs[0]));
    }
}

__global__ void lossred_kernel(const float* __restrict__ rowloss, float* __restrict__ out)
{
    __shared__ float red[256];
    float s = 0.f;
    for (int i = threadIdx.x; i < BT; i += 256) s += rowloss[i];
    red[threadIdx.x] = s; __syncthreads();
    for (int o = 128; o > 0; o >>= 1) { if (threadIdx.x < o) red[threadIdx.x] += red[threadIdx.x + o]; __syncthreads(); }
    if (threadIdx.x == 0) out[0] = red[0] / (float)BT;
}

// ---------------- host ----------------
template <typename T>
static T* symaddr(const void* sym)
{
    void* p = nullptr;
    cudaGetSymbolAddress(&p, sym);
    return (T*)p;
}

static void launch_gemm(const __half* Ah, const __half* Al, const __half* Bh,
                        const float* bias, const float* res,
                        float* Cf, __half* Chi, __half* Clo,
                        int M, int N, int K, int gelu_split, int bm64)
{
    if (bm64) {
        dim3 grid(M / 64, (N + BN - 1) / BN);
        mm_gemm_t<2><<<grid, 256, GSMEM2>>>(Ah, Al, Bh, bias, res, Cf, Chi, Clo, M, N, K, gelu_split);
    } else {
        dim3 grid(M / 128, (N + BN - 1) / BN);
        mm_gemm_t<4><<<grid, 256, GSMEM4>>>(Ah, Al, Bh, bias, res, Cf, Chi, Clo, M, N, K, gelu_split);
    }
}

extern "C" void kernel_launch(void* const* d_in, const int* in_sizes, int n_in,
                              void* d_out, int out_size)
{
    const int*   idx     = (const int*)d_in[0];
    const int*   targets = (const int*)d_in[1];
    const float* wte     = (const float*)d_in[2];
    const float* wpe     = (const float*)d_in[3];
    const float* ln1_s   = (const float*)d_in[4];
    const float* ln1_b   = (const float*)d_in[5];
    const float* ln2_s   = (const float*)d_in[6];
    const float* ln2_b   = (const float*)d_in[7];
    const float* Wq      = (const float*)d_in[8];
    const float* bq      = (const float*)d_in[9];
    const float* Wk      = (const float*)d_in[10];
    const float* bk      = (const float*)d_in[11];
    const float* Wv      = (const float*)d_in[12];
    const float* bv      = (const float*)d_in[13];
    const float* Wo      = (const float*)d_in[14];
    const float* bo      = (const float*)d_in[15];
    const float* W1      = (const float*)d_in[16];
    const float* b1      = (const float*)d_in[17];
    const float* W2      = (const float*)d_in[18];
    const float* b2      = (const float*)d_in[19];
    const float* lnf_s   = (const float*)d_in[20];
    const float* lnf_b   = (const float*)d_in[21];

    float* out = (float*)d_out;

    (void)cudaFuncSetAttribute(mm_gemm_t<4>, cudaFuncAttributeMaxDynamicSharedMemorySize, GSMEM4);
    (void)cudaFuncSetAttribute(mm_gemm_t<2>, cudaFuncAttributeMaxDynamicSharedMemorySize, GSMEM2);

    float* x    = symaddr<float>(g_x);
    float* qkv  = symaddr<float>(g_qkv);
    float* bqkv = symaddr<float>(g_bqkv);
    float* rowloss = symaddr<float>(g_rowloss);
    __half* hh  = symaddr<__half>(g_hh);
    __half* hl  = symaddr<__half>(g_hl);
    __half* ffh = symaddr<__half>(g_ffh);
    __half* ffl = symaddr<__half>(g_ffl);
    __half* ath = symaddr<__half>(g_ath);
    __half* atl = symaddr<__half>(g_atl);
    __half* wqkvh = symaddr<__half>(g_wqkvh);
    __half* woh = symaddr<__half>(g_woh);
    __half* w1h = symaddr<__half>(g_w1h);
    __half* w2h = symaddr<__half>(g_w2h);
    __half* wteh = symaddr<__half>(g_wteh);

    // Launch order: index 3 is the QKV mm_gemm (ncu window profiles index 3).
    embed_kernel<<<BT, 256>>>(idx, wte, wpe, x);                                   // 0

    for (int l = 0; l < LAYERS; l++) {
        ln_split_kernel<<<BT, 256>>>(x, ln1_s + l * DMODEL, ln1_b + l * DMODEL, hh, hl);   // 1

        {
            const int n = QKVN * DMODEL;
            prep_qkv_kernel<<<(n + 255) / 256, 256>>>(Wq, Wk, Wv, bq, bk, bv, l, wqkvh, bqkv); // 2
        }
        launch_gemm(hh, hl, wqkvh, bqkv, nullptr, qkv, nullptr, nullptr,
                    BT, QKVN, DMODEL, 0, 0);                                       // 3  <- profiled

        dim3 agrid(TT, NH, BB);
        attn_kernel<<<agrid, 128>>>(qkv, ath, atl);

        {
            dim3 tg(DMODEL / 32, DMODEL / 32);
            prep_T_kernel<<<tg, dim3(32, 8)>>>(Wo + (size_t)l * DMODEL * DMODEL, woh, DMODEL, DMODEL);
        }
        launch_gemm(ath, atl, woh, bo + l * DMODEL, x, x, nullptr, nullptr,
                    BT, DMODEL, DMODEL, 0, 1);                 // BM=64

        ln_split_kernel<<<BT, 256>>>(x, ln2_s + l * DMODEL, ln2_b + l * DMODEL, hh, hl);
        {
            dim3 tg(DMODEL / 32, FF / 32);
            prep_T_kernel<<<tg, dim3(32, 8)>>>(W1 + (size_t)l * DMODEL * FF, w1h, DMODEL, FF);
        }
        launch_gemm(hh, hl, w1h, b1 + l * FF, nullptr, nullptr, ffh, ffl,
                    BT, FF, DMODEL, 1, 0);                     // GELU + split
        {
            dim3 tg(FF / 32, DMODEL / 32);
            prep_T_kernel<<<tg, dim3(32, 8)>>>(W2 + (size_t)l * FF * DMODEL, w2h, FF, DMODEL);
        }
        launch_gemm(ffh, ffl, w2h, b2 + l * DMODEL, x, x, nullptr, nullptr,
                    BT, DMODEL, FF, 0, 1);                     // BM=64
    }

    ln_split_kernel<<<BT, 256>>>(x, lnf_s, lnf_b, hh, hl);

    {
        const int n4 = (VOCAB * DMODEL) / 4;
        prep_split_kernel<<<(n4 + 255) / 256, 256>>>(wte, wteh, n4);
    }

    // logits = h @ wte^T  (N odd -> scalar epilogue path)
    launch_gemm(hh, hl, wteh, nullptr, nullptr, out, nullptr, nullptr,
                BT, VOCAB, DMODEL, 0, 0);

    const long long NL = (long long)BT * VOCAB;
    lossrow_kernel<<<BT, 256>>>(out, targets, rowloss);
    if ((long long)out_size > NL)
        lossred_kernel<<<1, 256>>>(rowloss, out + NL);
}